// round 1
// baseline (speedup 1.0000x reference)
#include <cuda_runtime.h>
#include <cstdint>

#define TOTAL    8192
#define HIDDEN   1280
#define HEADS    16
#define HEAD_DIM 80
#define NCHUNK   8
#define CHUNK_L  1024
#define QKV_N    (3 * HIDDEN)
#define SCALE    0.11180339887498949f  /* 80^-0.5 */

// Scratch (device globals: no allocation in kernel_launch allowed)
__device__ float g_qkv[(size_t)TOTAL * QKV_N];    // [T, 3D] : q | k | v
__device__ float g_attn[(size_t)TOTAL * HIDDEN];  // attention output [T, D]

// ---------------------------------------------------------------------------
// SGEMM with bias: C[M,N] = A[M,K] @ B[K,N] + bias[N]
// 128x128 block, BK=8, 256 threads, 8x8 per-thread microtile, reg prefetch.
// Requires M%128==0, N%128==0, K%8==0 (true for all our shapes).
// ---------------------------------------------------------------------------
__global__ __launch_bounds__(256) void sgemm_bias(
    const float* __restrict__ A, const float* __restrict__ B,
    const float* __restrict__ bias, float* __restrict__ C,
    int M, int N, int K)
{
    __shared__ float As[8][128];   // transposed A tile
    __shared__ float Bs[8][128];

    const int tid = threadIdx.x;
    const int tx  = tid & 15;
    const int ty  = tid >> 4;
    const int bx  = blockIdx.x;
    const int by  = blockIdx.y;

    // global->smem load mapping
    const int a_row = tid >> 1;            // 0..127
    const int a_col = (tid & 1) * 4;       // 0 or 4
    const int b_row = tid >> 5;            // 0..7
    const int b_col = (tid & 31) * 4;      // 0..124

    const float* Ap = A + (size_t)(by * 128 + a_row) * K + a_col;
    const float* Bp = B + (size_t)b_row * N + bx * 128 + b_col;

    float acc[8][8];
#pragma unroll
    for (int i = 0; i < 8; i++)
#pragma unroll
        for (int j = 0; j < 8; j++) acc[i][j] = 0.0f;

    float4 a_nx = *(const float4*)Ap;
    float4 b_nx = *(const float4*)Bp;

    for (int k0 = 0; k0 < K; k0 += 8) {
        As[a_col + 0][a_row] = a_nx.x;
        As[a_col + 1][a_row] = a_nx.y;
        As[a_col + 2][a_row] = a_nx.z;
        As[a_col + 3][a_row] = a_nx.w;
        *(float4*)&Bs[b_row][b_col] = b_nx;
        __syncthreads();

        if (k0 + 8 < K) {
            a_nx = *(const float4*)(Ap + k0 + 8);
            b_nx = *(const float4*)(Bp + (size_t)(k0 + 8) * N);
        }

#pragma unroll
        for (int k = 0; k < 8; k++) {
            float4 t0 = *(const float4*)&As[k][ty * 4];
            float4 t1 = *(const float4*)&As[k][64 + ty * 4];
            float4 u0 = *(const float4*)&Bs[k][tx * 4];
            float4 u1 = *(const float4*)&Bs[k][64 + tx * 4];
            float aF[8] = {t0.x, t0.y, t0.z, t0.w, t1.x, t1.y, t1.z, t1.w};
            float bF[8] = {u0.x, u0.y, u0.z, u0.w, u1.x, u1.y, u1.z, u1.w};
#pragma unroll
            for (int i = 0; i < 8; i++)
#pragma unroll
                for (int j = 0; j < 8; j++)
                    acc[i][j] += aF[i] * bF[j];
        }
        __syncthreads();
    }

    const int col0 = bx * 128 + tx * 4;
    const int col1 = col0 + 64;
    const float4 bv0 = *(const float4*)&bias[col0];
    const float4 bv1 = *(const float4*)&bias[col1];

#pragma unroll
    for (int i = 0; i < 8; i++) {
        int row = by * 128 + ((i < 4) ? (ty * 4 + i) : (64 + ty * 4 + i - 4));
        float4 o0, o1;
        o0.x = acc[i][0] + bv0.x; o0.y = acc[i][1] + bv0.y;
        o0.z = acc[i][2] + bv0.z; o0.w = acc[i][3] + bv0.w;
        o1.x = acc[i][4] + bv1.x; o1.y = acc[i][5] + bv1.y;
        o1.z = acc[i][6] + bv1.z; o1.w = acc[i][7] + bv1.w;
        *(float4*)&C[(size_t)row * N + col0] = o0;
        *(float4*)&C[(size_t)row * N + col1] = o1;
    }
}

// ---------------------------------------------------------------------------
// RoPE applied in-place to q and k halves of g_qkv; q additionally scaled by
// hd^-0.5 (folds the attention score scale into q).
// One thread handles one (t, h, d<40) rotation pair for both q and k.
// ---------------------------------------------------------------------------
__global__ __launch_bounds__(256) void rope_kernel(
    const float* __restrict__ cosp, const float* __restrict__ sinp)
{
    int idx = blockIdx.x * blockDim.x + threadIdx.x;
    const int total = TOTAL * HEADS * (HEAD_DIM / 2);
    if (idx >= total) return;
    int d = idx % 40;
    int h = (idx / 40) % HEADS;
    int t = idx / (40 * HEADS);

    float c1 = cosp[t * HEAD_DIM + d];
    float s1 = sinp[t * HEAD_DIM + d];
    float c2 = cosp[t * HEAD_DIM + d + 40];
    float s2 = sinp[t * HEAD_DIM + d + 40];

    float* row = g_qkv + (size_t)t * QKV_N;
    int qi = h * HEAD_DIM + d;

    float q1 = row[qi], q2 = row[qi + 40];
    row[qi]      = (q1 * c1 - q2 * s1) * SCALE;
    row[qi + 40] = (q2 * c2 + q1 * s2) * SCALE;

    float k1 = row[HIDDEN + qi], k2 = row[HIDDEN + qi + 40];
    row[HIDDEN + qi]      = k1 * c1 - k2 * s1;
    row[HIDDEN + qi + 40] = k2 * c2 + k1 * s2;
}

// ---------------------------------------------------------------------------
// Flash attention (fp32, online softmax). One block = 64 q-rows of one
// (chunk, head). Iterates over 16 KV tiles of 64 rows. 256 threads.
//   S-gemm: 16x16 thread grid, 4x4 microtile -> Pt (col-major S) in smem.
//   PV-gemm: same grid, 4 rows x 5 cols of O per thread (hd=80).
// ---------------------------------------------------------------------------
struct FlashSmem {
    float Qs[80][64];    // transposed Q (q pre-scaled)
    float Ks[80][64];    // transposed K
    float Vs[64][80];    // row-major V
    float Pt[64][68];    // S / P, stored [col][row], padded for alignment
    float red[4][65];    // segment reductions
    float m_s[64];
    float l_s[64];
    float alpha_s[64];
};

__global__ __launch_bounds__(256) void flash_attn()
{
    extern __shared__ char raw[];
    FlashSmem& S = *reinterpret_cast<FlashSmem*>(raw);

    const int tid = threadIdx.x;
    const int tx  = tid & 15;
    const int ty  = tid >> 4;
    const int qt  = blockIdx.x;   // q tile within chunk (0..15)
    const int h   = blockIdx.y;   // head
    const int c   = blockIdx.z;   // chunk
    const int q0  = c * CHUNK_L + qt * 64;

    // load Q tile, transposed
#pragma unroll
    for (int it = 0; it < 20; it++) {
        int idx = tid + it * 256;         // 0..5119
        int r = idx / 80, d = idx % 80;
        S.Qs[d][r] = g_qkv[(size_t)(q0 + r) * QKV_N + h * HEAD_DIM + d];
    }
    if (tid < 64) { S.m_s[tid] = -1e30f; S.l_s[tid] = 0.0f; }

    float acc[4][5];
#pragma unroll
    for (int i = 0; i < 4; i++)
#pragma unroll
        for (int j = 0; j < 5; j++) acc[i][j] = 0.0f;

    __syncthreads();

    const int seg = tid & 3;
    const int rr  = tid >> 2;

    for (int kt = 0; kt < CHUNK_L / 64; kt++) {
        const int k0 = c * CHUNK_L + kt * 64;

        // load K (transposed) and V tiles
#pragma unroll
        for (int it = 0; it < 20; it++) {
            int idx = tid + it * 256;
            int r = idx / 80, d = idx % 80;
            size_t base = (size_t)(k0 + r) * QKV_N + h * HEAD_DIM + d;
            S.Ks[d][r] = g_qkv[base + HIDDEN];
            S.Vs[r][d] = g_qkv[base + 2 * HIDDEN];
        }
        __syncthreads();

        // S = (Q*scale) @ K^T   -> Pt[col][row]
        float sv[4][4];
#pragma unroll
        for (int i = 0; i < 4; i++)
#pragma unroll
            for (int j = 0; j < 4; j++) sv[i][j] = 0.0f;

#pragma unroll 8
        for (int d = 0; d < 80; d++) {
            float4 a = *(const float4*)&S.Qs[d][ty * 4];
            float4 b = *(const float4*)&S.Ks[d][tx * 4];
            float aF[4] = {a.x, a.y, a.z, a.w};
            float bF[4] = {b.x, b.y, b.z, b.w};
#pragma unroll
            for (int i = 0; i < 4; i++)
#pragma unroll
                for (int j = 0; j < 4; j++)
                    sv[i][j] += aF[i] * bF[j];
        }
#pragma unroll
        for (int i = 0; i < 4; i++)
#pragma unroll
            for (int j = 0; j < 4; j++)
                S.Pt[tx * 4 + j][ty * 4 + i] = sv[i][j];
        __syncthreads();

        // row max (each thread: 16 cols of one row)
        float mx = -1e30f;
#pragma unroll
        for (int jj = 0; jj < 16; jj++)
            mx = fmaxf(mx, S.Pt[seg * 16 + jj][rr]);
        S.red[seg][rr] = mx;
        __syncthreads();

        if (tid < 64) {
            float mold = S.m_s[tid];
            float mnew = fmaxf(fmaxf(S.red[0][tid], S.red[1][tid]),
                               fmaxf(S.red[2][tid], S.red[3][tid]));
            mnew = fmaxf(mold, mnew);
            S.alpha_s[tid] = __expf(mold - mnew);
            S.m_s[tid] = mnew;
        }
        __syncthreads();

        // exponentiate + partial sums
        float mnew = S.m_s[rr];
        float ssum = 0.0f;
#pragma unroll
        for (int jj = 0; jj < 16; jj++) {
            float e = __expf(S.Pt[seg * 16 + jj][rr] - mnew);
            S.Pt[seg * 16 + jj][rr] = e;
            ssum += e;
        }
        S.red[seg][rr] = ssum;
        __syncthreads();

        if (tid < 64) {
            S.l_s[tid] = S.l_s[tid] * S.alpha_s[tid] +
                         S.red[0][tid] + S.red[1][tid] +
                         S.red[2][tid] + S.red[3][tid];
        }

        // rescale accumulator rows
        float al[4];
#pragma unroll
        for (int i = 0; i < 4; i++) al[i] = S.alpha_s[ty * 4 + i];
#pragma unroll
        for (int i = 0; i < 4; i++)
#pragma unroll
            for (int j = 0; j < 5; j++) acc[i][j] *= al[i];

        // O += P @ V
#pragma unroll 4
        for (int j = 0; j < 64; j++) {
            float4 a = *(const float4*)&S.Pt[j][ty * 4];
            float aF[4] = {a.x, a.y, a.z, a.w};
            float vF[5];
#pragma unroll
            for (int cj = 0; cj < 5; cj++) vF[cj] = S.Vs[j][tx * 5 + cj];
#pragma unroll
            for (int i = 0; i < 4; i++)
#pragma unroll
                for (int cj = 0; cj < 5; cj++)
                    acc[i][cj] += aF[i] * vF[cj];
        }
        __syncthreads();
    }

    // normalize and write out
#pragma unroll
    for (int i = 0; i < 4; i++) {
        float inv = 1.0f / S.l_s[ty * 4 + i];
        int t = q0 + ty * 4 + i;
#pragma unroll
        for (int cj = 0; cj < 5; cj++)
            g_attn[(size_t)t * HIDDEN + h * HEAD_DIM + tx * 5 + cj] =
                acc[i][cj] * inv;
    }
}

// ---------------------------------------------------------------------------
extern "C" void kernel_launch(void* const* d_in, const int* in_sizes, int n_in,
                              void* d_out, int out_size)
{
    (void)in_sizes; (void)n_in; (void)out_size;
    const float* x      = (const float*)d_in[0];
    const float* cosp   = (const float*)d_in[1];
    const float* sinp   = (const float*)d_in[2];
    const float* w_qkv  = (const float*)d_in[3];
    const float* b_qkv  = (const float*)d_in[4];
    const float* w_proj = (const float*)d_in[5];
    const float* b_proj = (const float*)d_in[6];
    float* out = (float*)d_out;

    float *qkv = nullptr, *attn = nullptr;
    cudaGetSymbolAddress((void**)&qkv,  g_qkv);
    cudaGetSymbolAddress((void**)&attn, g_attn);

    // 1) QKV projection: [8192,1280] @ [1280,3840] + b
    sgemm_bias<<<dim3(QKV_N / 128, TOTAL / 128), 256>>>(
        x, w_qkv, b_qkv, qkv, TOTAL, QKV_N, HIDDEN);

    // 2) RoPE on q,k (q pre-scaled by hd^-0.5)
    {
        int total = TOTAL * HEADS * (HEAD_DIM / 2);
        rope_kernel<<<(total + 255) / 256, 256>>>(cosp, sinp);
    }

    // 3) block-diagonal flash attention
    cudaFuncSetAttribute(flash_attn,
                         cudaFuncAttributeMaxDynamicSharedMemorySize,
                         (int)sizeof(FlashSmem));
    flash_attn<<<dim3(CHUNK_L / 64, HEADS, NCHUNK), 256, sizeof(FlashSmem)>>>();

    // 4) output projection: [8192,1280] @ [1280,1280] + b -> d_out
    sgemm_bias<<<dim3(HIDDEN / 128, TOTAL / 128), 256>>>(
        attn, w_proj, b_proj, out, TOTAL, HIDDEN, HIDDEN);
}

// round 3
// speedup vs baseline: 1.1951x; 1.1951x over previous
#include <cuda_runtime.h>
#include <cuda_bf16.h>
#include <cstdint>

#define TOTAL    8192
#define HIDDEN   1280
#define HEADS    16
#define HEAD_DIM 80
#define NCHUNK   8
#define CHUNK_L  1024
#define QKVN     3840
#define K3       3840   /* 3 * 1280 : tripled K for the bf16x3 trick */
#define SCALE    0.11180339887498949f  /* 80^-0.5 */

// ---------------- device scratch (no allocs allowed) ----------------
__device__ float         g_qkv [(size_t)TOTAL * QKVN];    // [T, 3D] fp32
__device__ float         g_attn[(size_t)TOTAL * HIDDEN];  // attn out fp32
__device__ __nv_bfloat16 g_Aq  [(size_t)TOTAL * K3];      // split(x)
__device__ __nv_bfloat16 g_Ap  [(size_t)TOTAL * K3];      // split(attn)
__device__ __nv_bfloat16 g_Bq  [(size_t)QKVN  * K3];      // split+T(w_qkv)
__device__ __nv_bfloat16 g_Bp  [(size_t)HIDDEN* K3];      // split+T(w_proj)

// ---------------- PTX helpers (arch-agnostic: mma.sync + ldmatrix) --------
__device__ __forceinline__ uint32_t smem_u32(const void* p) {
    uint32_t a;
    asm("{ .reg .u64 t; cvta.to.shared.u64 t, %1; cvt.u32.u64 %0, t; }"
        : "=r"(a) : "l"(p));
    return a;
}
__device__ __forceinline__ void ldsm_x4(uint32_t* r, uint32_t addr) {
    asm volatile("ldmatrix.sync.aligned.m8n8.x4.shared.b16 {%0,%1,%2,%3}, [%4];"
                 : "=r"(r[0]), "=r"(r[1]), "=r"(r[2]), "=r"(r[3]) : "r"(addr));
}
__device__ __forceinline__ void mma_16816(float* c, const uint32_t* a,
                                          const uint32_t* b) {
    asm volatile(
        "mma.sync.aligned.m16n8k16.row.col.f32.bf16.bf16.f32 "
        "{%0,%1,%2,%3}, {%4,%5,%6,%7}, {%8,%9}, {%0,%1,%2,%3};"
        : "+f"(c[0]), "+f"(c[1]), "+f"(c[2]), "+f"(c[3])
        : "r"(a[0]), "r"(a[1]), "r"(a[2]), "r"(a[3]), "r"(b[0]), "r"(b[1]));
}

// ---------------------------------------------------------------------------
// Tensor-core GEMM: C[8192, N] = A[8192, K3] * B[N, K3]^T + bias
// 128x128 CTA tile, BK=32, double-buffered smem, 8 warps (4m x 2n),
// warp tile 32x64 (2 x 8 m16n8k16 frags).
// ---------------------------------------------------------------------------
#define BK   32
#define LDA  40   /* 32 + 8 pad: ldmatrix conflict-free (5r mod 8 permutation) */

__global__ __launch_bounds__(256) void gemm_bf16_mma(
    const __nv_bfloat16* __restrict__ A, const __nv_bfloat16* __restrict__ B,
    const float* __restrict__ bias, float* __restrict__ C, int N)
{
    __shared__ __nv_bfloat16 As[2][128][LDA];
    __shared__ __nv_bfloat16 Bs[2][128][LDA];

    const int tid  = threadIdx.x;
    const int wid  = tid >> 5;
    const int lane = tid & 31;
    const int m0   = blockIdx.y * 128;
    const int n0   = blockIdx.x * 128;
    const int wm   = wid & 3;        // 0..3 -> 32-row band
    const int wn   = wid >> 2;       // 0..1 -> 64-col band

    // global->smem mapping: 2 chunks of 16B each for A and B per thread
    int ldRow[2], ldCh[2];
    const __nv_bfloat16 *aSrc[2], *bSrc[2];
#pragma unroll
    for (int p = 0; p < 2; p++) {
        int u = tid + p * 256;
        ldRow[p] = u >> 2;
        ldCh[p]  = (u & 3) * 8;
        aSrc[p]  = A + (size_t)(m0 + ldRow[p]) * K3 + ldCh[p];
        bSrc[p]  = B + (size_t)(n0 + ldRow[p]) * K3 + ldCh[p];
    }

    float acc[2][8][4];
#pragma unroll
    for (int mt = 0; mt < 2; mt++)
#pragma unroll
        for (int nt = 0; nt < 8; nt++)
#pragma unroll
            for (int v = 0; v < 4; v++) acc[mt][nt][v] = 0.0f;

    // ldmatrix source addresses (lane-dependent row, 16B column select)
    const int lrow = lane & 15;
    const int lcol = (lane >> 4) << 3;   // 0 or 8 elements
    uint32_t aAddr[2][2], bAddr[2][4];   // [buf][tile]
#pragma unroll
    for (int buf = 0; buf < 2; buf++) {
#pragma unroll
        for (int mt = 0; mt < 2; mt++)
            aAddr[buf][mt] = smem_u32(&As[buf][wm * 32 + mt * 16 + lrow][lcol]);
#pragma unroll
        for (int np = 0; np < 4; np++)
            bAddr[buf][np] = smem_u32(&Bs[buf][wn * 64 + np * 16 + lrow][lcol]);
    }

    // preload k-block 0
    uint4 an[2], bn[2];
#pragma unroll
    for (int p = 0; p < 2; p++) {
        an[p] = *(const uint4*)aSrc[p];
        bn[p] = *(const uint4*)bSrc[p];
    }
#pragma unroll
    for (int p = 0; p < 2; p++) {
        *(uint4*)&As[0][ldRow[p]][ldCh[p]] = an[p];
        *(uint4*)&Bs[0][ldRow[p]][ldCh[p]] = bn[p];
    }
    __syncthreads();

    const int NKB = K3 / BK;   // 120
    for (int kb = 0; kb < NKB; kb++) {
        const int cur = kb & 1;
        const bool more = (kb + 1) < NKB;
        if (more) {
#pragma unroll
            for (int p = 0; p < 2; p++) {
                an[p] = *(const uint4*)(aSrc[p] + (kb + 1) * BK);
                bn[p] = *(const uint4*)(bSrc[p] + (kb + 1) * BK);
            }
        }

#pragma unroll
        for (int ks = 0; ks < 2; ks++) {
            const uint32_t koff = ks * 32;   // 16 elems * 2B
            uint32_t af[2][4];
#pragma unroll
            for (int mt = 0; mt < 2; mt++)
                ldsm_x4(af[mt], aAddr[cur][mt] + koff);
            uint32_t bf[8][2];
#pragma unroll
            for (int np = 0; np < 4; np++) {
                uint32_t r[4];
                ldsm_x4(r, bAddr[cur][np] + koff);
                bf[2 * np][0]     = r[0]; bf[2 * np][1]     = r[2];
                bf[2 * np + 1][0] = r[1]; bf[2 * np + 1][1] = r[3];
            }
#pragma unroll
            for (int mt = 0; mt < 2; mt++)
#pragma unroll
                for (int nt = 0; nt < 8; nt++)
                    mma_16816(acc[mt][nt], af[mt], bf[nt]);
        }

        if (more) {
            const int nxt = cur ^ 1;
#pragma unroll
            for (int p = 0; p < 2; p++) {
                *(uint4*)&As[nxt][ldRow[p]][ldCh[p]] = an[p];
                *(uint4*)&Bs[nxt][ldRow[p]][ldCh[p]] = bn[p];
            }
        }
        __syncthreads();
    }

    // epilogue: bias + store (c frag: lane -> row l/4 (+8), col (l%4)*2 (+1))
    const int cr = lane >> 2;
    const int cc = (lane & 3) * 2;
#pragma unroll
    for (int mt = 0; mt < 2; mt++) {
        const int r0 = m0 + wm * 32 + mt * 16 + cr;
#pragma unroll
        for (int nt = 0; nt < 8; nt++) {
            const int col = n0 + wn * 64 + nt * 8 + cc;
            const float b0 = __ldg(&bias[col]);
            const float b1 = __ldg(&bias[col + 1]);
            float2 v0, v1;
            v0.x = acc[mt][nt][0] + b0; v0.y = acc[mt][nt][1] + b1;
            v1.x = acc[mt][nt][2] + b0; v1.y = acc[mt][nt][3] + b1;
            *(float2*)&C[(size_t)r0 * N + col]       = v0;
            *(float2*)&C[(size_t)(r0 + 8) * N + col] = v1;
        }
    }
}

// ---------------------------------------------------------------------------
// bf16x3 split of activations: X[M,K] fp32 -> O[M,3K] = [hi | lo | hi]
// ---------------------------------------------------------------------------
__global__ __launch_bounds__(256) void split_A(
    const float* __restrict__ X, __nv_bfloat16* __restrict__ O, int MK, int K)
{
    int idx = blockIdx.x * 256 + threadIdx.x;
    if (idx >= MK) return;
    int m = idx / K, k = idx - m * K;
    float x = X[idx];
    __nv_bfloat16 h = __float2bfloat16(x);
    __nv_bfloat16 l = __float2bfloat16(x - __bfloat162float(h));
    size_t o = (size_t)m * (3 * K) + k;
    O[o]         = h;
    O[o + K]     = l;
    O[o + 2 * K] = h;
}

// ---------------------------------------------------------------------------
// bf16x3 split + transpose of weights: W[K,N] fp32 -> O[N,3K] = [hi ; hi ; lo]
// ---------------------------------------------------------------------------
__global__ __launch_bounds__(256) void convert_B(
    const float* __restrict__ W, __nv_bfloat16* __restrict__ O, int K, int N)
{
    __shared__ float t[32][33];
    const int k0 = blockIdx.y * 32, n0 = blockIdx.x * 32;
    const int tx = threadIdx.x, ty = threadIdx.y;   // 32 x 8
#pragma unroll
    for (int i = 0; i < 32; i += 8)
        t[ty + i][tx] = W[(size_t)(k0 + ty + i) * N + n0 + tx];
    __syncthreads();
#pragma unroll
    for (int i = 0; i < 32; i += 8) {
        int n = n0 + ty + i, k = k0 + tx;
        float x = t[tx][ty + i];
        __nv_bfloat16 h = __float2bfloat16(x);
        __nv_bfloat16 l = __float2bfloat16(x - __bfloat162float(h));
        size_t o = (size_t)n * (3 * K) + k;
        O[o]         = h;
        O[o + K]     = h;
        O[o + 2 * K] = l;
    }
}

// ---------------------------------------------------------------------------
// RoPE in-place on q,k halves of g_qkv; q pre-scaled by hd^-0.5.
// ---------------------------------------------------------------------------
__global__ __launch_bounds__(256) void rope_kernel(
    const float* __restrict__ cosp, const float* __restrict__ sinp)
{
    int idx = blockIdx.x * blockDim.x + threadIdx.x;
    const int total = TOTAL * HEADS * (HEAD_DIM / 2);
    if (idx >= total) return;
    int d = idx % 40;
    int h = (idx / 40) % HEADS;
    int t = idx / (40 * HEADS);

    float c1 = cosp[t * HEAD_DIM + d];
    float s1 = sinp[t * HEAD_DIM + d];
    float c2 = cosp[t * HEAD_DIM + d + 40];
    float s2 = sinp[t * HEAD_DIM + d + 40];

    float* row = g_qkv + (size_t)t * QKVN;
    int qi = h * HEAD_DIM + d;

    float q1 = row[qi], q2 = row[qi + 40];
    row[qi]      = (q1 * c1 - q2 * s1) * SCALE;
    row[qi + 40] = (q2 * c2 + q1 * s2) * SCALE;

    float k1 = row[HIDDEN + qi], k2 = row[HIDDEN + qi + 40];
    row[HIDDEN + qi]      = k1 * c1 - k2 * s1;
    row[HIDDEN + qi + 40] = k2 * c2 + k1 * s2;
}

// ---------------------------------------------------------------------------
// Flash attention (fp32, online softmax) — unchanged (verified in R1).
// ---------------------------------------------------------------------------
struct FlashSmem {
    float Qs[80][64];
    float Ks[80][64];
    float Vs[64][80];
    float Pt[64][68];
    float red[4][65];
    float m_s[64];
    float l_s[64];
    float alpha_s[64];
};

__global__ __launch_bounds__(256) void flash_attn()
{
    extern __shared__ char raw[];
    FlashSmem& S = *reinterpret_cast<FlashSmem*>(raw);

    const int tid = threadIdx.x;
    const int tx  = tid & 15;
    const int ty  = tid >> 4;
    const int qt  = blockIdx.x;
    const int h   = blockIdx.y;
    const int c   = blockIdx.z;
    const int q0  = c * CHUNK_L + qt * 64;

#pragma unroll
    for (int it = 0; it < 20; it++) {
        int idx = tid + it * 256;
        int r = idx / 80, d = idx % 80;
        S.Qs[d][r] = g_qkv[(size_t)(q0 + r) * QKVN + h * HEAD_DIM + d];
    }
    if (tid < 64) { S.m_s[tid] = -1e30f; S.l_s[tid] = 0.0f; }

    float acc[4][5];
#pragma unroll
    for (int i = 0; i < 4; i++)
#pragma unroll
        for (int j = 0; j < 5; j++) acc[i][j] = 0.0f;

    __syncthreads();

    const int seg = tid & 3;
    const int rr  = tid >> 2;

    for (int kt = 0; kt < CHUNK_L / 64; kt++) {
        const int k0 = c * CHUNK_L + kt * 64;

#pragma unroll
        for (int it = 0; it < 20; it++) {
            int idx = tid + it * 256;
            int r = idx / 80, d = idx % 80;
            size_t base = (size_t)(k0 + r) * QKVN + h * HEAD_DIM + d;
            S.Ks[d][r] = g_qkv[base + HIDDEN];
            S.Vs[r][d] = g_qkv[base + 2 * HIDDEN];
        }
        __syncthreads();

        float sv[4][4];
#pragma unroll
        for (int i = 0; i < 4; i++)
#pragma unroll
            for (int j = 0; j < 4; j++) sv[i][j] = 0.0f;

#pragma unroll 8
        for (int d = 0; d < 80; d++) {
            float4 a = *(const float4*)&S.Qs[d][ty * 4];
            float4 b = *(const float4*)&S.Ks[d][tx * 4];
            float aF[4] = {a.x, a.y, a.z, a.w};
            float bF[4] = {b.x, b.y, b.z, b.w};
#pragma unroll
            for (int i = 0; i < 4; i++)
#pragma unroll
                for (int j = 0; j < 4; j++)
                    sv[i][j] += aF[i] * bF[j];
        }
#pragma unroll
        for (int i = 0; i < 4; i++)
#pragma unroll
            for (int j = 0; j < 4; j++)
                S.Pt[tx * 4 + j][ty * 4 + i] = sv[i][j];
        __syncthreads();

        float mx = -1e30f;
#pragma unroll
        for (int jj = 0; jj < 16; jj++)
            mx = fmaxf(mx, S.Pt[seg * 16 + jj][rr]);
        S.red[seg][rr] = mx;
        __syncthreads();

        if (tid < 64) {
            float mold = S.m_s[tid];
            float mnew = fmaxf(fmaxf(S.red[0][tid], S.red[1][tid]),
                               fmaxf(S.red[2][tid], S.red[3][tid]));
            mnew = fmaxf(mold, mnew);
            S.alpha_s[tid] = __expf(mold - mnew);
            S.m_s[tid] = mnew;
        }
        __syncthreads();

        float mnew = S.m_s[rr];
        float ssum = 0.0f;
#pragma unroll
        for (int jj = 0; jj < 16; jj++) {
            float e = __expf(S.Pt[seg * 16 + jj][rr] - mnew);
            S.Pt[seg * 16 + jj][rr] = e;
            ssum += e;
        }
        S.red[seg][rr] = ssum;
        __syncthreads();

        if (tid < 64) {
            S.l_s[tid] = S.l_s[tid] * S.alpha_s[tid] +
                         S.red[0][tid] + S.red[1][tid] +
                         S.red[2][tid] + S.red[3][tid];
        }

        float al[4];
#pragma unroll
        for (int i = 0; i < 4; i++) al[i] = S.alpha_s[ty * 4 + i];
#pragma unroll
        for (int i = 0; i < 4; i++)
#pragma unroll
            for (int j = 0; j < 5; j++) acc[i][j] *= al[i];

#pragma unroll 4
        for (int j = 0; j < 64; j++) {
            float4 a = *(const float4*)&S.Pt[j][ty * 4];
            float aF[4] = {a.x, a.y, a.z, a.w};
            float vF[5];
#pragma unroll
            for (int cj = 0; cj < 5; cj++) vF[cj] = S.Vs[j][tx * 5 + cj];
#pragma unroll
            for (int i = 0; i < 4; i++)
#pragma unroll
                for (int cj = 0; cj < 5; cj++)
                    acc[i][cj] += aF[i] * vF[cj];
        }
        __syncthreads();
    }

#pragma unroll
    for (int i = 0; i < 4; i++) {
        float inv = 1.0f / S.l_s[ty * 4 + i];
        int t = q0 + ty * 4 + i;
#pragma unroll
        for (int cj = 0; cj < 5; cj++)
            g_attn[(size_t)t * HIDDEN + h * HEAD_DIM + tx * 5 + cj] =
                acc[i][cj] * inv;
    }
}

// ---------------------------------------------------------------------------
extern "C" void kernel_launch(void* const* d_in, const int* in_sizes, int n_in,
                              void* d_out, int out_size)
{
    (void)in_sizes; (void)n_in; (void)out_size;
    const float* x      = (const float*)d_in[0];
    const float* cosp   = (const float*)d_in[1];
    const float* sinp   = (const float*)d_in[2];
    const float* w_qkv  = (const float*)d_in[3];
    const float* b_qkv  = (const float*)d_in[4];
    const float* w_proj = (const float*)d_in[5];
    const float* b_proj = (const float*)d_in[6];
    float* out = (float*)d_out;

    float *qkv = nullptr, *attn = nullptr;
    __nv_bfloat16 *Aq = nullptr, *Ap = nullptr, *Bq = nullptr, *Bp = nullptr;
    cudaGetSymbolAddress((void**)&qkv,  g_qkv);
    cudaGetSymbolAddress((void**)&attn, g_attn);
    cudaGetSymbolAddress((void**)&Aq,   g_Aq);
    cudaGetSymbolAddress((void**)&Ap,   g_Ap);
    cudaGetSymbolAddress((void**)&Bq,   g_Bq);
    cudaGetSymbolAddress((void**)&Bp,   g_Bp);

    cudaFuncSetAttribute(flash_attn,
                         cudaFuncAttributeMaxDynamicSharedMemorySize,
                         (int)sizeof(FlashSmem));

    // weight + activation bf16x3 conversion
    convert_B<<<dim3(QKVN / 32, HIDDEN / 32), dim3(32, 8)>>>(w_qkv, Bq, HIDDEN, QKVN);
    convert_B<<<dim3(HIDDEN / 32, HIDDEN / 32), dim3(32, 8)>>>(w_proj, Bp, HIDDEN, HIDDEN);
    {
        int mk = TOTAL * HIDDEN;
        split_A<<<(mk + 255) / 256, 256>>>(x, Aq, mk, HIDDEN);
    }

    // 1) QKV projection on tensor cores (mma.sync bf16x3)
    gemm_bf16_mma<<<dim3(QKVN / 128, TOTAL / 128), 256>>>(Aq, Bq, b_qkv, qkv, QKVN);

    // 2) RoPE
    {
        int total = TOTAL * HEADS * (HEAD_DIM / 2);
        rope_kernel<<<(total + 255) / 256, 256>>>(cosp, sinp);
    }

    // 3) block-diagonal flash attention
    flash_attn<<<dim3(CHUNK_L / 64, HEADS, NCHUNK), 256, sizeof(FlashSmem)>>>();

    // 4) output projection on tensor cores
    {
        int mk = TOTAL * HIDDEN;
        split_A<<<(mk + 255) / 256, 256>>>(attn, Ap, mk, HIDDEN);
    }
    gemm_bf16_mma<<<dim3(HIDDEN / 128, TOTAL / 128), 256>>>(Ap, Bp, b_proj, out, HIDDEN);
}

// round 4
// speedup vs baseline: 1.9855x; 1.6614x over previous
#include <cuda_runtime.h>
#include <cuda_bf16.h>
#include <cstdint>

#define TOTAL    8192
#define HIDDEN   1280
#define HEADS    16
#define HEAD_DIM 80
#define NCHUNK   8
#define CHUNK_L  1024
#define QKVN     3840
#define K3       3840   /* 3 * 1280 : tripled K for the bf16x3 trick */
#define SCALE    0.11180339887498949f  /* 80^-0.5 */

// ---------------- device scratch (no allocs allowed) ----------------
__device__ float         g_qkv [(size_t)TOTAL * QKVN];    // [T, 3D] fp32
__device__ float         g_attn[(size_t)TOTAL * HIDDEN];  // attn out fp32
__device__ __nv_bfloat16 g_Aq  [(size_t)TOTAL * K3];      // split(x)
__device__ __nv_bfloat16 g_Ap  [(size_t)TOTAL * K3];      // split(attn)
__device__ __nv_bfloat16 g_Bq  [(size_t)QKVN  * K3];      // split+T(w_qkv)
__device__ __nv_bfloat16 g_Bp  [(size_t)HIDDEN* K3];      // split+T(w_proj)
__device__ __nv_bfloat16 g_Q3 [(size_t)TOTAL * HEADS * 240]; // [t][h][Qh|Ql|Qh]
__device__ __nv_bfloat16 g_K3 [(size_t)TOTAL * HEADS * 240]; // [t][h][Kh|Kh|Kl]
__device__ __nv_bfloat16 g_Vt3[(size_t)NCHUNK * HEADS * HEAD_DIM * 3 * CHUNK_L];
                                  // [c][h][d][Vh(1024)|Vh(1024)|Vl(1024)]

// ---------------- PTX helpers (arch-agnostic: mma.sync + ldmatrix) --------
__device__ __forceinline__ uint32_t smem_u32(const void* p) {
    uint32_t a;
    asm("{ .reg .u64 t; cvta.to.shared.u64 t, %1; cvt.u32.u64 %0, t; }"
        : "=r"(a) : "l"(p));
    return a;
}
__device__ __forceinline__ void ldsm_x4(uint32_t* r, uint32_t addr) {
    asm volatile("ldmatrix.sync.aligned.m8n8.x4.shared.b16 {%0,%1,%2,%3}, [%4];"
                 : "=r"(r[0]), "=r"(r[1]), "=r"(r[2]), "=r"(r[3]) : "r"(addr));
}
__device__ __forceinline__ void mma_16816(float* c, const uint32_t* a,
                                          const uint32_t* b) {
    asm volatile(
        "mma.sync.aligned.m16n8k16.row.col.f32.bf16.bf16.f32 "
        "{%0,%1,%2,%3}, {%4,%5,%6,%7}, {%8,%9}, {%0,%1,%2,%3};"
        : "+f"(c[0]), "+f"(c[1]), "+f"(c[2]), "+f"(c[3])
        : "r"(a[0]), "r"(a[1]), "r"(a[2]), "r"(a[3]), "r"(b[0]), "r"(b[1]));
}
__device__ __forceinline__ uint32_t packbf2(float lo, float hi) {
    uint32_t r;
    asm("cvt.rn.bf16x2.f32 %0, %1, %2;" : "=r"(r) : "f"(hi), "f"(lo));
    return r;
}
__device__ __forceinline__ void sp(float x, __nv_bfloat16& h, __nv_bfloat16& l) {
    h = __float2bfloat16(x);
    l = __float2bfloat16(x - __bfloat162float(h));
}

// ---------------------------------------------------------------------------
// Tensor-core GEMM (unchanged from R3): C[8192, N] = A * B^T + bias
// ---------------------------------------------------------------------------
#define BK   32
#define LDA  40

__global__ __launch_bounds__(256) void gemm_bf16_mma(
    const __nv_bfloat16* __restrict__ A, const __nv_bfloat16* __restrict__ B,
    const float* __restrict__ bias, float* __restrict__ C, int N)
{
    __shared__ __nv_bfloat16 As[2][128][LDA];
    __shared__ __nv_bfloat16 Bs[2][128][LDA];

    const int tid  = threadIdx.x;
    const int wid  = tid >> 5;
    const int lane = tid & 31;
    const int m0   = blockIdx.y * 128;
    const int n0   = blockIdx.x * 128;
    const int wm   = wid & 3;
    const int wn   = wid >> 2;

    int ldRow[2], ldCh[2];
    const __nv_bfloat16 *aSrc[2], *bSrc[2];
#pragma unroll
    for (int p = 0; p < 2; p++) {
        int u = tid + p * 256;
        ldRow[p] = u >> 2;
        ldCh[p]  = (u & 3) * 8;
        aSrc[p]  = A + (size_t)(m0 + ldRow[p]) * K3 + ldCh[p];
        bSrc[p]  = B + (size_t)(n0 + ldRow[p]) * K3 + ldCh[p];
    }

    float acc[2][8][4];
#pragma unroll
    for (int mt = 0; mt < 2; mt++)
#pragma unroll
        for (int nt = 0; nt < 8; nt++)
#pragma unroll
            for (int v = 0; v < 4; v++) acc[mt][nt][v] = 0.0f;

    const int lrow = lane & 15;
    const int lcol = (lane >> 4) << 3;
    uint32_t aAddr[2][2], bAddr[2][4];
#pragma unroll
    for (int buf = 0; buf < 2; buf++) {
#pragma unroll
        for (int mt = 0; mt < 2; mt++)
            aAddr[buf][mt] = smem_u32(&As[buf][wm * 32 + mt * 16 + lrow][lcol]);
#pragma unroll
        for (int np = 0; np < 4; np++)
            bAddr[buf][np] = smem_u32(&Bs[buf][wn * 64 + np * 16 + lrow][lcol]);
    }

    uint4 an[2], bn[2];
#pragma unroll
    for (int p = 0; p < 2; p++) {
        an[p] = *(const uint4*)aSrc[p];
        bn[p] = *(const uint4*)bSrc[p];
    }
#pragma unroll
    for (int p = 0; p < 2; p++) {
        *(uint4*)&As[0][ldRow[p]][ldCh[p]] = an[p];
        *(uint4*)&Bs[0][ldRow[p]][ldCh[p]] = bn[p];
    }
    __syncthreads();

    const int NKB = K3 / BK;
    for (int kb = 0; kb < NKB; kb++) {
        const int cur = kb & 1;
        const bool more = (kb + 1) < NKB;
        if (more) {
#pragma unroll
            for (int p = 0; p < 2; p++) {
                an[p] = *(const uint4*)(aSrc[p] + (kb + 1) * BK);
                bn[p] = *(const uint4*)(bSrc[p] + (kb + 1) * BK);
            }
        }
#pragma unroll
        for (int ks = 0; ks < 2; ks++) {
            const uint32_t koff = ks * 32;
            uint32_t af[2][4];
#pragma unroll
            for (int mt = 0; mt < 2; mt++)
                ldsm_x4(af[mt], aAddr[cur][mt] + koff);
            uint32_t bf[8][2];
#pragma unroll
            for (int np = 0; np < 4; np++) {
                uint32_t r[4];
                ldsm_x4(r, bAddr[cur][np] + koff);
                bf[2 * np][0]     = r[0]; bf[2 * np][1]     = r[2];
                bf[2 * np + 1][0] = r[1]; bf[2 * np + 1][1] = r[3];
            }
#pragma unroll
            for (int mt = 0; mt < 2; mt++)
#pragma unroll
                for (int nt = 0; nt < 8; nt++)
                    mma_16816(acc[mt][nt], af[mt], bf[nt]);
        }
        if (more) {
            const int nxt = cur ^ 1;
#pragma unroll
            for (int p = 0; p < 2; p++) {
                *(uint4*)&As[nxt][ldRow[p]][ldCh[p]] = an[p];
                *(uint4*)&Bs[nxt][ldRow[p]][ldCh[p]] = bn[p];
            }
        }
        __syncthreads();
    }

    const int cr = lane >> 2;
    const int cc = (lane & 3) * 2;
#pragma unroll
    for (int mt = 0; mt < 2; mt++) {
        const int r0 = m0 + wm * 32 + mt * 16 + cr;
#pragma unroll
        for (int nt = 0; nt < 8; nt++) {
            const int col = n0 + wn * 64 + nt * 8 + cc;
            const float b0 = __ldg(&bias[col]);
            const float b1 = __ldg(&bias[col + 1]);
            float2 v0, v1;
            v0.x = acc[mt][nt][0] + b0; v0.y = acc[mt][nt][1] + b1;
            v1.x = acc[mt][nt][2] + b0; v1.y = acc[mt][nt][3] + b1;
            *(float2*)&C[(size_t)r0 * N + col]       = v0;
            *(float2*)&C[(size_t)(r0 + 8) * N + col] = v1;
        }
    }
}

// ---------------------------------------------------------------------------
// bf16x3 split of activations: X[M,K] fp32 -> O[M,3K] = [hi | lo | hi]
// ---------------------------------------------------------------------------
__global__ __launch_bounds__(256) void split_A(
    const float* __restrict__ X, __nv_bfloat16* __restrict__ O, int MK, int K)
{
    int idx = blockIdx.x * 256 + threadIdx.x;
    if (idx >= MK) return;
    int m = idx / K, k = idx - m * K;
    float x = X[idx];
    __nv_bfloat16 h, l; sp(x, h, l);
    size_t o = (size_t)m * (3 * K) + k;
    O[o]         = h;
    O[o + K]     = l;
    O[o + 2 * K] = h;
}

// ---------------------------------------------------------------------------
// bf16x3 split + transpose of weights: W[K,N] fp32 -> O[N,3K] = [hi ; hi ; lo]
// ---------------------------------------------------------------------------
__global__ __launch_bounds__(256) void convert_B(
    const float* __restrict__ W, __nv_bfloat16* __restrict__ O, int K, int N)
{
    __shared__ float t[32][33];
    const int k0 = blockIdx.y * 32, n0 = blockIdx.x * 32;
    const int tx = threadIdx.x, ty = threadIdx.y;
#pragma unroll
    for (int i = 0; i < 32; i += 8)
        t[ty + i][tx] = W[(size_t)(k0 + ty + i) * N + n0 + tx];
    __syncthreads();
#pragma unroll
    for (int i = 0; i < 32; i += 8) {
        int n = n0 + ty + i, k = k0 + tx;
        float x = t[tx][ty + i];
        __nv_bfloat16 h, l; sp(x, h, l);
        size_t o = (size_t)n * (3 * K) + k;
        O[o]         = h;
        O[o + K]     = h;
        O[o + 2 * K] = l;
    }
}

// ---------------------------------------------------------------------------
// RoPE + bf16x3 split of q,k: reads g_qkv fp32, writes g_Q3 / g_K3.
// Q3 row: [Qh(80) | Ql(80) | Qh(80)], K3 row: [Kh | Kh | Kl]. q pre-scaled.
// ---------------------------------------------------------------------------
__global__ __launch_bounds__(256) void rope_split(
    const float* __restrict__ cosp, const float* __restrict__ sinp)
{
    int idx = blockIdx.x * blockDim.x + threadIdx.x;
    const int total = TOTAL * HEADS * (HEAD_DIM / 2);
    if (idx >= total) return;
    int d = idx % 40;
    int h = (idx / 40) % HEADS;
    int t = idx / (40 * HEADS);

    float c1 = cosp[t * HEAD_DIM + d];
    float s1 = sinp[t * HEAD_DIM + d];
    float c2 = cosp[t * HEAD_DIM + d + 40];
    float s2 = sinp[t * HEAD_DIM + d + 40];

    const float* row = g_qkv + (size_t)t * QKVN;
    int qi = h * HEAD_DIM + d;

    float q1 = row[qi], q2 = row[qi + 40];
    float rq1 = (q1 * c1 - q2 * s1) * SCALE;
    float rq2 = (q2 * c2 + q1 * s2) * SCALE;

    float k1 = row[HIDDEN + qi], k2 = row[HIDDEN + qi + 40];
    float rk1 = k1 * c1 - k2 * s1;
    float rk2 = k2 * c2 + k1 * s2;

    __nv_bfloat16 hh, ll;
    __nv_bfloat16* Q = g_Q3 + ((size_t)t * HEADS + h) * 240;
    __nv_bfloat16* K = g_K3 + ((size_t)t * HEADS + h) * 240;

    sp(rq1, hh, ll); Q[d]      = hh; Q[80 + d]      = ll; Q[160 + d]      = hh;
    sp(rq2, hh, ll); Q[d + 40] = hh; Q[80 + d + 40] = ll; Q[160 + d + 40] = hh;
    sp(rk1, hh, ll); K[d]      = hh; K[80 + d]      = hh; K[160 + d]      = ll;
    sp(rk2, hh, ll); K[d + 40] = hh; K[80 + d + 40] = hh; K[160 + d + 40] = ll;
}

// ---------------------------------------------------------------------------
// V transpose + split: g_qkv v-part [t][h*80+d] -> g_Vt3 [c][h][d][Vh|Vh|Vl]
// ---------------------------------------------------------------------------
__global__ __launch_bounds__(256) void vtrans()
{
    __shared__ float vs[64][81];
    const int tid = threadIdx.x;
    const int t0  = blockIdx.x * 64;
    const int h   = blockIdx.y;
    const int c   = t0 / CHUNK_L;
#pragma unroll
    for (int i = 0; i < 20; i++) {
        int idx = tid + i * 256;            // 5120 = 64*80
        int r = idx / 80, d = idx % 80;
        vs[r][d] = g_qkv[(size_t)(t0 + r) * QKVN + 2 * HIDDEN + h * HEAD_DIM + d];
    }
    __syncthreads();
#pragma unroll
    for (int i = 0; i < 20; i++) {
        int idx = tid + i * 256;
        int d = idx / 64, tl = idx % 64;
        float v = vs[tl][d];
        __nv_bfloat16 hh, ll; sp(v, hh, ll);
        size_t base = ((size_t)(c * HEADS + h) * HEAD_DIM + d) * (3 * CHUNK_L)
                      + (t0 - c * CHUNK_L) + tl;
        g_Vt3[base]                 = hh;
        g_Vt3[base + CHUNK_L]       = hh;
        g_Vt3[base + 2 * CHUNK_L]   = ll;
    }
}

// ---------------------------------------------------------------------------
// Tensor-core flash attention. One CTA = 128 q-rows of one (chunk, head).
// 8 warps; warp w owns q-rows [w*16, w*16+16) for the entire kernel.
// kv tiles of 64; S k-dim = 240 (bf16x3), PV k-dim = 192 (bf16x3).
// ---------------------------------------------------------------------------
#define LDQ 248   /* 240 + 8 pad */
#define LDP 200   /* 192 + 8 pad */
#define SM_Q 0
#define SM_K (SM_Q + 128 * LDQ * 2)       /* 63488  */
#define SM_V (SM_K + 64 * LDQ * 2)        /* 95232  */
#define SM_P (SM_V + 80 * LDP * 2)        /* 127232 */
#define SM_TOT (SM_P + 128 * LDP * 2)     /* 178432 */

__global__ __launch_bounds__(256) void flash_mma()
{
    extern __shared__ char sm[];
    __nv_bfloat16 (*Q3s)[LDQ] = (__nv_bfloat16(*)[LDQ])(sm + SM_Q);
    __nv_bfloat16 (*K3s)[LDQ] = (__nv_bfloat16(*)[LDQ])(sm + SM_K);
    __nv_bfloat16 (*Vts)[LDP] = (__nv_bfloat16(*)[LDP])(sm + SM_V);
    __nv_bfloat16 (*P3s)[LDP] = (__nv_bfloat16(*)[LDP])(sm + SM_P);

    const int tid  = threadIdx.x;
    const int w    = tid >> 5;
    const int lane = tid & 31;
    const int h    = blockIdx.y;
    const int c    = blockIdx.z;
    const int q0   = c * CHUNK_L + blockIdx.x * 128;

    // load Q3 tile: 128 rows x 240 = 3840 uint4
#pragma unroll
    for (int i = 0; i < 15; i++) {
        int idx = tid + i * 256;
        int r = idx / 30, j = idx % 30;
        *(uint4*)&Q3s[r][j * 8] =
            *(const uint4*)&g_Q3[((size_t)(q0 + r) * HEADS + h) * 240 + j * 8];
    }

    const int lrow = lane & 15;
    const int lcol = (lane >> 4) << 3;
    const uint32_t qAddr = smem_u32(&Q3s[w * 16 + lrow][lcol]);
    const uint32_t pAddr = smem_u32(&P3s[w * 16 + lrow][lcol]);
    uint32_t kAddr[4], vAddr[5];
#pragma unroll
    for (int np = 0; np < 4; np++)
        kAddr[np] = smem_u32(&K3s[np * 16 + lrow][lcol]);
#pragma unroll
    for (int np = 0; np < 5; np++)
        vAddr[np] = smem_u32(&Vts[np * 16 + lrow][lcol]);

    const int cr = lane >> 2;
    const int cc = (lane & 3) * 2;
    uint32_t* Prow0 = (uint32_t*)&P3s[w * 16 + cr][0];
    uint32_t* Prow1 = (uint32_t*)&P3s[w * 16 + cr + 8][0];

    float O[10][4];
#pragma unroll
    for (int nt = 0; nt < 10; nt++)
#pragma unroll
        for (int v = 0; v < 4; v++) O[nt][v] = 0.0f;
    float m0 = -1e30f, m1 = -1e30f, l0 = 0.0f, l1 = 0.0f;

    const size_t kBase = (size_t)c * CHUNK_L * QKVN;  (void)kBase;
    const size_t vBase = (size_t)(c * HEADS + h) * HEAD_DIM * (3 * CHUNK_L);

    for (int kt = 0; kt < CHUNK_L / 64; kt++) {
        const int kv0 = kt * 64;
        __syncthreads();   // prev PV done reading K3s/Vts/P3s
        // load K3 tile (1920 uint4) + Vt tile (1920 uint4)
#pragma unroll
        for (int i = 0; i < 15; i++) {
            int idx = tid + i * 256;     // 0..3839
            if (idx < 1920) {
                int r = idx / 30, j = idx % 30;
                *(uint4*)&K3s[r][j * 8] =
                    *(const uint4*)&g_K3[((size_t)(c * CHUNK_L + kv0 + r) * HEADS + h) * 240 + j * 8];
            } else {
                int vx = idx - 1920;
                int j = vx & 7, b = (vx >> 3) % 3, d = vx / 24;
                *(uint4*)&Vts[d][b * 64 + j * 8] =
                    *(const uint4*)&g_Vt3[vBase + (size_t)d * (3 * CHUNK_L) + b * CHUNK_L + kv0 + j * 8];
            }
        }
        __syncthreads();

        // ---- S = Q3 @ K3^T (k = 240) ----
        float s[8][4];
#pragma unroll
        for (int nt = 0; nt < 8; nt++)
#pragma unroll
            for (int v = 0; v < 4; v++) s[nt][v] = 0.0f;
#pragma unroll
        for (int ks = 0; ks < 15; ks++) {
            uint32_t af[4];
            ldsm_x4(af, qAddr + ks * 32);
            uint32_t bf[8][2];
#pragma unroll
            for (int np = 0; np < 4; np++) {
                uint32_t r[4];
                ldsm_x4(r, kAddr[np] + ks * 32);
                bf[2 * np][0]     = r[0]; bf[2 * np][1]     = r[2];
                bf[2 * np + 1][0] = r[1]; bf[2 * np + 1][1] = r[3];
            }
#pragma unroll
            for (int nt = 0; nt < 8; nt++)
                mma_16816(s[nt], af, bf[nt]);
        }

        // ---- online softmax (rows cr and cr+8 of this warp's 16) ----
        float tm0 = -1e30f, tm1 = -1e30f;
#pragma unroll
        for (int nt = 0; nt < 8; nt++) {
            tm0 = fmaxf(tm0, fmaxf(s[nt][0], s[nt][1]));
            tm1 = fmaxf(tm1, fmaxf(s[nt][2], s[nt][3]));
        }
        tm0 = fmaxf(tm0, __shfl_xor_sync(0xffffffffu, tm0, 1));
        tm0 = fmaxf(tm0, __shfl_xor_sync(0xffffffffu, tm0, 2));
        tm1 = fmaxf(tm1, __shfl_xor_sync(0xffffffffu, tm1, 1));
        tm1 = fmaxf(tm1, __shfl_xor_sync(0xffffffffu, tm1, 2));
        const float nm0 = fmaxf(m0, tm0);
        const float nm1 = fmaxf(m1, tm1);
        const float a0 = __expf(m0 - nm0);
        const float a1 = __expf(m1 - nm1);
        m0 = nm0; m1 = nm1;

        float sum0 = 0.0f, sum1 = 0.0f;
#pragma unroll
        for (int nt = 0; nt < 8; nt++) {
            float p00 = __expf(s[nt][0] - nm0);
            float p01 = __expf(s[nt][1] - nm0);
            float p10 = __expf(s[nt][2] - nm1);
            float p11 = __expf(s[nt][3] - nm1);
            sum0 += p00 + p01;
            sum1 += p10 + p11;
            const int cw = (nt * 8 + cc) >> 1;   // u32 column index
            uint32_t hp0 = packbf2(p00, p01);
            uint32_t hp1 = packbf2(p10, p11);
            float h00 = __uint_as_float(hp0 << 16);
            float h01 = __uint_as_float(hp0 & 0xFFFF0000u);
            float h10 = __uint_as_float(hp1 << 16);
            float h11 = __uint_as_float(hp1 & 0xFFFF0000u);
            uint32_t lp0 = packbf2(p00 - h00, p01 - h01);
            uint32_t lp1 = packbf2(p10 - h10, p11 - h11);
            Prow0[cw]      = hp0;  Prow1[cw]      = hp1;   // Ph block 0
            Prow0[cw + 32] = lp0;  Prow1[cw + 32] = lp1;   // Pl block 1
            Prow0[cw + 64] = hp0;  Prow1[cw + 64] = hp1;   // Ph block 2
        }
        sum0 += __shfl_xor_sync(0xffffffffu, sum0, 1);
        sum0 += __shfl_xor_sync(0xffffffffu, sum0, 2);
        sum1 += __shfl_xor_sync(0xffffffffu, sum1, 1);
        sum1 += __shfl_xor_sync(0xffffffffu, sum1, 2);
        l0 = l0 * a0 + sum0;
        l1 = l1 * a1 + sum1;

#pragma unroll
        for (int nt = 0; nt < 10; nt++) {
            O[nt][0] *= a0; O[nt][1] *= a0;
            O[nt][2] *= a1; O[nt][3] *= a1;
        }
        __syncthreads();   // P3s visible to ldmatrix

        // ---- O += P3 @ Vt3^T (k = 192, n = 80) ----
#pragma unroll
        for (int ks = 0; ks < 12; ks++) {
            uint32_t af[4];
            ldsm_x4(af, pAddr + ks * 32);
            uint32_t bf[10][2];
#pragma unroll
            for (int np = 0; np < 5; np++) {
                uint32_t r[4];
                ldsm_x4(r, vAddr[np] + ks * 32);
                bf[2 * np][0]     = r[0]; bf[2 * np][1]     = r[2];
                bf[2 * np + 1][0] = r[1]; bf[2 * np + 1][1] = r[3];
            }
#pragma unroll
            for (int nt = 0; nt < 10; nt++)
                mma_16816(O[nt], af, bf[nt]);
        }
    }

    // ---- normalize and store ----
    const float inv0 = 1.0f / l0;
    const float inv1 = 1.0f / l1;
    const int r0 = q0 + w * 16 + cr;
#pragma unroll
    for (int nt = 0; nt < 10; nt++) {
        const int col = h * HEAD_DIM + nt * 8 + cc;
        float2 v0, v1;
        v0.x = O[nt][0] * inv0; v0.y = O[nt][1] * inv0;
        v1.x = O[nt][2] * inv1; v1.y = O[nt][3] * inv1;
        *(float2*)&g_attn[(size_t)r0 * HIDDEN + col]       = v0;
        *(float2*)&g_attn[(size_t)(r0 + 8) * HIDDEN + col] = v1;
    }
}

// ---------------------------------------------------------------------------
extern "C" void kernel_launch(void* const* d_in, const int* in_sizes, int n_in,
                              void* d_out, int out_size)
{
    (void)in_sizes; (void)n_in; (void)out_size;
    const float* x      = (const float*)d_in[0];
    const float* cosp   = (const float*)d_in[1];
    const float* sinp   = (const float*)d_in[2];
    const float* w_qkv  = (const float*)d_in[3];
    const float* b_qkv  = (const float*)d_in[4];
    const float* w_proj = (const float*)d_in[5];
    const float* b_proj = (const float*)d_in[6];
    float* out = (float*)d_out;

    float *qkv = nullptr, *attn = nullptr;
    __nv_bfloat16 *Aq = nullptr, *Ap = nullptr, *Bq = nullptr, *Bp = nullptr;
    cudaGetSymbolAddress((void**)&qkv,  g_qkv);
    cudaGetSymbolAddress((void**)&attn, g_attn);
    cudaGetSymbolAddress((void**)&Aq,   g_Aq);
    cudaGetSymbolAddress((void**)&Ap,   g_Ap);
    cudaGetSymbolAddress((void**)&Bq,   g_Bq);
    cudaGetSymbolAddress((void**)&Bp,   g_Bp);

    cudaFuncSetAttribute(flash_mma,
                         cudaFuncAttributeMaxDynamicSharedMemorySize, SM_TOT);

    // weight + activation bf16x3 conversion
    convert_B<<<dim3(QKVN / 32, HIDDEN / 32), dim3(32, 8)>>>(w_qkv, Bq, HIDDEN, QKVN);
    convert_B<<<dim3(HIDDEN / 32, HIDDEN / 32), dim3(32, 8)>>>(w_proj, Bp, HIDDEN, HIDDEN);
    {
        int mk = TOTAL * HIDDEN;
        split_A<<<(mk + 255) / 256, 256>>>(x, Aq, mk, HIDDEN);
    }

    // 1) QKV projection (tensor cores)
    gemm_bf16_mma<<<dim3(QKVN / 128, TOTAL / 128), 256>>>(Aq, Bq, b_qkv, qkv, QKVN);

    // 2) RoPE + q/k split ; V transpose + split
    {
        int total = TOTAL * HEADS * (HEAD_DIM / 2);
        rope_split<<<(total + 255) / 256, 256>>>(cosp, sinp);
    }
    vtrans<<<dim3(TOTAL / 64, HEADS), 256>>>();

    // 3) tensor-core flash attention
    flash_mma<<<dim3(CHUNK_L / 128, HEADS, NCHUNK), 256, SM_TOT>>>();

    // 4) output projection (tensor cores)
    {
        int mk = TOTAL * HIDDEN;
        split_A<<<(mk + 255) / 256, 256>>>(attn, Ap, mk, HIDDEN);
    }
    gemm_bf16_mma<<<dim3(HIDDEN / 128, TOTAL / 128), 256>>>(Ap, Bp, b_proj, out, HIDDEN);
}

// round 5
// speedup vs baseline: 2.0318x; 1.0233x over previous
#include <cuda_runtime.h>
#include <cuda_bf16.h>
#include <cstdint>

#define TOTAL    8192
#define HIDDEN   1280
#define HEADS    16
#define HEAD_DIM 80
#define NCHUNK   8
#define CHUNK_L  1024
#define QKVN     3840
#define K3       3840   /* 3 * 1280 : tripled K for the bf16x3 trick */
#define SCALE    0.11180339887498949f  /* 80^-0.5 */

// ---------------- device scratch (no allocs allowed) ----------------
__device__ float         g_qkv [(size_t)TOTAL * QKVN];
__device__ float         g_attn[(size_t)TOTAL * HIDDEN];
__device__ __nv_bfloat16 g_Aq  [(size_t)TOTAL * K3];
__device__ __nv_bfloat16 g_Ap  [(size_t)TOTAL * K3];
__device__ __nv_bfloat16 g_Bq  [(size_t)QKVN  * K3];
__device__ __nv_bfloat16 g_Bp  [(size_t)HIDDEN* K3];
__device__ __nv_bfloat16 g_Q3 [(size_t)TOTAL * HEADS * 240];
__device__ __nv_bfloat16 g_K3 [(size_t)TOTAL * HEADS * 240];
__device__ __nv_bfloat16 g_Vt3[(size_t)NCHUNK * HEADS * HEAD_DIM * 3 * CHUNK_L];

// ---------------- PTX helpers ----------------
__device__ __forceinline__ uint32_t smem_u32(const void* p) {
    uint32_t a;
    asm("{ .reg .u64 t; cvta.to.shared.u64 t, %1; cvt.u32.u64 %0, t; }"
        : "=r"(a) : "l"(p));
    return a;
}
__device__ __forceinline__ void ldsm_x4(uint32_t* r, uint32_t addr) {
    asm volatile("ldmatrix.sync.aligned.m8n8.x4.shared.b16 {%0,%1,%2,%3}, [%4];"
                 : "=r"(r[0]), "=r"(r[1]), "=r"(r[2]), "=r"(r[3]) : "r"(addr));
}
__device__ __forceinline__ void mma_16816(float* c, const uint32_t* a,
                                          const uint32_t* b) {
    asm volatile(
        "mma.sync.aligned.m16n8k16.row.col.f32.bf16.bf16.f32 "
        "{%0,%1,%2,%3}, {%4,%5,%6,%7}, {%8,%9}, {%0,%1,%2,%3};"
        : "+f"(c[0]), "+f"(c[1]), "+f"(c[2]), "+f"(c[3])
        : "r"(a[0]), "r"(a[1]), "r"(a[2]), "r"(a[3]), "r"(b[0]), "r"(b[1]));
}
__device__ __forceinline__ void cp16(uint32_t dst, const void* src) {
    asm volatile("cp.async.cg.shared.global [%0], [%1], 16;"
                 :: "r"(dst), "l"(src));
}
__device__ __forceinline__ void cp_commit() {
    asm volatile("cp.async.commit_group;" ::: "memory");
}
template <int W>
__device__ __forceinline__ void cp_wait() {
    asm volatile("cp.async.wait_group %0;" :: "n"(W) : "memory");
}
__device__ __forceinline__ uint32_t packbf2(float lo, float hi) {
    uint32_t r;
    asm("cvt.rn.bf16x2.f32 %0, %1, %2;" : "=r"(r) : "f"(hi), "f"(lo));
    return r;
}
__device__ __forceinline__ void sp(float x, __nv_bfloat16& h, __nv_bfloat16& l) {
    h = __float2bfloat16(x);
    l = __float2bfloat16(x - __bfloat162float(h));
}

// ---------------------------------------------------------------------------
// Tensor-core GEMM: C[8192, N] = A[8192, K3] * B[N, K3]^T + bias
// 128x128 CTA tile, 4 warps (2x2) each 64x64, BK=32, 3-stage cp.async pipe.
// ---------------------------------------------------------------------------
#define BK     32
#define NST    3
#define LDAE   40                 /* smem row: 32 + 8 pad elements */
#define ROWB   (LDAE * 2)         /* 80 bytes */
#define STAGEB (128 * ROWB)       /* 10240 bytes per matrix per stage */
#define BOFF   (NST * STAGEB)     /* 30720 : B base */
#define GSMEM  (2 * NST * STAGEB) /* 61440 */

__global__ __launch_bounds__(128, 2) void gemm_bf16_mma(
    const __nv_bfloat16* __restrict__ A, const __nv_bfloat16* __restrict__ B,
    const float* __restrict__ bias, float* __restrict__ C, int N)
{
    extern __shared__ char sm[];
    const int tid  = threadIdx.x;
    const int wid  = tid >> 5;
    const int lane = tid & 31;
    const int m0   = blockIdx.y * 128;
    const int n0   = blockIdx.x * 128;
    const int wm   = wid & 1;
    const int wn   = wid >> 1;

    // cp.async global->smem mapping: 4 x 16B per thread for A and for B
    uint32_t aDst[4], bDst[4];
    const __nv_bfloat16 *aS[4], *bS[4];
#pragma unroll
    for (int p = 0; p < 4; p++) {
        int u  = tid + p * 128;
        int r  = u >> 2;
        int ch = (u & 3) * 8;
        aDst[p] = smem_u32(sm + r * ROWB + ch * 2);
        bDst[p] = aDst[p] + BOFF;
        aS[p]   = A + (size_t)(m0 + r) * K3 + ch;
        bS[p]   = B + (size_t)(n0 + r) * K3 + ch;
    }

    float acc[4][8][4];
#pragma unroll
    for (int mt = 0; mt < 4; mt++)
#pragma unroll
        for (int nt = 0; nt < 8; nt++)
#pragma unroll
            for (int v = 0; v < 4; v++) acc[mt][nt][v] = 0.0f;

    // ldmatrix addresses (stage 0; add stage offset at use)
    const int lrow  = lane & 15;
    const int lcolb = ((lane >> 4) << 3) * 2;
    uint32_t aAddr[4], bAddr[4];
#pragma unroll
    for (int mt = 0; mt < 4; mt++)
        aAddr[mt] = smem_u32(sm + (wm * 64 + mt * 16 + lrow) * ROWB + lcolb);
#pragma unroll
    for (int np = 0; np < 4; np++)
        bAddr[np] = smem_u32(sm + BOFF + (wn * 64 + np * 16 + lrow) * ROWB + lcolb);

    // prefetch stages for kb = 0, 1
#pragma unroll
    for (int s = 0; s < 2; s++) {
#pragma unroll
        for (int p = 0; p < 4; p++) {
            cp16(aDst[p] + s * STAGEB, aS[p] + s * BK);
            cp16(bDst[p] + s * STAGEB, bS[p] + s * BK);
        }
        cp_commit();
    }

    const int NKB = K3 / BK;   // 120
    for (int kb = 0; kb < NKB; kb++) {
        cp_wait<1>();
        __syncthreads();

        const int nxt = kb + 2;
        if (nxt < NKB) {
            const uint32_t so = (uint32_t)(nxt % NST) * STAGEB;
#pragma unroll
            for (int p = 0; p < 4; p++) {
                cp16(aDst[p] + so, aS[p] + nxt * BK);
                cp16(bDst[p] + so, bS[p] + nxt * BK);
            }
        }
        cp_commit();

        const uint32_t base = (uint32_t)(kb % NST) * STAGEB;
#pragma unroll
        for (int ks = 0; ks < 2; ks++) {
            const uint32_t ko = base + ks * 32;
            uint32_t af[4][4];
#pragma unroll
            for (int mt = 0; mt < 4; mt++)
                ldsm_x4(af[mt], aAddr[mt] + ko);
            uint32_t bf[8][2];
#pragma unroll
            for (int np = 0; np < 4; np++) {
                uint32_t r[4];
                ldsm_x4(r, bAddr[np] + ko);
                bf[2 * np][0]     = r[0]; bf[2 * np][1]     = r[2];
                bf[2 * np + 1][0] = r[1]; bf[2 * np + 1][1] = r[3];
            }
#pragma unroll
            for (int mt = 0; mt < 4; mt++)
#pragma unroll
                for (int nt = 0; nt < 8; nt++)
                    mma_16816(acc[mt][nt], af[mt], bf[nt]);
        }
    }

    // epilogue: bias + store
    const int cr = lane >> 2;
    const int cc = (lane & 3) * 2;
#pragma unroll
    for (int mt = 0; mt < 4; mt++) {
        const int r0 = m0 + wm * 64 + mt * 16 + cr;
#pragma unroll
        for (int nt = 0; nt < 8; nt++) {
            const int col = n0 + wn * 64 + nt * 8 + cc;
            const float b0 = __ldg(&bias[col]);
            const float b1 = __ldg(&bias[col + 1]);
            float2 v0, v1;
            v0.x = acc[mt][nt][0] + b0; v0.y = acc[mt][nt][1] + b1;
            v1.x = acc[mt][nt][2] + b0; v1.y = acc[mt][nt][3] + b1;
            *(float2*)&C[(size_t)r0 * N + col]       = v0;
            *(float2*)&C[(size_t)(r0 + 8) * N + col] = v1;
        }
    }
}

// ---------------------------------------------------------------------------
// bf16x3 split of activations: X[M,K] fp32 -> O[M,3K] = [hi | lo | hi]
// ---------------------------------------------------------------------------
__global__ __launch_bounds__(256) void split_A(
    const float* __restrict__ X, __nv_bfloat16* __restrict__ O, int MK, int K)
{
    int idx = blockIdx.x * 256 + threadIdx.x;
    if (idx >= MK) return;
    int m = idx / K, k = idx - m * K;
    float x = X[idx];
    __nv_bfloat16 h, l; sp(x, h, l);
    size_t o = (size_t)m * (3 * K) + k;
    O[o]         = h;
    O[o + K]     = l;
    O[o + 2 * K] = h;
}

// ---------------------------------------------------------------------------
// bf16x3 split + transpose of weights: W[K,N] fp32 -> O[N,3K] = [hi ; hi ; lo]
// ---------------------------------------------------------------------------
__global__ __launch_bounds__(256) void convert_B(
    const float* __restrict__ W, __nv_bfloat16* __restrict__ O, int K, int N)
{
    __shared__ float t[32][33];
    const int k0 = blockIdx.y * 32, n0 = blockIdx.x * 32;
    const int tx = threadIdx.x, ty = threadIdx.y;
#pragma unroll
    for (int i = 0; i < 32; i += 8)
        t[ty + i][tx] = W[(size_t)(k0 + ty + i) * N + n0 + tx];
    __syncthreads();
#pragma unroll
    for (int i = 0; i < 32; i += 8) {
        int n = n0 + ty + i, k = k0 + tx;
        float x = t[tx][ty + i];
        __nv_bfloat16 h, l; sp(x, h, l);
        size_t o = (size_t)n * (3 * K) + k;
        O[o]         = h;
        O[o + K]     = h;
        O[o + 2 * K] = l;
    }
}

// ---------------------------------------------------------------------------
// RoPE + bf16x3 split of q,k (q pre-scaled by hd^-0.5).
// ---------------------------------------------------------------------------
__global__ __launch_bounds__(256) void rope_split(
    const float* __restrict__ cosp, const float* __restrict__ sinp)
{
    int idx = blockIdx.x * blockDim.x + threadIdx.x;
    const int total = TOTAL * HEADS * (HEAD_DIM / 2);
    if (idx >= total) return;
    int d = idx % 40;
    int h = (idx / 40) % HEADS;
    int t = idx / (40 * HEADS);

    float c1 = cosp[t * HEAD_DIM + d];
    float s1 = sinp[t * HEAD_DIM + d];
    float c2 = cosp[t * HEAD_DIM + d + 40];
    float s2 = sinp[t * HEAD_DIM + d + 40];

    const float* row = g_qkv + (size_t)t * QKVN;
    int qi = h * HEAD_DIM + d;

    float q1 = row[qi], q2 = row[qi + 40];
    float rq1 = (q1 * c1 - q2 * s1) * SCALE;
    float rq2 = (q2 * c2 + q1 * s2) * SCALE;

    float k1 = row[HIDDEN + qi], k2 = row[HIDDEN + qi + 40];
    float rk1 = k1 * c1 - k2 * s1;
    float rk2 = k2 * c2 + k1 * s2;

    __nv_bfloat16 hh, ll;
    __nv_bfloat16* Q = g_Q3 + ((size_t)t * HEADS + h) * 240;
    __nv_bfloat16* K = g_K3 + ((size_t)t * HEADS + h) * 240;

    sp(rq1, hh, ll); Q[d]      = hh; Q[80 + d]      = ll; Q[160 + d]      = hh;
    sp(rq2, hh, ll); Q[d + 40] = hh; Q[80 + d + 40] = ll; Q[160 + d + 40] = hh;
    sp(rk1, hh, ll); K[d]      = hh; K[80 + d]      = hh; K[160 + d]      = ll;
    sp(rk2, hh, ll); K[d + 40] = hh; K[80 + d + 40] = hh; K[160 + d + 40] = ll;
}

// ---------------------------------------------------------------------------
// V transpose + split
// ---------------------------------------------------------------------------
__global__ __launch_bounds__(256) void vtrans()
{
    __shared__ float vs[64][81];
    const int tid = threadIdx.x;
    const int t0  = blockIdx.x * 64;
    const int h   = blockIdx.y;
    const int c   = t0 / CHUNK_L;
#pragma unroll
    for (int i = 0; i < 20; i++) {
        int idx = tid + i * 256;
        int r = idx / 80, d = idx % 80;
        vs[r][d] = g_qkv[(size_t)(t0 + r) * QKVN + 2 * HIDDEN + h * HEAD_DIM + d];
    }
    __syncthreads();
#pragma unroll
    for (int i = 0; i < 20; i++) {
        int idx = tid + i * 256;
        int d = idx / 64, tl = idx % 64;
        float v = vs[tl][d];
        __nv_bfloat16 hh, ll; sp(v, hh, ll);
        size_t base = ((size_t)(c * HEADS + h) * HEAD_DIM + d) * (3 * CHUNK_L)
                      + (t0 - c * CHUNK_L) + tl;
        g_Vt3[base]               = hh;
        g_Vt3[base + CHUNK_L]     = hh;
        g_Vt3[base + 2 * CHUNK_L] = ll;
    }
}

// ---------------------------------------------------------------------------
// Tensor-core flash attention (unchanged from R4 — verified).
// ---------------------------------------------------------------------------
#define LDQ 248
#define LDP 200
#define SM_Q 0
#define SM_K (SM_Q + 128 * LDQ * 2)
#define SM_V (SM_K + 64 * LDQ * 2)
#define SM_P (SM_V + 80 * LDP * 2)
#define SM_TOT (SM_P + 128 * LDP * 2)

__global__ __launch_bounds__(256) void flash_mma()
{
    extern __shared__ char sm[];
    __nv_bfloat16 (*Q3s)[LDQ] = (__nv_bfloat16(*)[LDQ])(sm + SM_Q);
    __nv_bfloat16 (*K3s)[LDQ] = (__nv_bfloat16(*)[LDQ])(sm + SM_K);
    __nv_bfloat16 (*Vts)[LDP] = (__nv_bfloat16(*)[LDP])(sm + SM_V);
    __nv_bfloat16 (*P3s)[LDP] = (__nv_bfloat16(*)[LDP])(sm + SM_P);

    const int tid  = threadIdx.x;
    const int w    = tid >> 5;
    const int lane = tid & 31;
    const int h    = blockIdx.y;
    const int c    = blockIdx.z;
    const int q0   = c * CHUNK_L + blockIdx.x * 128;

#pragma unroll
    for (int i = 0; i < 15; i++) {
        int idx = tid + i * 256;
        int r = idx / 30, j = idx % 30;
        *(uint4*)&Q3s[r][j * 8] =
            *(const uint4*)&g_Q3[((size_t)(q0 + r) * HEADS + h) * 240 + j * 8];
    }

    const int lrow = lane & 15;
    const int lcol = (lane >> 4) << 3;
    const uint32_t qAddr = smem_u32(&Q3s[w * 16 + lrow][lcol]);
    const uint32_t pAddr = smem_u32(&P3s[w * 16 + lrow][lcol]);
    uint32_t kAddr[4], vAddr[5];
#pragma unroll
    for (int np = 0; np < 4; np++)
        kAddr[np] = smem_u32(&K3s[np * 16 + lrow][lcol]);
#pragma unroll
    for (int np = 0; np < 5; np++)
        vAddr[np] = smem_u32(&Vts[np * 16 + lrow][lcol]);

    const int cr = lane >> 2;
    const int cc = (lane & 3) * 2;
    uint32_t* Prow0 = (uint32_t*)&P3s[w * 16 + cr][0];
    uint32_t* Prow1 = (uint32_t*)&P3s[w * 16 + cr + 8][0];

    float O[10][4];
#pragma unroll
    for (int nt = 0; nt < 10; nt++)
#pragma unroll
        for (int v = 0; v < 4; v++) O[nt][v] = 0.0f;
    float m0 = -1e30f, m1 = -1e30f, l0 = 0.0f, l1 = 0.0f;

    const size_t vBase = (size_t)(c * HEADS + h) * HEAD_DIM * (3 * CHUNK_L);

    for (int kt = 0; kt < CHUNK_L / 64; kt++) {
        const int kv0 = kt * 64;
        __syncthreads();
#pragma unroll
        for (int i = 0; i < 15; i++) {
            int idx = tid + i * 256;
            if (idx < 1920) {
                int r = idx / 30, j = idx % 30;
                *(uint4*)&K3s[r][j * 8] =
                    *(const uint4*)&g_K3[((size_t)(c * CHUNK_L + kv0 + r) * HEADS + h) * 240 + j * 8];
            } else {
                int vx = idx - 1920;
                int j = vx & 7, b = (vx >> 3) % 3, d = vx / 24;
                *(uint4*)&Vts[d][b * 64 + j * 8] =
                    *(const uint4*)&g_Vt3[vBase + (size_t)d * (3 * CHUNK_L) + b * CHUNK_L + kv0 + j * 8];
            }
        }
        __syncthreads();

        float s[8][4];
#pragma unroll
        for (int nt = 0; nt < 8; nt++)
#pragma unroll
            for (int v = 0; v < 4; v++) s[nt][v] = 0.0f;
#pragma unroll
        for (int ks = 0; ks < 15; ks++) {
            uint32_t af[4];
            ldsm_x4(af, qAddr + ks * 32);
            uint32_t bf[8][2];
#pragma unroll
            for (int np = 0; np < 4; np++) {
                uint32_t r[4];
                ldsm_x4(r, kAddr[np] + ks * 32);
                bf[2 * np][0]     = r[0]; bf[2 * np][1]     = r[2];
                bf[2 * np + 1][0] = r[1]; bf[2 * np + 1][1] = r[3];
            }
#pragma unroll
            for (int nt = 0; nt < 8; nt++)
                mma_16816(s[nt], af, bf[nt]);
        }

        float tm0 = -1e30f, tm1 = -1e30f;
#pragma unroll
        for (int nt = 0; nt < 8; nt++) {
            tm0 = fmaxf(tm0, fmaxf(s[nt][0], s[nt][1]));
            tm1 = fmaxf(tm1, fmaxf(s[nt][2], s[nt][3]));
        }
        tm0 = fmaxf(tm0, __shfl_xor_sync(0xffffffffu, tm0, 1));
        tm0 = fmaxf(tm0, __shfl_xor_sync(0xffffffffu, tm0, 2));
        tm1 = fmaxf(tm1, __shfl_xor_sync(0xffffffffu, tm1, 1));
        tm1 = fmaxf(tm1, __shfl_xor_sync(0xffffffffu, tm1, 2));
        const float nm0 = fmaxf(m0, tm0);
        const float nm1 = fmaxf(m1, tm1);
        const float a0 = __expf(m0 - nm0);
        const float a1 = __expf(m1 - nm1);
        m0 = nm0; m1 = nm1;

        float sum0 = 0.0f, sum1 = 0.0f;
#pragma unroll
        for (int nt = 0; nt < 8; nt++) {
            float p00 = __expf(s[nt][0] - nm0);
            float p01 = __expf(s[nt][1] - nm0);
            float p10 = __expf(s[nt][2] - nm1);
            float p11 = __expf(s[nt][3] - nm1);
            sum0 += p00 + p01;
            sum1 += p10 + p11;
            const int cw = (nt * 8 + cc) >> 1;
            uint32_t hp0 = packbf2(p00, p01);
            uint32_t hp1 = packbf2(p10, p11);
            float h00 = __uint_as_float(hp0 << 16);
            float h01 = __uint_as_float(hp0 & 0xFFFF0000u);
            float h10 = __uint_as_float(hp1 << 16);
            float h11 = __uint_as_float(hp1 & 0xFFFF0000u);
            uint32_t lp0 = packbf2(p00 - h00, p01 - h01);
            uint32_t lp1 = packbf2(p10 - h10, p11 - h11);
            Prow0[cw]      = hp0;  Prow1[cw]      = hp1;
            Prow0[cw + 32] = lp0;  Prow1[cw + 32] = lp1;
            Prow0[cw + 64] = hp0;  Prow1[cw + 64] = hp1;
        }
        sum0 += __shfl_xor_sync(0xffffffffu, sum0, 1);
        sum0 += __shfl_xor_sync(0xffffffffu, sum0, 2);
        sum1 += __shfl_xor_sync(0xffffffffu, sum1, 1);
        sum1 += __shfl_xor_sync(0xffffffffu, sum1, 2);
        l0 = l0 * a0 + sum0;
        l1 = l1 * a1 + sum1;

#pragma unroll
        for (int nt = 0; nt < 10; nt++) {
            O[nt][0] *= a0; O[nt][1] *= a0;
            O[nt][2] *= a1; O[nt][3] *= a1;
        }
        __syncthreads();

#pragma unroll
        for (int ks = 0; ks < 12; ks++) {
            uint32_t af[4];
            ldsm_x4(af, pAddr + ks * 32);
            uint32_t bf[10][2];
#pragma unroll
            for (int np = 0; np < 5; np++) {
                uint32_t r[4];
                ldsm_x4(r, vAddr[np] + ks * 32);
                bf[2 * np][0]     = r[0]; bf[2 * np][1]     = r[2];
                bf[2 * np + 1][0] = r[1]; bf[2 * np + 1][1] = r[3];
            }
#pragma unroll
            for (int nt = 0; nt < 10; nt++)
                mma_16816(O[nt], af, bf[nt]);
        }
    }

    const float inv0 = 1.0f / l0;
    const float inv1 = 1.0f / l1;
    const int r0 = q0 + w * 16 + cr;
#pragma unroll
    for (int nt = 0; nt < 10; nt++) {
        const int col = h * HEAD_DIM + nt * 8 + cc;
        float2 v0, v1;
        v0.x = O[nt][0] * inv0; v0.y = O[nt][1] * inv0;
        v1.x = O[nt][2] * inv1; v1.y = O[nt][3] * inv1;
        *(float2*)&g_attn[(size_t)r0 * HIDDEN + col]       = v0;
        *(float2*)&g_attn[(size_t)(r0 + 8) * HIDDEN + col] = v1;
    }
}

// ---------------------------------------------------------------------------
extern "C" void kernel_launch(void* const* d_in, const int* in_sizes, int n_in,
                              void* d_out, int out_size)
{
    (void)in_sizes; (void)n_in; (void)out_size;
    const float* x      = (const float*)d_in[0];
    const float* cosp   = (const float*)d_in[1];
    const float* sinp   = (const float*)d_in[2];
    const float* w_qkv  = (const float*)d_in[3];
    const float* b_qkv  = (const float*)d_in[4];
    const float* w_proj = (const float*)d_in[5];
    const float* b_proj = (const float*)d_in[6];
    float* out = (float*)d_out;

    float *qkv = nullptr, *attn = nullptr;
    __nv_bfloat16 *Aq = nullptr, *Ap = nullptr, *Bq = nullptr, *Bp = nullptr;
    cudaGetSymbolAddress((void**)&qkv,  g_qkv);
    cudaGetSymbolAddress((void**)&attn, g_attn);
    cudaGetSymbolAddress((void**)&Aq,   g_Aq);
    cudaGetSymbolAddress((void**)&Ap,   g_Ap);
    cudaGetSymbolAddress((void**)&Bq,   g_Bq);
    cudaGetSymbolAddress((void**)&Bp,   g_Bp);

    cudaFuncSetAttribute(gemm_bf16_mma,
                         cudaFuncAttributeMaxDynamicSharedMemorySize, GSMEM);
    cudaFuncSetAttribute(flash_mma,
                         cudaFuncAttributeMaxDynamicSharedMemorySize, SM_TOT);

    convert_B<<<dim3(QKVN / 32, HIDDEN / 32), dim3(32, 8)>>>(w_qkv, Bq, HIDDEN, QKVN);
    convert_B<<<dim3(HIDDEN / 32, HIDDEN / 32), dim3(32, 8)>>>(w_proj, Bp, HIDDEN, HIDDEN);
    {
        int mk = TOTAL * HIDDEN;
        split_A<<<(mk + 255) / 256, 256>>>(x, Aq, mk, HIDDEN);
    }

    // 1) QKV projection
    gemm_bf16_mma<<<dim3(QKVN / 128, TOTAL / 128), 128, GSMEM>>>(
        Aq, Bq, b_qkv, qkv, QKVN);

    // 2) RoPE + splits
    {
        int total = TOTAL * HEADS * (HEAD_DIM / 2);
        rope_split<<<(total + 255) / 256, 256>>>(cosp, sinp);
    }
    vtrans<<<dim3(TOTAL / 64, HEADS), 256>>>();

    // 3) flash attention
    flash_mma<<<dim3(CHUNK_L / 128, HEADS, NCHUNK), 256, SM_TOT>>>();

    // 4) output projection
    {
        int mk = TOTAL * HIDDEN;
        split_A<<<(mk + 255) / 256, 256>>>(attn, Ap, mk, HIDDEN);
    }
    gemm_bf16_mma<<<dim3(HIDDEN / 128, TOTAL / 128), 128, GSMEM>>>(
        Ap, Bp, b_proj, out, HIDDEN);
}

// round 6
// speedup vs baseline: 2.8050x; 1.3805x over previous
#include <cuda_runtime.h>
#include <cuda_fp16.h>
#include <cstdint>

#define TOTAL    8192
#define HIDDEN   1280
#define HEADS    16
#define HEAD_DIM 80
#define NCHUNK   8
#define CHUNK_L  1024
#define QKVN     3840
#define K2       2560   /* 2 * 1280 : doubled K for the fp16x2 trick */
#define SCALE    0.11180339887498949f  /* 80^-0.5 */

// ---------------- device scratch (no allocs allowed) ----------------
__device__ float  g_qkv [(size_t)TOTAL * QKVN];
__device__ float  g_attn[(size_t)TOTAL * HIDDEN];
__device__ __half g_Aq  [(size_t)TOTAL * K2];      // [xh | xl]
__device__ __half g_Ap  [(size_t)TOTAL * K2];
__device__ __half g_Bq  [(size_t)QKVN  * K2];      // [wh ; wh] transposed
__device__ __half g_Bp  [(size_t)HIDDEN* K2];
__device__ __half g_Q2 [(size_t)TOTAL * HEADS * 160];  // [Qh|Ql]
__device__ __half g_K2 [(size_t)TOTAL * HEADS * 160];  // [Kh|Kh]
__device__ __half g_Vt2[(size_t)NCHUNK * HEADS * HEAD_DIM * 2 * CHUNK_L];
                                  // [c][h][d][Vh(1024)|Vh(1024)]

// ---------------- PTX helpers ----------------
__device__ __forceinline__ uint32_t smem_u32(const void* p) {
    uint32_t a;
    asm("{ .reg .u64 t; cvta.to.shared.u64 t, %1; cvt.u32.u64 %0, t; }"
        : "=r"(a) : "l"(p));
    return a;
}
__device__ __forceinline__ void ldsm_x4(uint32_t* r, uint32_t addr) {
    asm volatile("ldmatrix.sync.aligned.m8n8.x4.shared.b16 {%0,%1,%2,%3}, [%4];"
                 : "=r"(r[0]), "=r"(r[1]), "=r"(r[2]), "=r"(r[3]) : "r"(addr));
}
__device__ __forceinline__ void mma_16816(float* c, const uint32_t* a,
                                          const uint32_t* b) {
    asm volatile(
        "mma.sync.aligned.m16n8k16.row.col.f32.f16.f16.f32 "
        "{%0,%1,%2,%3}, {%4,%5,%6,%7}, {%8,%9}, {%0,%1,%2,%3};"
        : "+f"(c[0]), "+f"(c[1]), "+f"(c[2]), "+f"(c[3])
        : "r"(a[0]), "r"(a[1]), "r"(a[2]), "r"(a[3]), "r"(b[0]), "r"(b[1]));
}
__device__ __forceinline__ void cp16(uint32_t dst, const void* src) {
    asm volatile("cp.async.cg.shared.global [%0], [%1], 16;"
                 :: "r"(dst), "l"(src));
}
__device__ __forceinline__ void cp_commit() {
    asm volatile("cp.async.commit_group;" ::: "memory");
}
template <int W>
__device__ __forceinline__ void cp_wait() {
    asm volatile("cp.async.wait_group %0;" :: "n"(W) : "memory");
}
__device__ __forceinline__ void sp16(float x, __half& h, __half& l) {
    h = __float2half_rn(x);
    l = __float2half_rn(x - __half2float(h));
}
__device__ __forceinline__ uint32_t pack2h(__half lo, __half hi) {
    return (uint32_t)__half_as_ushort(lo) |
           ((uint32_t)__half_as_ushort(hi) << 16);
}

// ---------------------------------------------------------------------------
// Tensor-core GEMM: C[8192, N] = A[8192, K2] * B[N, K2]^T + bias
// 128x128 CTA tile, 4 warps (2x2) each 64x64, BK=32, 3-stage cp.async pipe.
// ---------------------------------------------------------------------------
#define BK     32
#define NST    3
#define LDAE   40
#define ROWB   (LDAE * 2)
#define STAGEB (128 * ROWB)
#define BOFF   (NST * STAGEB)
#define GSMEM  (2 * NST * STAGEB)

__global__ __launch_bounds__(128, 2) void gemm_fp16_mma(
    const __half* __restrict__ A, const __half* __restrict__ B,
    const float* __restrict__ bias, float* __restrict__ C, int N)
{
    extern __shared__ char sm[];
    const int tid  = threadIdx.x;
    const int wid  = tid >> 5;
    const int lane = tid & 31;
    const int m0   = blockIdx.y * 128;
    const int n0   = blockIdx.x * 128;
    const int wm   = wid & 1;
    const int wn   = wid >> 1;

    uint32_t aDst[4], bDst[4];
    const __half *aS[4], *bS[4];
#pragma unroll
    for (int p = 0; p < 4; p++) {
        int u  = tid + p * 128;
        int r  = u >> 2;
        int ch = (u & 3) * 8;
        aDst[p] = smem_u32(sm + r * ROWB + ch * 2);
        bDst[p] = aDst[p] + BOFF;
        aS[p]   = A + (size_t)(m0 + r) * K2 + ch;
        bS[p]   = B + (size_t)(n0 + r) * K2 + ch;
    }

    float acc[4][8][4];
#pragma unroll
    for (int mt = 0; mt < 4; mt++)
#pragma unroll
        for (int nt = 0; nt < 8; nt++)
#pragma unroll
            for (int v = 0; v < 4; v++) acc[mt][nt][v] = 0.0f;

    const int lrow  = lane & 15;
    const int lcolb = ((lane >> 4) << 3) * 2;
    uint32_t aAddr[4], bAddr[4];
#pragma unroll
    for (int mt = 0; mt < 4; mt++)
        aAddr[mt] = smem_u32(sm + (wm * 64 + mt * 16 + lrow) * ROWB + lcolb);
#pragma unroll
    for (int np = 0; np < 4; np++)
        bAddr[np] = smem_u32(sm + BOFF + (wn * 64 + np * 16 + lrow) * ROWB + lcolb);

#pragma unroll
    for (int s = 0; s < 2; s++) {
#pragma unroll
        for (int p = 0; p < 4; p++) {
            cp16(aDst[p] + s * STAGEB, aS[p] + s * BK);
            cp16(bDst[p] + s * STAGEB, bS[p] + s * BK);
        }
        cp_commit();
    }

    const int NKB = K2 / BK;   // 80
    for (int kb = 0; kb < NKB; kb++) {
        cp_wait<1>();
        __syncthreads();

        const int nxt = kb + 2;
        if (nxt < NKB) {
            const uint32_t so = (uint32_t)(nxt % NST) * STAGEB;
#pragma unroll
            for (int p = 0; p < 4; p++) {
                cp16(aDst[p] + so, aS[p] + nxt * BK);
                cp16(bDst[p] + so, bS[p] + nxt * BK);
            }
        }
        cp_commit();

        const uint32_t base = (uint32_t)(kb % NST) * STAGEB;
#pragma unroll
        for (int ks = 0; ks < 2; ks++) {
            const uint32_t ko = base + ks * 32;
            uint32_t af[4][4];
#pragma unroll
            for (int mt = 0; mt < 4; mt++)
                ldsm_x4(af[mt], aAddr[mt] + ko);
            uint32_t bf[8][2];
#pragma unroll
            for (int np = 0; np < 4; np++) {
                uint32_t r[4];
                ldsm_x4(r, bAddr[np] + ko);
                bf[2 * np][0]     = r[0]; bf[2 * np][1]     = r[2];
                bf[2 * np + 1][0] = r[1]; bf[2 * np + 1][1] = r[3];
            }
#pragma unroll
            for (int mt = 0; mt < 4; mt++)
#pragma unroll
                for (int nt = 0; nt < 8; nt++)
                    mma_16816(acc[mt][nt], af[mt], bf[nt]);
        }
    }

    const int cr = lane >> 2;
    const int cc = (lane & 3) * 2;
#pragma unroll
    for (int mt = 0; mt < 4; mt++) {
        const int r0 = m0 + wm * 64 + mt * 16 + cr;
#pragma unroll
        for (int nt = 0; nt < 8; nt++) {
            const int col = n0 + wn * 64 + nt * 8 + cc;
            const float b0 = __ldg(&bias[col]);
            const float b1 = __ldg(&bias[col + 1]);
            float2 v0, v1;
            v0.x = acc[mt][nt][0] + b0; v0.y = acc[mt][nt][1] + b1;
            v1.x = acc[mt][nt][2] + b0; v1.y = acc[mt][nt][3] + b1;
            *(float2*)&C[(size_t)r0 * N + col]       = v0;
            *(float2*)&C[(size_t)(r0 + 8) * N + col] = v1;
        }
    }
}

// ---------------------------------------------------------------------------
// fp16x2 split of activations: X[M,K] fp32 -> O[M,2K] = [hi | lo]
// ---------------------------------------------------------------------------
__global__ __launch_bounds__(256) void split_A(
    const float* __restrict__ X, __half* __restrict__ O, int MK, int K)
{
    int idx = blockIdx.x * 256 + threadIdx.x;
    if (idx >= MK) return;
    int m = idx / K, k = idx - m * K;
    float x = X[idx];
    __half h, l; sp16(x, h, l);
    size_t o = (size_t)m * (2 * K) + k;
    O[o]     = h;
    O[o + K] = l;
}

// ---------------------------------------------------------------------------
// fp16 weight transpose, duplicated: W[K,N] fp32 -> O[N,2K] = [hi ; hi]
// ---------------------------------------------------------------------------
__global__ __launch_bounds__(256) void convert_B(
    const float* __restrict__ W, __half* __restrict__ O, int K, int N)
{
    __shared__ float t[32][33];
    const int k0 = blockIdx.y * 32, n0 = blockIdx.x * 32;
    const int tx = threadIdx.x, ty = threadIdx.y;
#pragma unroll
    for (int i = 0; i < 32; i += 8)
        t[ty + i][tx] = W[(size_t)(k0 + ty + i) * N + n0 + tx];
    __syncthreads();
#pragma unroll
    for (int i = 0; i < 32; i += 8) {
        int n = n0 + ty + i, k = k0 + tx;
        __half h = __float2half_rn(t[tx][ty + i]);
        size_t o = (size_t)n * (2 * K) + k;
        O[o]     = h;
        O[o + K] = h;
    }
}

// ---------------------------------------------------------------------------
// RoPE + fp16x2 split of q,k (q pre-scaled by hd^-0.5).
// Q2: [Qh(80)|Ql(80)], K2row: [Kh|Kh].
// ---------------------------------------------------------------------------
__global__ __launch_bounds__(256) void rope_split(
    const float* __restrict__ cosp, const float* __restrict__ sinp)
{
    int idx = blockIdx.x * blockDim.x + threadIdx.x;
    const int total = TOTAL * HEADS * (HEAD_DIM / 2);
    if (idx >= total) return;
    int d = idx % 40;
    int h = (idx / 40) % HEADS;
    int t = idx / (40 * HEADS);

    float c1 = cosp[t * HEAD_DIM + d];
    float s1 = sinp[t * HEAD_DIM + d];
    float c2 = cosp[t * HEAD_DIM + d + 40];
    float s2 = sinp[t * HEAD_DIM + d + 40];

    const float* row = g_qkv + (size_t)t * QKVN;
    int qi = h * HEAD_DIM + d;

    float q1 = row[qi], q2 = row[qi + 40];
    float rq1 = (q1 * c1 - q2 * s1) * SCALE;
    float rq2 = (q2 * c2 + q1 * s2) * SCALE;

    float k1 = row[HIDDEN + qi], k2 = row[HIDDEN + qi + 40];
    float rk1 = k1 * c1 - k2 * s1;
    float rk2 = k2 * c2 + k1 * s2;

    __half hh, ll;
    __half* Q = g_Q2 + ((size_t)t * HEADS + h) * 160;
    __half* K = g_K2 + ((size_t)t * HEADS + h) * 160;

    sp16(rq1, hh, ll); Q[d]      = hh; Q[80 + d]      = ll;
    sp16(rq2, hh, ll); Q[d + 40] = hh; Q[80 + d + 40] = ll;
    hh = __float2half_rn(rk1); K[d]      = hh; K[80 + d]      = hh;
    hh = __float2half_rn(rk2); K[d + 40] = hh; K[80 + d + 40] = hh;
}

// ---------------------------------------------------------------------------
// V transpose: g_qkv v-part -> g_Vt2 [c][h][d][Vh|Vh]
// ---------------------------------------------------------------------------
__global__ __launch_bounds__(256) void vtrans()
{
    __shared__ float vs[64][81];
    const int tid = threadIdx.x;
    const int t0  = blockIdx.x * 64;
    const int h   = blockIdx.y;
    const int c   = t0 / CHUNK_L;
#pragma unroll
    for (int i = 0; i < 20; i++) {
        int idx = tid + i * 256;
        int r = idx / 80, d = idx % 80;
        vs[r][d] = g_qkv[(size_t)(t0 + r) * QKVN + 2 * HIDDEN + h * HEAD_DIM + d];
    }
    __syncthreads();
#pragma unroll
    for (int i = 0; i < 20; i++) {
        int idx = tid + i * 256;
        int d = idx / 64, tl = idx % 64;
        __half hh = __float2half_rn(vs[tl][d]);
        size_t base = ((size_t)(c * HEADS + h) * HEAD_DIM + d) * (2 * CHUNK_L)
                      + (t0 - c * CHUNK_L) + tl;
        g_Vt2[base]           = hh;
        g_Vt2[base + CHUNK_L] = hh;
    }
}

// ---------------------------------------------------------------------------
// Tensor-core flash attention (fp16x2). One CTA = 128 q-rows x (chunk, head).
// S k-dim = 160, PV k-dim = 128.
// ---------------------------------------------------------------------------
#define LDQ 168   /* 160 + 8 */
#define LDP 136   /* 128 + 8 */
#define SM_Q 0
#define SM_K (SM_Q + 128 * LDQ * 2)       /* 43008  */
#define SM_V (SM_K + 64 * LDQ * 2)        /* 64512  */
#define SM_P (SM_V + 80 * LDP * 2)        /* 86272  */
#define SM_TOT (SM_P + 128 * LDP * 2)     /* 121088 */

__global__ __launch_bounds__(256) void flash_mma()
{
    extern __shared__ char sm[];
    __half (*Q2s)[LDQ] = (__half(*)[LDQ])(sm + SM_Q);
    __half (*K2s)[LDQ] = (__half(*)[LDQ])(sm + SM_K);
    __half (*Vts)[LDP] = (__half(*)[LDP])(sm + SM_V);
    __half (*P2s)[LDP] = (__half(*)[LDP])(sm + SM_P);

    const int tid  = threadIdx.x;
    const int w    = tid >> 5;
    const int lane = tid & 31;
    const int h    = blockIdx.y;
    const int c    = blockIdx.z;
    const int q0   = c * CHUNK_L + blockIdx.x * 128;

    // load Q2 tile: 128 x 160 = 2560 uint4
#pragma unroll
    for (int i = 0; i < 10; i++) {
        int idx = tid + i * 256;
        int r = idx / 20, j = idx % 20;
        *(uint4*)&Q2s[r][j * 8] =
            *(const uint4*)&g_Q2[((size_t)(q0 + r) * HEADS + h) * 160 + j * 8];
    }

    const int lrow = lane & 15;
    const int lcol = (lane >> 4) << 3;
    const uint32_t qAddr = smem_u32(&Q2s[w * 16 + lrow][lcol]);
    const uint32_t pAddr = smem_u32(&P2s[w * 16 + lrow][lcol]);
    uint32_t kAddr[4], vAddr[5];
#pragma unroll
    for (int np = 0; np < 4; np++)
        kAddr[np] = smem_u32(&K2s[np * 16 + lrow][lcol]);
#pragma unroll
    for (int np = 0; np < 5; np++)
        vAddr[np] = smem_u32(&Vts[np * 16 + lrow][lcol]);

    const int cr = lane >> 2;
    const int cc = (lane & 3) * 2;
    uint32_t* Prow0 = (uint32_t*)&P2s[w * 16 + cr][0];
    uint32_t* Prow1 = (uint32_t*)&P2s[w * 16 + cr + 8][0];

    float O[10][4];
#pragma unroll
    for (int nt = 0; nt < 10; nt++)
#pragma unroll
        for (int v = 0; v < 4; v++) O[nt][v] = 0.0f;
    float m0 = -1e30f, m1 = -1e30f, l0 = 0.0f, l1 = 0.0f;

    const size_t vBase = (size_t)(c * HEADS + h) * HEAD_DIM * (2 * CHUNK_L);

    for (int kt = 0; kt < CHUNK_L / 64; kt++) {
        const int kv0 = kt * 64;
        __syncthreads();
        // load K2 tile (1280 uint4) + Vt tile (1280 uint4)
#pragma unroll
        for (int i = 0; i < 10; i++) {
            int idx = tid + i * 256;
            if (idx < 1280) {
                int r = idx / 20, j = idx % 20;
                *(uint4*)&K2s[r][j * 8] =
                    *(const uint4*)&g_K2[((size_t)(c * CHUNK_L + kv0 + r) * HEADS + h) * 160 + j * 8];
            } else {
                int vx = idx - 1280;
                int d = vx >> 4, rest = vx & 15;
                int b = rest >> 3, j = rest & 7;
                *(uint4*)&Vts[d][b * 64 + j * 8] =
                    *(const uint4*)&g_Vt2[vBase + (size_t)d * (2 * CHUNK_L) + b * CHUNK_L + kv0 + j * 8];
            }
        }
        __syncthreads();

        // ---- S = Q2 @ K2^T (k = 160) ----
        float s[8][4];
#pragma unroll
        for (int nt = 0; nt < 8; nt++)
#pragma unroll
            for (int v = 0; v < 4; v++) s[nt][v] = 0.0f;
#pragma unroll
        for (int ks = 0; ks < 10; ks++) {
            uint32_t af[4];
            ldsm_x4(af, qAddr + ks * 32);
            uint32_t bf[8][2];
#pragma unroll
            for (int np = 0; np < 4; np++) {
                uint32_t r[4];
                ldsm_x4(r, kAddr[np] + ks * 32);
                bf[2 * np][0]     = r[0]; bf[2 * np][1]     = r[2];
                bf[2 * np + 1][0] = r[1]; bf[2 * np + 1][1] = r[3];
            }
#pragma unroll
            for (int nt = 0; nt < 8; nt++)
                mma_16816(s[nt], af, bf[nt]);
        }

        // ---- online softmax ----
        float tm0 = -1e30f, tm1 = -1e30f;
#pragma unroll
        for (int nt = 0; nt < 8; nt++) {
            tm0 = fmaxf(tm0, fmaxf(s[nt][0], s[nt][1]));
            tm1 = fmaxf(tm1, fmaxf(s[nt][2], s[nt][3]));
        }
        tm0 = fmaxf(tm0, __shfl_xor_sync(0xffffffffu, tm0, 1));
        tm0 = fmaxf(tm0, __shfl_xor_sync(0xffffffffu, tm0, 2));
        tm1 = fmaxf(tm1, __shfl_xor_sync(0xffffffffu, tm1, 1));
        tm1 = fmaxf(tm1, __shfl_xor_sync(0xffffffffu, tm1, 2));
        const float nm0 = fmaxf(m0, tm0);
        const float nm1 = fmaxf(m1, tm1);
        const float a0 = __expf(m0 - nm0);
        const float a1 = __expf(m1 - nm1);
        m0 = nm0; m1 = nm1;

        float sum0 = 0.0f, sum1 = 0.0f;
#pragma unroll
        for (int nt = 0; nt < 8; nt++) {
            float p00 = __expf(s[nt][0] - nm0);
            float p01 = __expf(s[nt][1] - nm0);
            float p10 = __expf(s[nt][2] - nm1);
            float p11 = __expf(s[nt][3] - nm1);
            sum0 += p00 + p01;
            sum1 += p10 + p11;
            const int cw = (nt * 8 + cc) >> 1;
            __half h00, l00, h01, l01, h10, l10, h11, l11;
            sp16(p00, h00, l00); sp16(p01, h01, l01);
            sp16(p10, h10, l10); sp16(p11, h11, l11);
            Prow0[cw]      = pack2h(h00, h01);   // Ph block (cols 0..63)
            Prow1[cw]      = pack2h(h10, h11);
            Prow0[cw + 32] = pack2h(l00, l01);   // Pl block (cols 64..127)
            Prow1[cw + 32] = pack2h(l10, l11);
        }
        sum0 += __shfl_xor_sync(0xffffffffu, sum0, 1);
        sum0 += __shfl_xor_sync(0xffffffffu, sum0, 2);
        sum1 += __shfl_xor_sync(0xffffffffu, sum1, 1);
        sum1 += __shfl_xor_sync(0xffffffffu, sum1, 2);
        l0 = l0 * a0 + sum0;
        l1 = l1 * a1 + sum1;

#pragma unroll
        for (int nt = 0; nt < 10; nt++) {
            O[nt][0] *= a0; O[nt][1] *= a0;
            O[nt][2] *= a1; O[nt][3] *= a1;
        }
        __syncthreads();

        // ---- O += P2 @ Vt2^T (k = 128, n = 80) ----
#pragma unroll
        for (int ks = 0; ks < 8; ks++) {
            uint32_t af[4];
            ldsm_x4(af, pAddr + ks * 32);
            uint32_t bf[10][2];
#pragma unroll
            for (int np = 0; np < 5; np++) {
                uint32_t r[4];
                ldsm_x4(r, vAddr[np] + ks * 32);
                bf[2 * np][0]     = r[0]; bf[2 * np][1]     = r[2];
                bf[2 * np + 1][0] = r[1]; bf[2 * np + 1][1] = r[3];
            }
#pragma unroll
            for (int nt = 0; nt < 10; nt++)
                mma_16816(O[nt], af, bf[nt]);
        }
    }

    const float inv0 = 1.0f / l0;
    const float inv1 = 1.0f / l1;
    const int r0 = q0 + w * 16 + cr;
#pragma unroll
    for (int nt = 0; nt < 10; nt++) {
        const int col = h * HEAD_DIM + nt * 8 + cc;
        float2 v0, v1;
        v0.x = O[nt][0] * inv0; v0.y = O[nt][1] * inv0;
        v1.x = O[nt][2] * inv1; v1.y = O[nt][3] * inv1;
        *(float2*)&g_attn[(size_t)r0 * HIDDEN + col]       = v0;
        *(float2*)&g_attn[(size_t)(r0 + 8) * HIDDEN + col] = v1;
    }
}

// ---------------------------------------------------------------------------
extern "C" void kernel_launch(void* const* d_in, const int* in_sizes, int n_in,
                              void* d_out, int out_size)
{
    (void)in_sizes; (void)n_in; (void)out_size;
    const float* x      = (const float*)d_in[0];
    const float* cosp   = (const float*)d_in[1];
    const float* sinp   = (const float*)d_in[2];
    const float* w_qkv  = (const float*)d_in[3];
    const float* b_qkv  = (const float*)d_in[4];
    const float* w_proj = (const float*)d_in[5];
    const float* b_proj = (const float*)d_in[6];
    float* out = (float*)d_out;

    float *qkv = nullptr, *attn = nullptr;
    __half *Aq = nullptr, *Ap = nullptr, *Bq = nullptr, *Bp = nullptr;
    cudaGetSymbolAddress((void**)&qkv,  g_qkv);
    cudaGetSymbolAddress((void**)&attn, g_attn);
    cudaGetSymbolAddress((void**)&Aq,   g_Aq);
    cudaGetSymbolAddress((void**)&Ap,   g_Ap);
    cudaGetSymbolAddress((void**)&Bq,   g_Bq);
    cudaGetSymbolAddress((void**)&Bp,   g_Bp);

    cudaFuncSetAttribute(gemm_fp16_mma,
                         cudaFuncAttributeMaxDynamicSharedMemorySize, GSMEM);
    cudaFuncSetAttribute(flash_mma,
                         cudaFuncAttributeMaxDynamicSharedMemorySize, SM_TOT);

    convert_B<<<dim3(QKVN / 32, HIDDEN / 32), dim3(32, 8)>>>(w_qkv, Bq, HIDDEN, QKVN);
    convert_B<<<dim3(HIDDEN / 32, HIDDEN / 32), dim3(32, 8)>>>(w_proj, Bp, HIDDEN, HIDDEN);
    {
        int mk = TOTAL * HIDDEN;
        split_A<<<(mk + 255) / 256, 256>>>(x, Aq, mk, HIDDEN);
    }

    // 1) QKV projection
    gemm_fp16_mma<<<dim3(QKVN / 128, TOTAL / 128), 128, GSMEM>>>(
        Aq, Bq, b_qkv, qkv, QKVN);

    // 2) RoPE + splits
    {
        int total = TOTAL * HEADS * (HEAD_DIM / 2);
        rope_split<<<(total + 255) / 256, 256>>>(cosp, sinp);
    }
    vtrans<<<dim3(TOTAL / 64, HEADS), 256>>>();

    // 3) flash attention
    flash_mma<<<dim3(CHUNK_L / 128, HEADS, NCHUNK), 256, SM_TOT>>>();

    // 4) output projection
    {
        int mk = TOTAL * HIDDEN;
        split_A<<<(mk + 255) / 256, 256>>>(attn, Ap, mk, HIDDEN);
    }
    gemm_fp16_mma<<<dim3(HIDDEN / 128, TOTAL / 128), 128, GSMEM>>>(
        Ap, Bp, b_proj, out, HIDDEN);
}

// round 7
// speedup vs baseline: 3.2432x; 1.1562x over previous
#include <cuda_runtime.h>
#include <cuda_fp16.h>
#include <cstdint>

#define TOTAL    8192
#define HIDDEN   1280
#define HEADS    16
#define HEAD_DIM 80
#define NCHUNK   8
#define CHUNK_L  1024
#define QKVN     3840
#define K2       2560   /* 2 * 1280 : doubled K for the fp16x2 trick */
#define SCALE    0.11180339887498949f  /* 80^-0.5 */

// ---------------- device scratch (no allocs allowed) ----------------
__device__ float  g_qkv [(size_t)TOTAL * QKVN];
__device__ __half g_Aq  [(size_t)TOTAL * K2];      // [xh | xl]
__device__ __half g_Ap  [(size_t)TOTAL * K2];      // [attn_h | attn_l] (flash writes)
__device__ __half g_Bq  [(size_t)QKVN  * K2];      // [wh ; wh] transposed
__device__ __half g_Bp  [(size_t)HIDDEN* K2];
__device__ __half g_Q2 [(size_t)TOTAL * HEADS * 160];  // [Qh|Ql]
__device__ __half g_K2 [(size_t)TOTAL * HEADS * 160];  // [Kh|Kh]
__device__ __half g_Vt [(size_t)NCHUNK * HEADS * HEAD_DIM * CHUNK_L];
                                  // [c][h][d][t_local]  (single copy)

// ---------------- PTX helpers ----------------
__device__ __forceinline__ uint32_t smem_u32(const void* p) {
    uint32_t a;
    asm("{ .reg .u64 t; cvta.to.shared.u64 t, %1; cvt.u32.u64 %0, t; }"
        : "=r"(a) : "l"(p));
    return a;
}
__device__ __forceinline__ void ldsm_x4(uint32_t* r, uint32_t addr) {
    asm volatile("ldmatrix.sync.aligned.m8n8.x4.shared.b16 {%0,%1,%2,%3}, [%4];"
                 : "=r"(r[0]), "=r"(r[1]), "=r"(r[2]), "=r"(r[3]) : "r"(addr));
}
__device__ __forceinline__ void mma_16816(float* c, const uint32_t* a,
                                          const uint32_t* b) {
    asm volatile(
        "mma.sync.aligned.m16n8k16.row.col.f32.f16.f16.f32 "
        "{%0,%1,%2,%3}, {%4,%5,%6,%7}, {%8,%9}, {%0,%1,%2,%3};"
        : "+f"(c[0]), "+f"(c[1]), "+f"(c[2]), "+f"(c[3])
        : "r"(a[0]), "r"(a[1]), "r"(a[2]), "r"(a[3]), "r"(b[0]), "r"(b[1]));
}
__device__ __forceinline__ void cp16(uint32_t dst, const void* src) {
    asm volatile("cp.async.cg.shared.global [%0], [%1], 16;"
                 :: "r"(dst), "l"(src));
}
__device__ __forceinline__ void cp_commit() {
    asm volatile("cp.async.commit_group;" ::: "memory");
}
template <int W>
__device__ __forceinline__ void cp_wait() {
    asm volatile("cp.async.wait_group %0;" :: "n"(W) : "memory");
}
__device__ __forceinline__ void sp16(float x, __half& h, __half& l) {
    h = __float2half_rn(x);
    l = __float2half_rn(x - __half2float(h));
}
__device__ __forceinline__ uint32_t pack2h(__half lo, __half hi) {
    return (uint32_t)__half_as_ushort(lo) |
           ((uint32_t)__half_as_ushort(hi) << 16);
}

// ---------------------------------------------------------------------------
// Tensor-core GEMM (unchanged from R6): C[8192, N] = A * B^T + bias
// ---------------------------------------------------------------------------
#define BK     32
#define NST    3
#define LDAE   40
#define ROWB   (LDAE * 2)
#define STAGEB (128 * ROWB)
#define BOFF   (NST * STAGEB)
#define GSMEM  (2 * NST * STAGEB)

__global__ __launch_bounds__(128, 2) void gemm_fp16_mma(
    const __half* __restrict__ A, const __half* __restrict__ B,
    const float* __restrict__ bias, float* __restrict__ C, int N)
{
    extern __shared__ char sm[];
    const int tid  = threadIdx.x;
    const int wid  = tid >> 5;
    const int lane = tid & 31;
    const int m0   = blockIdx.y * 128;
    const int n0   = blockIdx.x * 128;
    const int wm   = wid & 1;
    const int wn   = wid >> 1;

    uint32_t aDst[4], bDst[4];
    const __half *aS[4], *bS[4];
#pragma unroll
    for (int p = 0; p < 4; p++) {
        int u  = tid + p * 128;
        int r  = u >> 2;
        int ch = (u & 3) * 8;
        aDst[p] = smem_u32(sm + r * ROWB + ch * 2);
        bDst[p] = aDst[p] + BOFF;
        aS[p]   = A + (size_t)(m0 + r) * K2 + ch;
        bS[p]   = B + (size_t)(n0 + r) * K2 + ch;
    }

    float acc[4][8][4];
#pragma unroll
    for (int mt = 0; mt < 4; mt++)
#pragma unroll
        for (int nt = 0; nt < 8; nt++)
#pragma unroll
            for (int v = 0; v < 4; v++) acc[mt][nt][v] = 0.0f;

    const int lrow  = lane & 15;
    const int lcolb = ((lane >> 4) << 3) * 2;
    uint32_t aAddr[4], bAddr[4];
#pragma unroll
    for (int mt = 0; mt < 4; mt++)
        aAddr[mt] = smem_u32(sm + (wm * 64 + mt * 16 + lrow) * ROWB + lcolb);
#pragma unroll
    for (int np = 0; np < 4; np++)
        bAddr[np] = smem_u32(sm + BOFF + (wn * 64 + np * 16 + lrow) * ROWB + lcolb);

#pragma unroll
    for (int s = 0; s < 2; s++) {
#pragma unroll
        for (int p = 0; p < 4; p++) {
            cp16(aDst[p] + s * STAGEB, aS[p] + s * BK);
            cp16(bDst[p] + s * STAGEB, bS[p] + s * BK);
        }
        cp_commit();
    }

    const int NKB = K2 / BK;   // 80
    for (int kb = 0; kb < NKB; kb++) {
        cp_wait<1>();
        __syncthreads();

        const int nxt = kb + 2;
        if (nxt < NKB) {
            const uint32_t so = (uint32_t)(nxt % NST) * STAGEB;
#pragma unroll
            for (int p = 0; p < 4; p++) {
                cp16(aDst[p] + so, aS[p] + nxt * BK);
                cp16(bDst[p] + so, bS[p] + nxt * BK);
            }
        }
        cp_commit();

        const uint32_t base = (uint32_t)(kb % NST) * STAGEB;
#pragma unroll
        for (int ks = 0; ks < 2; ks++) {
            const uint32_t ko = base + ks * 32;
            uint32_t af[4][4];
#pragma unroll
            for (int mt = 0; mt < 4; mt++)
                ldsm_x4(af[mt], aAddr[mt] + ko);
            uint32_t bf[8][2];
#pragma unroll
            for (int np = 0; np < 4; np++) {
                uint32_t r[4];
                ldsm_x4(r, bAddr[np] + ko);
                bf[2 * np][0]     = r[0]; bf[2 * np][1]     = r[2];
                bf[2 * np + 1][0] = r[1]; bf[2 * np + 1][1] = r[3];
            }
#pragma unroll
            for (int mt = 0; mt < 4; mt++)
#pragma unroll
                for (int nt = 0; nt < 8; nt++)
                    mma_16816(acc[mt][nt], af[mt], bf[nt]);
        }
    }

    const int cr = lane >> 2;
    const int cc = (lane & 3) * 2;
#pragma unroll
    for (int mt = 0; mt < 4; mt++) {
        const int r0 = m0 + wm * 64 + mt * 16 + cr;
#pragma unroll
        for (int nt = 0; nt < 8; nt++) {
            const int col = n0 + wn * 64 + nt * 8 + cc;
            const float b0 = __ldg(&bias[col]);
            const float b1 = __ldg(&bias[col + 1]);
            float2 v0, v1;
            v0.x = acc[mt][nt][0] + b0; v0.y = acc[mt][nt][1] + b1;
            v1.x = acc[mt][nt][2] + b0; v1.y = acc[mt][nt][3] + b1;
            *(float2*)&C[(size_t)r0 * N + col]       = v0;
            *(float2*)&C[(size_t)(r0 + 8) * N + col] = v1;
        }
    }
}

// ---------------------------------------------------------------------------
// fp16x2 split of activations: X[M,K] fp32 -> O[M,2K] = [hi | lo]
// ---------------------------------------------------------------------------
__global__ __launch_bounds__(256) void split_A(
    const float* __restrict__ X, __half* __restrict__ O, int MK, int K)
{
    int idx = blockIdx.x * 256 + threadIdx.x;
    if (idx >= MK) return;
    int m = idx / K, k = idx - m * K;
    float x = X[idx];
    __half h, l; sp16(x, h, l);
    size_t o = (size_t)m * (2 * K) + k;
    O[o]     = h;
    O[o + K] = l;
}

// ---------------------------------------------------------------------------
// fp16 weight transpose, duplicated: W[K,N] fp32 -> O[N,2K] = [hi ; hi]
// ---------------------------------------------------------------------------
__global__ __launch_bounds__(256) void convert_B(
    const float* __restrict__ W, __half* __restrict__ O, int K, int N)
{
    __shared__ float t[32][33];
    const int k0 = blockIdx.y * 32, n0 = blockIdx.x * 32;
    const int tx = threadIdx.x, ty = threadIdx.y;
#pragma unroll
    for (int i = 0; i < 32; i += 8)
        t[ty + i][tx] = W[(size_t)(k0 + ty + i) * N + n0 + tx];
    __syncthreads();
#pragma unroll
    for (int i = 0; i < 32; i += 8) {
        int n = n0 + ty + i, k = k0 + tx;
        __half h = __float2half_rn(t[tx][ty + i]);
        size_t o = (size_t)n * (2 * K) + k;
        O[o]     = h;
        O[o + K] = h;
    }
}

// ---------------------------------------------------------------------------
// RoPE + fp16x2 split of q,k (q pre-scaled by hd^-0.5).
// ---------------------------------------------------------------------------
__global__ __launch_bounds__(256) void rope_split(
    const float* __restrict__ cosp, const float* __restrict__ sinp)
{
    int idx = blockIdx.x * blockDim.x + threadIdx.x;
    const int total = TOTAL * HEADS * (HEAD_DIM / 2);
    if (idx >= total) return;
    int d = idx % 40;
    int h = (idx / 40) % HEADS;
    int t = idx / (40 * HEADS);

    float c1 = cosp[t * HEAD_DIM + d];
    float s1 = sinp[t * HEAD_DIM + d];
    float c2 = cosp[t * HEAD_DIM + d + 40];
    float s2 = sinp[t * HEAD_DIM + d + 40];

    const float* row = g_qkv + (size_t)t * QKVN;
    int qi = h * HEAD_DIM + d;

    float q1 = row[qi], q2 = row[qi + 40];
    float rq1 = (q1 * c1 - q2 * s1) * SCALE;
    float rq2 = (q2 * c2 + q1 * s2) * SCALE;

    float k1 = row[HIDDEN + qi], k2 = row[HIDDEN + qi + 40];
    float rk1 = k1 * c1 - k2 * s1;
    float rk2 = k2 * c2 + k1 * s2;

    __half hh, ll;
    __half* Q = g_Q2 + ((size_t)t * HEADS + h) * 160;
    __half* K = g_K2 + ((size_t)t * HEADS + h) * 160;

    sp16(rq1, hh, ll); Q[d]      = hh; Q[80 + d]      = ll;
    sp16(rq2, hh, ll); Q[d + 40] = hh; Q[80 + d + 40] = ll;
    hh = __float2half_rn(rk1); K[d]      = hh; K[80 + d]      = hh;
    hh = __float2half_rn(rk2); K[d + 40] = hh; K[80 + d + 40] = hh;
}

// ---------------------------------------------------------------------------
// V transpose (single fp16 copy): g_qkv v-part -> g_Vt [c][h][d][t_local]
// ---------------------------------------------------------------------------
__global__ __launch_bounds__(256) void vtrans()
{
    __shared__ float vs[64][81];
    const int tid = threadIdx.x;
    const int t0  = blockIdx.x * 64;
    const int h   = blockIdx.y;
    const int c   = t0 / CHUNK_L;
#pragma unroll
    for (int i = 0; i < 20; i++) {
        int idx = tid + i * 256;
        int r = idx / 80, d = idx % 80;
        vs[r][d] = g_qkv[(size_t)(t0 + r) * QKVN + 2 * HIDDEN + h * HEAD_DIM + d];
    }
    __syncthreads();
#pragma unroll
    for (int i = 0; i < 20; i++) {
        int idx = tid + i * 256;
        int d = idx / 64, tl = idx % 64;
        g_Vt[((size_t)(c * HEADS + h) * HEAD_DIM + d) * CHUNK_L
             + (t0 - c * CHUNK_L) + tl] = __float2half_rn(vs[tl][d]);
    }
}

// ---------------------------------------------------------------------------
// Tensor-core flash attention (fp16x2 scores, single-fp16 P).
// One CTA = 128 q-rows x (chunk, head). S k = 160, PV k = 64.
// Epilogue writes [Oh|Ol] fp16 directly into g_Ap (fused split for proj).
// ---------------------------------------------------------------------------
#define LDQ 168   /* 160 + 8 */
#define LDP 72    /* 64 + 8  */
#define SM_Q 0
#define SM_K (SM_Q + 128 * LDQ * 2)       /* 43008 */
#define SM_V (SM_K + 64 * LDQ * 2)        /* 64512 */
#define SM_P (SM_V + 80 * LDP * 2)        /* 76032 */
#define SM_TOT (SM_P + 128 * LDP * 2)     /* 94464 */

__global__ __launch_bounds__(256) void flash_mma()
{
    extern __shared__ char sm[];
    __half (*Q2s)[LDQ] = (__half(*)[LDQ])(sm + SM_Q);
    __half (*K2s)[LDQ] = (__half(*)[LDQ])(sm + SM_K);
    __half (*Vts)[LDP] = (__half(*)[LDP])(sm + SM_V);
    __half (*P1s)[LDP] = (__half(*)[LDP])(sm + SM_P);

    const int tid  = threadIdx.x;
    const int w    = tid >> 5;
    const int lane = tid & 31;
    const int h    = blockIdx.y;
    const int c    = blockIdx.z;
    const int q0   = c * CHUNK_L + blockIdx.x * 128;

    // load Q2 tile: 128 x 160 = 2560 uint4
#pragma unroll
    for (int i = 0; i < 10; i++) {
        int idx = tid + i * 256;
        int r = idx / 20, j = idx % 20;
        *(uint4*)&Q2s[r][j * 8] =
            *(const uint4*)&g_Q2[((size_t)(q0 + r) * HEADS + h) * 160 + j * 8];
    }

    const int lrow = lane & 15;
    const int lcol = (lane >> 4) << 3;
    const uint32_t qAddr = smem_u32(&Q2s[w * 16 + lrow][lcol]);
    const uint32_t pAddr = smem_u32(&P1s[w * 16 + lrow][lcol]);
    uint32_t kAddr[4], vAddr[5];
#pragma unroll
    for (int np = 0; np < 4; np++)
        kAddr[np] = smem_u32(&K2s[np * 16 + lrow][lcol]);
#pragma unroll
    for (int np = 0; np < 5; np++)
        vAddr[np] = smem_u32(&Vts[np * 16 + lrow][lcol]);

    const int cr = lane >> 2;
    const int cc = (lane & 3) * 2;
    uint32_t* Prow0 = (uint32_t*)&P1s[w * 16 + cr][0];
    uint32_t* Prow1 = (uint32_t*)&P1s[w * 16 + cr + 8][0];

    float O[10][4];
#pragma unroll
    for (int nt = 0; nt < 10; nt++)
#pragma unroll
        for (int v = 0; v < 4; v++) O[nt][v] = 0.0f;
    float m0 = -1e30f, m1 = -1e30f, l0 = 0.0f, l1 = 0.0f;

    const size_t vBase = (size_t)(c * HEADS + h) * HEAD_DIM * CHUNK_L;

    for (int kt = 0; kt < CHUNK_L / 64; kt++) {
        const int kv0 = kt * 64;
        __syncthreads();
        // load K2 tile (1280 uint4) + Vt tile (640 uint4)
#pragma unroll
        for (int i = 0; i < 8; i++) {
            int idx = tid + i * 256;
            if (idx < 1280) {
                int r = idx / 20, j = idx % 20;
                *(uint4*)&K2s[r][j * 8] =
                    *(const uint4*)&g_K2[((size_t)(c * CHUNK_L + kv0 + r) * HEADS + h) * 160 + j * 8];
            } else if (idx < 1920) {
                int vx = idx - 1280;
                int d = vx >> 3, j = vx & 7;
                *(uint4*)&Vts[d][j * 8] =
                    *(const uint4*)&g_Vt[vBase + (size_t)d * CHUNK_L + kv0 + j * 8];
            }
        }
        __syncthreads();

        // ---- S = Q2 @ K2^T (k = 160) ----
        float s[8][4];
#pragma unroll
        for (int nt = 0; nt < 8; nt++)
#pragma unroll
            for (int v = 0; v < 4; v++) s[nt][v] = 0.0f;
#pragma unroll
        for (int ks = 0; ks < 10; ks++) {
            uint32_t af[4];
            ldsm_x4(af, qAddr + ks * 32);
            uint32_t bf[8][2];
#pragma unroll
            for (int np = 0; np < 4; np++) {
                uint32_t r[4];
                ldsm_x4(r, kAddr[np] + ks * 32);
                bf[2 * np][0]     = r[0]; bf[2 * np][1]     = r[2];
                bf[2 * np + 1][0] = r[1]; bf[2 * np + 1][1] = r[3];
            }
#pragma unroll
            for (int nt = 0; nt < 8; nt++)
                mma_16816(s[nt], af, bf[nt]);
        }

        // ---- online softmax ----
        float tm0 = -1e30f, tm1 = -1e30f;
#pragma unroll
        for (int nt = 0; nt < 8; nt++) {
            tm0 = fmaxf(tm0, fmaxf(s[nt][0], s[nt][1]));
            tm1 = fmaxf(tm1, fmaxf(s[nt][2], s[nt][3]));
        }
        tm0 = fmaxf(tm0, __shfl_xor_sync(0xffffffffu, tm0, 1));
        tm0 = fmaxf(tm0, __shfl_xor_sync(0xffffffffu, tm0, 2));
        tm1 = fmaxf(tm1, __shfl_xor_sync(0xffffffffu, tm1, 1));
        tm1 = fmaxf(tm1, __shfl_xor_sync(0xffffffffu, tm1, 2));
        const float nm0 = fmaxf(m0, tm0);
        const float nm1 = fmaxf(m1, tm1);
        const float a0 = __expf(m0 - nm0);
        const float a1 = __expf(m1 - nm1);
        m0 = nm0; m1 = nm1;

        float sum0 = 0.0f, sum1 = 0.0f;
#pragma unroll
        for (int nt = 0; nt < 8; nt++) {
            float p00 = __expf(s[nt][0] - nm0);
            float p01 = __expf(s[nt][1] - nm0);
            float p10 = __expf(s[nt][2] - nm1);
            float p11 = __expf(s[nt][3] - nm1);
            sum0 += p00 + p01;
            sum1 += p10 + p11;
            const int cw = (nt * 8 + cc) >> 1;
            Prow0[cw] = pack2h(__float2half_rn(p00), __float2half_rn(p01));
            Prow1[cw] = pack2h(__float2half_rn(p10), __float2half_rn(p11));
        }
        sum0 += __shfl_xor_sync(0xffffffffu, sum0, 1);
        sum0 += __shfl_xor_sync(0xffffffffu, sum0, 2);
        sum1 += __shfl_xor_sync(0xffffffffu, sum1, 1);
        sum1 += __shfl_xor_sync(0xffffffffu, sum1, 2);
        l0 = l0 * a0 + sum0;
        l1 = l1 * a1 + sum1;

#pragma unroll
        for (int nt = 0; nt < 10; nt++) {
            O[nt][0] *= a0; O[nt][1] *= a0;
            O[nt][2] *= a1; O[nt][3] *= a1;
        }
        __syncthreads();

        // ---- O += P @ Vt^T (k = 64, n = 80) ----
#pragma unroll
        for (int ks = 0; ks < 4; ks++) {
            uint32_t af[4];
            ldsm_x4(af, pAddr + ks * 32);
            uint32_t bf[10][2];
#pragma unroll
            for (int np = 0; np < 5; np++) {
                uint32_t r[4];
                ldsm_x4(r, vAddr[np] + ks * 32);
                bf[2 * np][0]     = r[0]; bf[2 * np][1]     = r[2];
                bf[2 * np + 1][0] = r[1]; bf[2 * np + 1][1] = r[3];
            }
#pragma unroll
            for (int nt = 0; nt < 10; nt++)
                mma_16816(O[nt], af, bf[nt]);
        }
    }

    // ---- normalize + fused fp16x2 split into g_Ap ----
    const float inv0 = 1.0f / l0;
    const float inv1 = 1.0f / l1;
    const int r0 = q0 + w * 16 + cr;
#pragma unroll
    for (int nt = 0; nt < 10; nt++) {
        const int col = h * HEAD_DIM + nt * 8 + cc;
        float o00 = O[nt][0] * inv0, o01 = O[nt][1] * inv0;
        float o10 = O[nt][2] * inv1, o11 = O[nt][3] * inv1;
        __half h00, l00, h01, l01, h10, l10, h11, l11;
        sp16(o00, h00, l00); sp16(o01, h01, l01);
        sp16(o10, h10, l10); sp16(o11, h11, l11);
        *(uint32_t*)&g_Ap[(size_t)r0 * K2 + col] = pack2h(h00, h01);
        *(uint32_t*)&g_Ap[(size_t)r0 * K2 + HIDDEN + col] = pack2h(l00, l01);
        *(uint32_t*)&g_Ap[(size_t)(r0 + 8) * K2 + col] = pack2h(h10, h11);
        *(uint32_t*)&g_Ap[(size_t)(r0 + 8) * K2 + HIDDEN + col] = pack2h(l10, l11);
    }
}

// ---------------------------------------------------------------------------
extern "C" void kernel_launch(void* const* d_in, const int* in_sizes, int n_in,
                              void* d_out, int out_size)
{
    (void)in_sizes; (void)n_in; (void)out_size;
    const float* x      = (const float*)d_in[0];
    const float* cosp   = (const float*)d_in[1];
    const float* sinp   = (const float*)d_in[2];
    const float* w_qkv  = (const float*)d_in[3];
    const float* b_qkv  = (const float*)d_in[4];
    const float* w_proj = (const float*)d_in[5];
    const float* b_proj = (const float*)d_in[6];
    float* out = (float*)d_out;

    float* qkv = nullptr;
    __half *Aq = nullptr, *Ap = nullptr, *Bq = nullptr, *Bp = nullptr;
    cudaGetSymbolAddress((void**)&qkv,  g_qkv);
    cudaGetSymbolAddress((void**)&Aq,   g_Aq);
    cudaGetSymbolAddress((void**)&Ap,   g_Ap);
    cudaGetSymbolAddress((void**)&Bq,   g_Bq);
    cudaGetSymbolAddress((void**)&Bp,   g_Bp);

    cudaFuncSetAttribute(gemm_fp16_mma,
                         cudaFuncAttributeMaxDynamicSharedMemorySize, GSMEM);
    cudaFuncSetAttribute(flash_mma,
                         cudaFuncAttributeMaxDynamicSharedMemorySize, SM_TOT);

    convert_B<<<dim3(QKVN / 32, HIDDEN / 32), dim3(32, 8)>>>(w_qkv, Bq, HIDDEN, QKVN);
    convert_B<<<dim3(HIDDEN / 32, HIDDEN / 32), dim3(32, 8)>>>(w_proj, Bp, HIDDEN, HIDDEN);
    {
        int mk = TOTAL * HIDDEN;
        split_A<<<(mk + 255) / 256, 256>>>(x, Aq, mk, HIDDEN);
    }

    // 1) QKV projection
    gemm_fp16_mma<<<dim3(QKVN / 128, TOTAL / 128), 128, GSMEM>>>(
        Aq, Bq, b_qkv, qkv, QKVN);

    // 2) RoPE + splits
    {
        int total = TOTAL * HEADS * (HEAD_DIM / 2);
        rope_split<<<(total + 255) / 256, 256>>>(cosp, sinp);
    }
    vtrans<<<dim3(TOTAL / 64, HEADS), 256>>>();

    // 3) flash attention (writes g_Ap directly)
    flash_mma<<<dim3(CHUNK_L / 128, HEADS, NCHUNK), 256, SM_TOT>>>();

    // 4) output projection
    gemm_fp16_mma<<<dim3(HIDDEN / 128, TOTAL / 128), 128, GSMEM>>>(
        Ap, Bp, b_proj, out, HIDDEN);
}

// round 8
// speedup vs baseline: 4.3592x; 1.3441x over previous
#include <cuda_runtime.h>
#include <cuda_fp16.h>
#include <cstdint>

#define TOTAL    8192
#define HIDDEN   1280
#define HEADS    16
#define HEAD_DIM 80
#define NCHUNK   8
#define CHUNK_L  1024
#define QKVN     3840
#define K2       2560   /* 2 * 1280 : doubled K for the fp16x2 trick (proj) */
#define SCALE    0.11180339887498949f  /* 80^-0.5 */

// ---------------- device scratch (no allocs allowed) ----------------
__device__ float  g_qkv [(size_t)TOTAL * QKVN];
__device__ __half g_Aq  [(size_t)TOTAL * HIDDEN];  // fp16(x)  (single)
__device__ __half g_Ap  [(size_t)TOTAL * K2];      // [attn_h | attn_l] (flash writes)
__device__ __half g_Bq  [(size_t)QKVN  * HIDDEN];  // fp16(w_qkv)^T (single)
__device__ __half g_Bp  [(size_t)HIDDEN* K2];      // [wh ; wh] transposed (proj)
__device__ __half g_Q2 [(size_t)TOTAL * HEADS * 160];  // [Qh|Ql]
__device__ __half g_K2 [(size_t)TOTAL * HEADS * 160];  // [Kh|Kh]
__device__ __half g_Vt [(size_t)NCHUNK * HEADS * HEAD_DIM * CHUNK_L];

// ---------------- PTX helpers ----------------
__device__ __forceinline__ uint32_t smem_u32(const void* p) {
    uint32_t a;
    asm("{ .reg .u64 t; cvta.to.shared.u64 t, %1; cvt.u32.u64 %0, t; }"
        : "=r"(a) : "l"(p));
    return a;
}
__device__ __forceinline__ void ldsm_x4(uint32_t* r, uint32_t addr) {
    asm volatile("ldmatrix.sync.aligned.m8n8.x4.shared.b16 {%0,%1,%2,%3}, [%4];"
                 : "=r"(r[0]), "=r"(r[1]), "=r"(r[2]), "=r"(r[3]) : "r"(addr));
}
__device__ __forceinline__ void mma_16816(float* c, const uint32_t* a,
                                          const uint32_t* b) {
    asm volatile(
        "mma.sync.aligned.m16n8k16.row.col.f32.f16.f16.f32 "
        "{%0,%1,%2,%3}, {%4,%5,%6,%7}, {%8,%9}, {%0,%1,%2,%3};"
        : "+f"(c[0]), "+f"(c[1]), "+f"(c[2]), "+f"(c[3])
        : "r"(a[0]), "r"(a[1]), "r"(a[2]), "r"(a[3]), "r"(b[0]), "r"(b[1]));
}
__device__ __forceinline__ void cp16(uint32_t dst, const void* src) {
    asm volatile("cp.async.cg.shared.global [%0], [%1], 16;"
                 :: "r"(dst), "l"(src));
}
__device__ __forceinline__ void cp_commit() {
    asm volatile("cp.async.commit_group;" ::: "memory");
}
template <int W>
__device__ __forceinline__ void cp_wait() {
    asm volatile("cp.async.wait_group %0;" :: "n"(W) : "memory");
}
__device__ __forceinline__ void sp16(float x, __half& h, __half& l) {
    h = __float2half_rn(x);
    l = __float2half_rn(x - __half2float(h));
}
__device__ __forceinline__ uint32_t pack2h(__half lo, __half hi) {
    return (uint32_t)__half_as_ushort(lo) |
           ((uint32_t)__half_as_ushort(hi) << 16);
}

// ---------------------------------------------------------------------------
// Tensor-core GEMM: C[8192, N] = A[8192, K] * B[N, K]^T + bias  (runtime K)
// 128x128 CTA tile, 4 warps (2x2) each 64x64, BK=32, 3-stage cp.async pipe.
// ---------------------------------------------------------------------------
#define BK     32
#define NST    3
#define LDAE   40
#define ROWB   (LDAE * 2)
#define STAGEB (128 * ROWB)
#define BOFF   (NST * STAGEB)
#define GSMEM  (2 * NST * STAGEB)

__global__ __launch_bounds__(128, 2) void gemm_fp16_mma(
    const __half* __restrict__ A, const __half* __restrict__ B,
    const float* __restrict__ bias, float* __restrict__ C, int N, int K)
{
    extern __shared__ char sm[];
    const int tid  = threadIdx.x;
    const int wid  = tid >> 5;
    const int lane = tid & 31;
    const int m0   = blockIdx.y * 128;
    const int n0   = blockIdx.x * 128;
    const int wm   = wid & 1;
    const int wn   = wid >> 1;

    uint32_t aDst[4], bDst[4];
    const __half *aS[4], *bS[4];
#pragma unroll
    for (int p = 0; p < 4; p++) {
        int u  = tid + p * 128;
        int r  = u >> 2;
        int ch = (u & 3) * 8;
        aDst[p] = smem_u32(sm + r * ROWB + ch * 2);
        bDst[p] = aDst[p] + BOFF;
        aS[p]   = A + (size_t)(m0 + r) * K + ch;
        bS[p]   = B + (size_t)(n0 + r) * K + ch;
    }

    float acc[4][8][4];
#pragma unroll
    for (int mt = 0; mt < 4; mt++)
#pragma unroll
        for (int nt = 0; nt < 8; nt++)
#pragma unroll
            for (int v = 0; v < 4; v++) acc[mt][nt][v] = 0.0f;

    const int lrow  = lane & 15;
    const int lcolb = ((lane >> 4) << 3) * 2;
    uint32_t aAddr[4], bAddr[4];
#pragma unroll
    for (int mt = 0; mt < 4; mt++)
        aAddr[mt] = smem_u32(sm + (wm * 64 + mt * 16 + lrow) * ROWB + lcolb);
#pragma unroll
    for (int np = 0; np < 4; np++)
        bAddr[np] = smem_u32(sm + BOFF + (wn * 64 + np * 16 + lrow) * ROWB + lcolb);

#pragma unroll
    for (int s = 0; s < 2; s++) {
#pragma unroll
        for (int p = 0; p < 4; p++) {
            cp16(aDst[p] + s * STAGEB, aS[p] + s * BK);
            cp16(bDst[p] + s * STAGEB, bS[p] + s * BK);
        }
        cp_commit();
    }

    const int NKB = K / BK;
    for (int kb = 0; kb < NKB; kb++) {
        cp_wait<1>();
        __syncthreads();

        const int nxt = kb + 2;
        if (nxt < NKB) {
            const uint32_t so = (uint32_t)(nxt % NST) * STAGEB;
#pragma unroll
            for (int p = 0; p < 4; p++) {
                cp16(aDst[p] + so, aS[p] + nxt * BK);
                cp16(bDst[p] + so, bS[p] + nxt * BK);
            }
        }
        cp_commit();

        const uint32_t base = (uint32_t)(kb % NST) * STAGEB;
#pragma unroll
        for (int ks = 0; ks < 2; ks++) {
            const uint32_t ko = base + ks * 32;
            uint32_t af[4][4];
#pragma unroll
            for (int mt = 0; mt < 4; mt++)
                ldsm_x4(af[mt], aAddr[mt] + ko);
            uint32_t bf[8][2];
#pragma unroll
            for (int np = 0; np < 4; np++) {
                uint32_t r[4];
                ldsm_x4(r, bAddr[np] + ko);
                bf[2 * np][0]     = r[0]; bf[2 * np][1]     = r[2];
                bf[2 * np + 1][0] = r[1]; bf[2 * np + 1][1] = r[3];
            }
#pragma unroll
            for (int mt = 0; mt < 4; mt++)
#pragma unroll
                for (int nt = 0; nt < 8; nt++)
                    mma_16816(acc[mt][nt], af[mt], bf[nt]);
        }
    }

    const int cr = lane >> 2;
    const int cc = (lane & 3) * 2;
#pragma unroll
    for (int mt = 0; mt < 4; mt++) {
        const int r0 = m0 + wm * 64 + mt * 16 + cr;
#pragma unroll
        for (int nt = 0; nt < 8; nt++) {
            const int col = n0 + wn * 64 + nt * 8 + cc;
            const float b0 = __ldg(&bias[col]);
            const float b1 = __ldg(&bias[col + 1]);
            float2 v0, v1;
            v0.x = acc[mt][nt][0] + b0; v0.y = acc[mt][nt][1] + b1;
            v1.x = acc[mt][nt][2] + b0; v1.y = acc[mt][nt][3] + b1;
            *(float2*)&C[(size_t)r0 * N + col]       = v0;
            *(float2*)&C[(size_t)(r0 + 8) * N + col] = v1;
        }
    }
}

// ---------------------------------------------------------------------------
// Plain fp16 conversion of activations: X[MK] fp32 -> O[MK] fp16
// ---------------------------------------------------------------------------
__global__ __launch_bounds__(256) void convert_A(
    const float* __restrict__ X, __half* __restrict__ O, int MK)
{
    int idx = (blockIdx.x * 256 + threadIdx.x) * 4;
    if (idx >= MK) return;
    float4 v = *(const float4*)&X[idx];
    uint32_t p0 = pack2h(__float2half_rn(v.x), __float2half_rn(v.y));
    uint32_t p1 = pack2h(__float2half_rn(v.z), __float2half_rn(v.w));
    *(uint2*)&O[idx] = make_uint2(p0, p1);
}

// ---------------------------------------------------------------------------
// fp16 weight transpose, single copy: W[K,N] fp32 -> O[N,K]
// ---------------------------------------------------------------------------
__global__ __launch_bounds__(256) void convert_B1(
    const float* __restrict__ W, __half* __restrict__ O, int K, int N)
{
    __shared__ float t[32][33];
    const int k0 = blockIdx.y * 32, n0 = blockIdx.x * 32;
    const int tx = threadIdx.x, ty = threadIdx.y;
#pragma unroll
    for (int i = 0; i < 32; i += 8)
        t[ty + i][tx] = W[(size_t)(k0 + ty + i) * N + n0 + tx];
    __syncthreads();
#pragma unroll
    for (int i = 0; i < 32; i += 8) {
        int n = n0 + ty + i, k = k0 + tx;
        O[(size_t)n * K + k] = __float2half_rn(t[tx][ty + i]);
    }
}

// ---------------------------------------------------------------------------
// fp16 weight transpose, duplicated: W[K,N] fp32 -> O[N,2K] = [hi ; hi]
// ---------------------------------------------------------------------------
__global__ __launch_bounds__(256) void convert_B2(
    const float* __restrict__ W, __half* __restrict__ O, int K, int N)
{
    __shared__ float t[32][33];
    const int k0 = blockIdx.y * 32, n0 = blockIdx.x * 32;
    const int tx = threadIdx.x, ty = threadIdx.y;
#pragma unroll
    for (int i = 0; i < 32; i += 8)
        t[ty + i][tx] = W[(size_t)(k0 + ty + i) * N + n0 + tx];
    __syncthreads();
#pragma unroll
    for (int i = 0; i < 32; i += 8) {
        int n = n0 + ty + i, k = k0 + tx;
        __half h = __float2half_rn(t[tx][ty + i]);
        size_t o = (size_t)n * (2 * K) + k;
        O[o]     = h;
        O[o + K] = h;
    }
}

// ---------------------------------------------------------------------------
// RoPE + fp16x2 split of q,k (q pre-scaled by hd^-0.5).
// ---------------------------------------------------------------------------
__global__ __launch_bounds__(256) void rope_split(
    const float* __restrict__ cosp, const float* __restrict__ sinp)
{
    int idx = blockIdx.x * blockDim.x + threadIdx.x;
    const int total = TOTAL * HEADS * (HEAD_DIM / 2);
    if (idx >= total) return;
    int d = idx % 40;
    int h = (idx / 40) % HEADS;
    int t = idx / (40 * HEADS);

    float c1 = cosp[t * HEAD_DIM + d];
    float s1 = sinp[t * HEAD_DIM + d];
    float c2 = cosp[t * HEAD_DIM + d + 40];
    float s2 = sinp[t * HEAD_DIM + d + 40];

    const float* row = g_qkv + (size_t)t * QKVN;
    int qi = h * HEAD_DIM + d;

    float q1 = row[qi], q2 = row[qi + 40];
    float rq1 = (q1 * c1 - q2 * s1) * SCALE;
    float rq2 = (q2 * c2 + q1 * s2) * SCALE;

    float k1 = row[HIDDEN + qi], k2 = row[HIDDEN + qi + 40];
    float rk1 = k1 * c1 - k2 * s1;
    float rk2 = k2 * c2 + k1 * s2;

    __half hh, ll;
    __half* Q = g_Q2 + ((size_t)t * HEADS + h) * 160;
    __half* K = g_K2 + ((size_t)t * HEADS + h) * 160;

    sp16(rq1, hh, ll); Q[d]      = hh; Q[80 + d]      = ll;
    sp16(rq2, hh, ll); Q[d + 40] = hh; Q[80 + d + 40] = ll;
    hh = __float2half_rn(rk1); K[d]      = hh; K[80 + d]      = hh;
    hh = __float2half_rn(rk2); K[d + 40] = hh; K[80 + d + 40] = hh;
}

// ---------------------------------------------------------------------------
// V transpose (single fp16 copy): g_qkv v-part -> g_Vt [c][h][d][t_local]
// ---------------------------------------------------------------------------
__global__ __launch_bounds__(256) void vtrans()
{
    __shared__ float vs[64][81];
    const int tid = threadIdx.x;
    const int t0  = blockIdx.x * 64;
    const int h   = blockIdx.y;
    const int c   = t0 / CHUNK_L;
#pragma unroll
    for (int i = 0; i < 20; i++) {
        int idx = tid + i * 256;
        int r = idx / 80, d = idx % 80;
        vs[r][d] = g_qkv[(size_t)(t0 + r) * QKVN + 2 * HIDDEN + h * HEAD_DIM + d];
    }
    __syncthreads();
#pragma unroll
    for (int i = 0; i < 20; i++) {
        int idx = tid + i * 256;
        int d = idx / 64, tl = idx % 64;
        g_Vt[((size_t)(c * HEADS + h) * HEAD_DIM + d) * CHUNK_L
             + (t0 - c * CHUNK_L) + tl] = __float2half_rn(vs[tl][d]);
    }
}

// ---------------------------------------------------------------------------
// Tensor-core flash attention (unchanged from R7 — verified).
// ---------------------------------------------------------------------------
#define LDQ 168
#define LDP 72
#define SM_Q 0
#define SM_K (SM_Q + 128 * LDQ * 2)
#define SM_V (SM_K + 64 * LDQ * 2)
#define SM_P (SM_V + 80 * LDP * 2)
#define SM_TOT (SM_P + 128 * LDP * 2)

__global__ __launch_bounds__(256) void flash_mma()
{
    extern __shared__ char sm[];
    __half (*Q2s)[LDQ] = (__half(*)[LDQ])(sm + SM_Q);
    __half (*K2s)[LDQ] = (__half(*)[LDQ])(sm + SM_K);
    __half (*Vts)[LDP] = (__half(*)[LDP])(sm + SM_V);
    __half (*P1s)[LDP] = (__half(*)[LDP])(sm + SM_P);

    const int tid  = threadIdx.x;
    const int w    = tid >> 5;
    const int lane = tid & 31;
    const int h    = blockIdx.y;
    const int c    = blockIdx.z;
    const int q0   = c * CHUNK_L + blockIdx.x * 128;

#pragma unroll
    for (int i = 0; i < 10; i++) {
        int idx = tid + i * 256;
        int r = idx / 20, j = idx % 20;
        *(uint4*)&Q2s[r][j * 8] =
            *(const uint4*)&g_Q2[((size_t)(q0 + r) * HEADS + h) * 160 + j * 8];
    }

    const int lrow = lane & 15;
    const int lcol = (lane >> 4) << 3;
    const uint32_t qAddr = smem_u32(&Q2s[w * 16 + lrow][lcol]);
    const uint32_t pAddr = smem_u32(&P1s[w * 16 + lrow][lcol]);
    uint32_t kAddr[4], vAddr[5];
#pragma unroll
    for (int np = 0; np < 4; np++)
        kAddr[np] = smem_u32(&K2s[np * 16 + lrow][lcol]);
#pragma unroll
    for (int np = 0; np < 5; np++)
        vAddr[np] = smem_u32(&Vts[np * 16 + lrow][lcol]);

    const int cr = lane >> 2;
    const int cc = (lane & 3) * 2;
    uint32_t* Prow0 = (uint32_t*)&P1s[w * 16 + cr][0];
    uint32_t* Prow1 = (uint32_t*)&P1s[w * 16 + cr + 8][0];

    float O[10][4];
#pragma unroll
    for (int nt = 0; nt < 10; nt++)
#pragma unroll
        for (int v = 0; v < 4; v++) O[nt][v] = 0.0f;
    float m0 = -1e30f, m1 = -1e30f, l0 = 0.0f, l1 = 0.0f;

    const size_t vBase = (size_t)(c * HEADS + h) * HEAD_DIM * CHUNK_L;

    for (int kt = 0; kt < CHUNK_L / 64; kt++) {
        const int kv0 = kt * 64;
        __syncthreads();
#pragma unroll
        for (int i = 0; i < 8; i++) {
            int idx = tid + i * 256;
            if (idx < 1280) {
                int r = idx / 20, j = idx % 20;
                *(uint4*)&K2s[r][j * 8] =
                    *(const uint4*)&g_K2[((size_t)(c * CHUNK_L + kv0 + r) * HEADS + h) * 160 + j * 8];
            } else if (idx < 1920) {
                int vx = idx - 1280;
                int d = vx >> 3, j = vx & 7;
                *(uint4*)&Vts[d][j * 8] =
                    *(const uint4*)&g_Vt[vBase + (size_t)d * CHUNK_L + kv0 + j * 8];
            }
        }
        __syncthreads();

        float s[8][4];
#pragma unroll
        for (int nt = 0; nt < 8; nt++)
#pragma unroll
            for (int v = 0; v < 4; v++) s[nt][v] = 0.0f;
#pragma unroll
        for (int ks = 0; ks < 10; ks++) {
            uint32_t af[4];
            ldsm_x4(af, qAddr + ks * 32);
            uint32_t bf[8][2];
#pragma unroll
            for (int np = 0; np < 4; np++) {
                uint32_t r[4];
                ldsm_x4(r, kAddr[np] + ks * 32);
                bf[2 * np][0]     = r[0]; bf[2 * np][1]     = r[2];
                bf[2 * np + 1][0] = r[1]; bf[2 * np + 1][1] = r[3];
            }
#pragma unroll
            for (int nt = 0; nt < 8; nt++)
                mma_16816(s[nt], af, bf[nt]);
        }

        float tm0 = -1e30f, tm1 = -1e30f;
#pragma unroll
        for (int nt = 0; nt < 8; nt++) {
            tm0 = fmaxf(tm0, fmaxf(s[nt][0], s[nt][1]));
            tm1 = fmaxf(tm1, fmaxf(s[nt][2], s[nt][3]));
        }
        tm0 = fmaxf(tm0, __shfl_xor_sync(0xffffffffu, tm0, 1));
        tm0 = fmaxf(tm0, __shfl_xor_sync(0xffffffffu, tm0, 2));
        tm1 = fmaxf(tm1, __shfl_xor_sync(0xffffffffu, tm1, 1));
        tm1 = fmaxf(tm1, __shfl_xor_sync(0xffffffffu, tm1, 2));
        const float nm0 = fmaxf(m0, tm0);
        const float nm1 = fmaxf(m1, tm1);
        const float a0 = __expf(m0 - nm0);
        const float a1 = __expf(m1 - nm1);
        m0 = nm0; m1 = nm1;

        float sum0 = 0.0f, sum1 = 0.0f;
#pragma unroll
        for (int nt = 0; nt < 8; nt++) {
            float p00 = __expf(s[nt][0] - nm0);
            float p01 = __expf(s[nt][1] - nm0);
            float p10 = __expf(s[nt][2] - nm1);
            float p11 = __expf(s[nt][3] - nm1);
            sum0 += p00 + p01;
            sum1 += p10 + p11;
            const int cw = (nt * 8 + cc) >> 1;
            Prow0[cw] = pack2h(__float2half_rn(p00), __float2half_rn(p01));
            Prow1[cw] = pack2h(__float2half_rn(p10), __float2half_rn(p11));
        }
        sum0 += __shfl_xor_sync(0xffffffffu, sum0, 1);
        sum0 += __shfl_xor_sync(0xffffffffu, sum0, 2);
        sum1 += __shfl_xor_sync(0xffffffffu, sum1, 1);
        sum1 += __shfl_xor_sync(0xffffffffu, sum1, 2);
        l0 = l0 * a0 + sum0;
        l1 = l1 * a1 + sum1;

#pragma unroll
        for (int nt = 0; nt < 10; nt++) {
            O[nt][0] *= a0; O[nt][1] *= a0;
            O[nt][2] *= a1; O[nt][3] *= a1;
        }
        __syncthreads();

#pragma unroll
        for (int ks = 0; ks < 4; ks++) {
            uint32_t af[4];
            ldsm_x4(af, pAddr + ks * 32);
            uint32_t bf[10][2];
#pragma unroll
            for (int np = 0; np < 5; np++) {
                uint32_t r[4];
                ldsm_x4(r, vAddr[np] + ks * 32);
                bf[2 * np][0]     = r[0]; bf[2 * np][1]     = r[2];
                bf[2 * np + 1][0] = r[1]; bf[2 * np + 1][1] = r[3];
            }
#pragma unroll
            for (int nt = 0; nt < 10; nt++)
                mma_16816(O[nt], af, bf[nt]);
        }
    }

    const float inv0 = 1.0f / l0;
    const float inv1 = 1.0f / l1;
    const int r0 = q0 + w * 16 + cr;
#pragma unroll
    for (int nt = 0; nt < 10; nt++) {
        const int col = h * HEAD_DIM + nt * 8 + cc;
        float o00 = O[nt][0] * inv0, o01 = O[nt][1] * inv0;
        float o10 = O[nt][2] * inv1, o11 = O[nt][3] * inv1;
        __half h00, l00, h01, l01, h10, l10, h11, l11;
        sp16(o00, h00, l00); sp16(o01, h01, l01);
        sp16(o10, h10, l10); sp16(o11, h11, l11);
        *(uint32_t*)&g_Ap[(size_t)r0 * K2 + col] = pack2h(h00, h01);
        *(uint32_t*)&g_Ap[(size_t)r0 * K2 + HIDDEN + col] = pack2h(l00, l01);
        *(uint32_t*)&g_Ap[(size_t)(r0 + 8) * K2 + col] = pack2h(h10, h11);
        *(uint32_t*)&g_Ap[(size_t)(r0 + 8) * K2 + HIDDEN + col] = pack2h(l10, l11);
    }
}

// ---------------------------------------------------------------------------
extern "C" void kernel_launch(void* const* d_in, const int* in_sizes, int n_in,
                              void* d_out, int out_size)
{
    (void)in_sizes; (void)n_in; (void)out_size;
    const float* x      = (const float*)d_in[0];
    const float* cosp   = (const float*)d_in[1];
    const float* sinp   = (const float*)d_in[2];
    const float* w_qkv  = (const float*)d_in[3];
    const float* b_qkv  = (const float*)d_in[4];
    const float* w_proj = (const float*)d_in[5];
    const float* b_proj = (const float*)d_in[6];
    float* out = (float*)d_out;

    float* qkv = nullptr;
    __half *Aq = nullptr, *Ap = nullptr, *Bq = nullptr, *Bp = nullptr;
    cudaGetSymbolAddress((void**)&qkv,  g_qkv);
    cudaGetSymbolAddress((void**)&Aq,   g_Aq);
    cudaGetSymbolAddress((void**)&Ap,   g_Ap);
    cudaGetSymbolAddress((void**)&Bq,   g_Bq);
    cudaGetSymbolAddress((void**)&Bp,   g_Bp);

    cudaFuncSetAttribute(gemm_fp16_mma,
                         cudaFuncAttributeMaxDynamicSharedMemorySize, GSMEM);
    cudaFuncSetAttribute(flash_mma,
                         cudaFuncAttributeMaxDynamicSharedMemorySize, SM_TOT);

    // conversions
    convert_B1<<<dim3(QKVN / 32, HIDDEN / 32), dim3(32, 8)>>>(w_qkv, Bq, HIDDEN, QKVN);
    convert_B2<<<dim3(HIDDEN / 32, HIDDEN / 32), dim3(32, 8)>>>(w_proj, Bp, HIDDEN, HIDDEN);
    {
        int mk = TOTAL * HIDDEN;
        convert_A<<<(mk / 4 + 255) / 256, 256>>>(x, Aq, mk);
    }

    // 1) QKV projection (plain fp16 A, K = 1280)
    gemm_fp16_mma<<<dim3(QKVN / 128, TOTAL / 128), 128, GSMEM>>>(
        Aq, Bq, b_qkv, qkv, QKVN, HIDDEN);

    // 2) RoPE + splits
    {
        int total = TOTAL * HEADS * (HEAD_DIM / 2);
        rope_split<<<(total + 255) / 256, 256>>>(cosp, sinp);
    }
    vtrans<<<dim3(TOTAL / 64, HEADS), 256>>>();

    // 3) flash attention (writes g_Ap directly)
    flash_mma<<<dim3(CHUNK_L / 128, HEADS, NCHUNK), 256, SM_TOT>>>();

    // 4) output projection (fp16x2, K = 2560)
    gemm_fp16_mma<<<dim3(HIDDEN / 128, TOTAL / 128), 128, GSMEM>>>(
        Ap, Bp, b_proj, out, HIDDEN, K2);
}

// round 9
// speedup vs baseline: 5.0410x; 1.1564x over previous
#include <cuda_runtime.h>
#include <cuda_fp16.h>
#include <cstdint>

#define TOTAL    8192
#define HIDDEN   1280
#define HEADS    16
#define HEAD_DIM 80
#define NCHUNK   8
#define CHUNK_L  1024
#define QKVN     3840
#define SCALE    0.11180339887498949f  /* 80^-0.5 */

// ---------------- device scratch (no allocs allowed) ----------------
__device__ float  g_qkv [(size_t)TOTAL * QKVN];
__device__ __half g_Aq  [(size_t)TOTAL * HIDDEN];  // fp16(x)
__device__ __half g_Ap  [(size_t)TOTAL * HIDDEN];  // fp16(attn) (flash writes)
__device__ __half g_Bq  [(size_t)QKVN  * HIDDEN];  // fp16(w_qkv)^T
__device__ __half g_Bp  [(size_t)HIDDEN* HIDDEN];  // fp16(w_proj)^T
__device__ __half g_Q2 [(size_t)TOTAL * HEADS * 160];  // [Qh|Ql]
__device__ __half g_K2 [(size_t)TOTAL * HEADS * 160];  // [Kh|Kh]
__device__ __half g_Vt [(size_t)NCHUNK * HEADS * HEAD_DIM * CHUNK_L];

// ---------------- PTX helpers ----------------
__device__ __forceinline__ uint32_t smem_u32(const void* p) {
    uint32_t a;
    asm("{ .reg .u64 t; cvta.to.shared.u64 t, %1; cvt.u32.u64 %0, t; }"
        : "=r"(a) : "l"(p));
    return a;
}
__device__ __forceinline__ void ldsm_x4(uint32_t* r, uint32_t addr) {
    asm volatile("ldmatrix.sync.aligned.m8n8.x4.shared.b16 {%0,%1,%2,%3}, [%4];"
                 : "=r"(r[0]), "=r"(r[1]), "=r"(r[2]), "=r"(r[3]) : "r"(addr));
}
__device__ __forceinline__ void mma_16816(float* c, const uint32_t* a,
                                          const uint32_t* b) {
    asm volatile(
        "mma.sync.aligned.m16n8k16.row.col.f32.f16.f16.f32 "
        "{%0,%1,%2,%3}, {%4,%5,%6,%7}, {%8,%9}, {%0,%1,%2,%3};"
        : "+f"(c[0]), "+f"(c[1]), "+f"(c[2]), "+f"(c[3])
        : "r"(a[0]), "r"(a[1]), "r"(a[2]), "r"(a[3]), "r"(b[0]), "r"(b[1]));
}
__device__ __forceinline__ void cp16(uint32_t dst, const void* src) {
    asm volatile("cp.async.cg.shared.global [%0], [%1], 16;"
                 :: "r"(dst), "l"(src));
}
__device__ __forceinline__ void cp_commit() {
    asm volatile("cp.async.commit_group;" ::: "memory");
}
template <int W>
__device__ __forceinline__ void cp_wait() {
    asm volatile("cp.async.wait_group %0;" :: "n"(W) : "memory");
}
__device__ __forceinline__ void sp16(float x, __half& h, __half& l) {
    h = __float2half_rn(x);
    l = __float2half_rn(x - __half2float(h));
}
__device__ __forceinline__ uint32_t pack2h(__half lo, __half hi) {
    return (uint32_t)__half_as_ushort(lo) |
           ((uint32_t)__half_as_ushort(hi) << 16);
}

// ---------------------------------------------------------------------------
// Tensor-core GEMM: C[8192, N] = A[8192, K] * B[N, K]^T + bias  (runtime K)
// 128x128 CTA tile, 4 warps (2x2) each 64x64, BK=32, 3-stage cp.async pipe.
// ---------------------------------------------------------------------------
#define BK     32
#define NST    3
#define LDAE   40
#define ROWB   (LDAE * 2)
#define STAGEB (128 * ROWB)
#define BOFF   (NST * STAGEB)
#define GSMEM  (2 * NST * STAGEB)

__global__ __launch_bounds__(128, 2) void gemm_fp16_mma(
    const __half* __restrict__ A, const __half* __restrict__ B,
    const float* __restrict__ bias, float* __restrict__ C, int N, int K)
{
    extern __shared__ char sm[];
    const int tid  = threadIdx.x;
    const int wid  = tid >> 5;
    const int lane = tid & 31;
    const int m0   = blockIdx.y * 128;
    const int n0   = blockIdx.x * 128;
    const int wm   = wid & 1;
    const int wn   = wid >> 1;

    uint32_t aDst[4], bDst[4];
    const __half *aS[4], *bS[4];
#pragma unroll
    for (int p = 0; p < 4; p++) {
        int u  = tid + p * 128;
        int r  = u >> 2;
        int ch = (u & 3) * 8;
        aDst[p] = smem_u32(sm + r * ROWB + ch * 2);
        bDst[p] = aDst[p] + BOFF;
        aS[p]   = A + (size_t)(m0 + r) * K + ch;
        bS[p]   = B + (size_t)(n0 + r) * K + ch;
    }

    float acc[4][8][4];
#pragma unroll
    for (int mt = 0; mt < 4; mt++)
#pragma unroll
        for (int nt = 0; nt < 8; nt++)
#pragma unroll
            for (int v = 0; v < 4; v++) acc[mt][nt][v] = 0.0f;

    const int lrow  = lane & 15;
    const int lcolb = ((lane >> 4) << 3) * 2;
    uint32_t aAddr[4], bAddr[4];
#pragma unroll
    for (int mt = 0; mt < 4; mt++)
        aAddr[mt] = smem_u32(sm + (wm * 64 + mt * 16 + lrow) * ROWB + lcolb);
#pragma unroll
    for (int np = 0; np < 4; np++)
        bAddr[np] = smem_u32(sm + BOFF + (wn * 64 + np * 16 + lrow) * ROWB + lcolb);

#pragma unroll
    for (int s = 0; s < 2; s++) {
#pragma unroll
        for (int p = 0; p < 4; p++) {
            cp16(aDst[p] + s * STAGEB, aS[p] + s * BK);
            cp16(bDst[p] + s * STAGEB, bS[p] + s * BK);
        }
        cp_commit();
    }

    const int NKB = K / BK;
    for (int kb = 0; kb < NKB; kb++) {
        cp_wait<1>();
        __syncthreads();

        const int nxt = kb + 2;
        if (nxt < NKB) {
            const uint32_t so = (uint32_t)(nxt % NST) * STAGEB;
#pragma unroll
            for (int p = 0; p < 4; p++) {
                cp16(aDst[p] + so, aS[p] + nxt * BK);
                cp16(bDst[p] + so, bS[p] + nxt * BK);
            }
        }
        cp_commit();

        const uint32_t base = (uint32_t)(kb % NST) * STAGEB;
#pragma unroll
        for (int ks = 0; ks < 2; ks++) {
            const uint32_t ko = base + ks * 32;
            uint32_t af[4][4];
#pragma unroll
            for (int mt = 0; mt < 4; mt++)
                ldsm_x4(af[mt], aAddr[mt] + ko);
            uint32_t bf[8][2];
#pragma unroll
            for (int np = 0; np < 4; np++) {
                uint32_t r[4];
                ldsm_x4(r, bAddr[np] + ko);
                bf[2 * np][0]     = r[0]; bf[2 * np][1]     = r[2];
                bf[2 * np + 1][0] = r[1]; bf[2 * np + 1][1] = r[3];
            }
#pragma unroll
            for (int mt = 0; mt < 4; mt++)
#pragma unroll
                for (int nt = 0; nt < 8; nt++)
                    mma_16816(acc[mt][nt], af[mt], bf[nt]);
        }
    }

    const int cr = lane >> 2;
    const int cc = (lane & 3) * 2;
#pragma unroll
    for (int mt = 0; mt < 4; mt++) {
        const int r0 = m0 + wm * 64 + mt * 16 + cr;
#pragma unroll
        for (int nt = 0; nt < 8; nt++) {
            const int col = n0 + wn * 64 + nt * 8 + cc;
            const float b0 = __ldg(&bias[col]);
            const float b1 = __ldg(&bias[col + 1]);
            float2 v0, v1;
            v0.x = acc[mt][nt][0] + b0; v0.y = acc[mt][nt][1] + b1;
            v1.x = acc[mt][nt][2] + b0; v1.y = acc[mt][nt][3] + b1;
            *(float2*)&C[(size_t)r0 * N + col]       = v0;
            *(float2*)&C[(size_t)(r0 + 8) * N + col] = v1;
        }
    }
}

// ---------------------------------------------------------------------------
// Plain fp16 conversion of activations: X[MK] fp32 -> O[MK] fp16
// ---------------------------------------------------------------------------
__global__ __launch_bounds__(256) void convert_A(
    const float* __restrict__ X, __half* __restrict__ O, int MK)
{
    int idx = (blockIdx.x * 256 + threadIdx.x) * 4;
    if (idx >= MK) return;
    float4 v = *(const float4*)&X[idx];
    uint32_t p0 = pack2h(__float2half_rn(v.x), __float2half_rn(v.y));
    uint32_t p1 = pack2h(__float2half_rn(v.z), __float2half_rn(v.w));
    *(uint2*)&O[idx] = make_uint2(p0, p1);
}

// ---------------------------------------------------------------------------
// fp16 weight transpose, single copy: W[K,N] fp32 -> O[N,K]
// ---------------------------------------------------------------------------
__global__ __launch_bounds__(256) void convert_B1(
    const float* __restrict__ W, __half* __restrict__ O, int K, int N)
{
    __shared__ float t[32][33];
    const int k0 = blockIdx.y * 32, n0 = blockIdx.x * 32;
    const int tx = threadIdx.x, ty = threadIdx.y;
#pragma unroll
    for (int i = 0; i < 32; i += 8)
        t[ty + i][tx] = W[(size_t)(k0 + ty + i) * N + n0 + tx];
    __syncthreads();
#pragma unroll
    for (int i = 0; i < 32; i += 8) {
        int n = n0 + ty + i, k = k0 + tx;
        O[(size_t)n * K + k] = __float2half_rn(t[tx][ty + i]);
    }
}

// ---------------------------------------------------------------------------
// RoPE + fp16x2 split of q,k (q pre-scaled by hd^-0.5).
// ---------------------------------------------------------------------------
__global__ __launch_bounds__(256) void rope_split(
    const float* __restrict__ cosp, const float* __restrict__ sinp)
{
    int idx = blockIdx.x * blockDim.x + threadIdx.x;
    const int total = TOTAL * HEADS * (HEAD_DIM / 2);
    if (idx >= total) return;
    int d = idx % 40;
    int h = (idx / 40) % HEADS;
    int t = idx / (40 * HEADS);

    float c1 = cosp[t * HEAD_DIM + d];
    float s1 = sinp[t * HEAD_DIM + d];
    float c2 = cosp[t * HEAD_DIM + d + 40];
    float s2 = sinp[t * HEAD_DIM + d + 40];

    const float* row = g_qkv + (size_t)t * QKVN;
    int qi = h * HEAD_DIM + d;

    float q1 = row[qi], q2 = row[qi + 40];
    float rq1 = (q1 * c1 - q2 * s1) * SCALE;
    float rq2 = (q2 * c2 + q1 * s2) * SCALE;

    float k1 = row[HIDDEN + qi], k2 = row[HIDDEN + qi + 40];
    float rk1 = k1 * c1 - k2 * s1;
    float rk2 = k2 * c2 + k1 * s2;

    __half hh, ll;
    __half* Q = g_Q2 + ((size_t)t * HEADS + h) * 160;
    __half* K = g_K2 + ((size_t)t * HEADS + h) * 160;

    sp16(rq1, hh, ll); Q[d]      = hh; Q[80 + d]      = ll;
    sp16(rq2, hh, ll); Q[d + 40] = hh; Q[80 + d + 40] = ll;
    hh = __float2half_rn(rk1); K[d]      = hh; K[80 + d]      = hh;
    hh = __float2half_rn(rk2); K[d + 40] = hh; K[80 + d + 40] = hh;
}

// ---------------------------------------------------------------------------
// V transpose (single fp16 copy): g_qkv v-part -> g_Vt [c][h][d][t_local]
// ---------------------------------------------------------------------------
__global__ __launch_bounds__(256) void vtrans()
{
    __shared__ float vs[64][81];
    const int tid = threadIdx.x;
    const int t0  = blockIdx.x * 64;
    const int h   = blockIdx.y;
    const int c   = t0 / CHUNK_L;
#pragma unroll
    for (int i = 0; i < 20; i++) {
        int idx = tid + i * 256;
        int r = idx / 80, d = idx % 80;
        vs[r][d] = g_qkv[(size_t)(t0 + r) * QKVN + 2 * HIDDEN + h * HEAD_DIM + d];
    }
    __syncthreads();
#pragma unroll
    for (int i = 0; i < 20; i++) {
        int idx = tid + i * 256;
        int d = idx / 64, tl = idx % 64;
        g_Vt[((size_t)(c * HEADS + h) * HEAD_DIM + d) * CHUNK_L
             + (t0 - c * CHUNK_L) + tl] = __float2half_rn(vs[tl][d]);
    }
}

// ---------------------------------------------------------------------------
// Tensor-core flash attention (fp16x2 scores, single-fp16 P and output).
// ---------------------------------------------------------------------------
#define LDQ 168
#define LDP 72
#define SM_Q 0
#define SM_K (SM_Q + 128 * LDQ * 2)
#define SM_V (SM_K + 64 * LDQ * 2)
#define SM_P (SM_V + 80 * LDP * 2)
#define SM_TOT (SM_P + 128 * LDP * 2)

__global__ __launch_bounds__(256) void flash_mma()
{
    extern __shared__ char sm[];
    __half (*Q2s)[LDQ] = (__half(*)[LDQ])(sm + SM_Q);
    __half (*K2s)[LDQ] = (__half(*)[LDQ])(sm + SM_K);
    __half (*Vts)[LDP] = (__half(*)[LDP])(sm + SM_V);
    __half (*P1s)[LDP] = (__half(*)[LDP])(sm + SM_P);

    const int tid  = threadIdx.x;
    const int w    = tid >> 5;
    const int lane = tid & 31;
    const int h    = blockIdx.y;
    const int c    = blockIdx.z;
    const int q0   = c * CHUNK_L + blockIdx.x * 128;

#pragma unroll
    for (int i = 0; i < 10; i++) {
        int idx = tid + i * 256;
        int r = idx / 20, j = idx % 20;
        *(uint4*)&Q2s[r][j * 8] =
            *(const uint4*)&g_Q2[((size_t)(q0 + r) * HEADS + h) * 160 + j * 8];
    }

    const int lrow = lane & 15;
    const int lcol = (lane >> 4) << 3;
    const uint32_t qAddr = smem_u32(&Q2s[w * 16 + lrow][lcol]);
    const uint32_t pAddr = smem_u32(&P1s[w * 16 + lrow][lcol]);
    uint32_t kAddr[4], vAddr[5];
#pragma unroll
    for (int np = 0; np < 4; np++)
        kAddr[np] = smem_u32(&K2s[np * 16 + lrow][lcol]);
#pragma unroll
    for (int np = 0; np < 5; np++)
        vAddr[np] = smem_u32(&Vts[np * 16 + lrow][lcol]);

    const int cr = lane >> 2;
    const int cc = (lane & 3) * 2;
    uint32_t* Prow0 = (uint32_t*)&P1s[w * 16 + cr][0];
    uint32_t* Prow1 = (uint32_t*)&P1s[w * 16 + cr + 8][0];

    float O[10][4];
#pragma unroll
    for (int nt = 0; nt < 10; nt++)
#pragma unroll
        for (int v = 0; v < 4; v++) O[nt][v] = 0.0f;
    float m0 = -1e30f, m1 = -1e30f, l0 = 0.0f, l1 = 0.0f;

    const size_t vBase = (size_t)(c * HEADS + h) * HEAD_DIM * CHUNK_L;

    for (int kt = 0; kt < CHUNK_L / 64; kt++) {
        const int kv0 = kt * 64;
        __syncthreads();
#pragma unroll
        for (int i = 0; i < 8; i++) {
            int idx = tid + i * 256;
            if (idx < 1280) {
                int r = idx / 20, j = idx % 20;
                *(uint4*)&K2s[r][j * 8] =
                    *(const uint4*)&g_K2[((size_t)(c * CHUNK_L + kv0 + r) * HEADS + h) * 160 + j * 8];
            } else if (idx < 1920) {
                int vx = idx - 1280;
                int d = vx >> 3, j = vx & 7;
                *(uint4*)&Vts[d][j * 8] =
                    *(const uint4*)&g_Vt[vBase + (size_t)d * CHUNK_L + kv0 + j * 8];
            }
        }
        __syncthreads();

        float s[8][4];
#pragma unroll
        for (int nt = 0; nt < 8; nt++)
#pragma unroll
            for (int v = 0; v < 4; v++) s[nt][v] = 0.0f;
#pragma unroll
        for (int ks = 0; ks < 10; ks++) {
            uint32_t af[4];
            ldsm_x4(af, qAddr + ks * 32);
            uint32_t bf[8][2];
#pragma unroll
            for (int np = 0; np < 4; np++) {
                uint32_t r[4];
                ldsm_x4(r, kAddr[np] + ks * 32);
                bf[2 * np][0]     = r[0]; bf[2 * np][1]     = r[2];
                bf[2 * np + 1][0] = r[1]; bf[2 * np + 1][1] = r[3];
            }
#pragma unroll
            for (int nt = 0; nt < 8; nt++)
                mma_16816(s[nt], af, bf[nt]);
        }

        float tm0 = -1e30f, tm1 = -1e30f;
#pragma unroll
        for (int nt = 0; nt < 8; nt++) {
            tm0 = fmaxf(tm0, fmaxf(s[nt][0], s[nt][1]));
            tm1 = fmaxf(tm1, fmaxf(s[nt][2], s[nt][3]));
        }
        tm0 = fmaxf(tm0, __shfl_xor_sync(0xffffffffu, tm0, 1));
        tm0 = fmaxf(tm0, __shfl_xor_sync(0xffffffffu, tm0, 2));
        tm1 = fmaxf(tm1, __shfl_xor_sync(0xffffffffu, tm1, 1));
        tm1 = fmaxf(tm1, __shfl_xor_sync(0xffffffffu, tm1, 2));
        const float nm0 = fmaxf(m0, tm0);
        const float nm1 = fmaxf(m1, tm1);
        const float a0 = __expf(m0 - nm0);
        const float a1 = __expf(m1 - nm1);
        m0 = nm0; m1 = nm1;

        float sum0 = 0.0f, sum1 = 0.0f;
#pragma unroll
        for (int nt = 0; nt < 8; nt++) {
            float p00 = __expf(s[nt][0] - nm0);
            float p01 = __expf(s[nt][1] - nm0);
            float p10 = __expf(s[nt][2] - nm1);
            float p11 = __expf(s[nt][3] - nm1);
            sum0 += p00 + p01;
            sum1 += p10 + p11;
            const int cw = (nt * 8 + cc) >> 1;
            Prow0[cw] = pack2h(__float2half_rn(p00), __float2half_rn(p01));
            Prow1[cw] = pack2h(__float2half_rn(p10), __float2half_rn(p11));
        }
        sum0 += __shfl_xor_sync(0xffffffffu, sum0, 1);
        sum0 += __shfl_xor_sync(0xffffffffu, sum0, 2);
        sum1 += __shfl_xor_sync(0xffffffffu, sum1, 1);
        sum1 += __shfl_xor_sync(0xffffffffu, sum1, 2);
        l0 = l0 * a0 + sum0;
        l1 = l1 * a1 + sum1;

#pragma unroll
        for (int nt = 0; nt < 10; nt++) {
            O[nt][0] *= a0; O[nt][1] *= a0;
            O[nt][2] *= a1; O[nt][3] *= a1;
        }
        __syncthreads();

#pragma unroll
        for (int ks = 0; ks < 4; ks++) {
            uint32_t af[4];
            ldsm_x4(af, pAddr + ks * 32);
            uint32_t bf[10][2];
#pragma unroll
            for (int np = 0; np < 5; np++) {
                uint32_t r[4];
                ldsm_x4(r, vAddr[np] + ks * 32);
                bf[2 * np][0]     = r[0]; bf[2 * np][1]     = r[2];
                bf[2 * np + 1][0] = r[1]; bf[2 * np + 1][1] = r[3];
            }
#pragma unroll
            for (int nt = 0; nt < 10; nt++)
                mma_16816(O[nt], af, bf[nt]);
        }
    }

    // ---- normalize + single-fp16 output into g_Ap ----
    const float inv0 = 1.0f / l0;
    const float inv1 = 1.0f / l1;
    const int r0 = q0 + w * 16 + cr;
#pragma unroll
    for (int nt = 0; nt < 10; nt++) {
        const int col = h * HEAD_DIM + nt * 8 + cc;
        *(uint32_t*)&g_Ap[(size_t)r0 * HIDDEN + col] =
            pack2h(__float2half_rn(O[nt][0] * inv0),
                   __float2half_rn(O[nt][1] * inv0));
        *(uint32_t*)&g_Ap[(size_t)(r0 + 8) * HIDDEN + col] =
            pack2h(__float2half_rn(O[nt][2] * inv1),
                   __float2half_rn(O[nt][3] * inv1));
    }
}

// ---------------------------------------------------------------------------
extern "C" void kernel_launch(void* const* d_in, const int* in_sizes, int n_in,
                              void* d_out, int out_size)
{
    (void)in_sizes; (void)n_in; (void)out_size;
    const float* x      = (const float*)d_in[0];
    const float* cosp   = (const float*)d_in[1];
    const float* sinp   = (const float*)d_in[2];
    const float* w_qkv  = (const float*)d_in[3];
    const float* b_qkv  = (const float*)d_in[4];
    const float* w_proj = (const float*)d_in[5];
    const float* b_proj = (const float*)d_in[6];
    float* out = (float*)d_out;

    float* qkv = nullptr;
    __half *Aq = nullptr, *Ap = nullptr, *Bq = nullptr, *Bp = nullptr;
    cudaGetSymbolAddress((void**)&qkv,  g_qkv);
    cudaGetSymbolAddress((void**)&Aq,   g_Aq);
    cudaGetSymbolAddress((void**)&Ap,   g_Ap);
    cudaGetSymbolAddress((void**)&Bq,   g_Bq);
    cudaGetSymbolAddress((void**)&Bp,   g_Bp);

    cudaFuncSetAttribute(gemm_fp16_mma,
                         cudaFuncAttributeMaxDynamicSharedMemorySize, GSMEM);
    cudaFuncSetAttribute(flash_mma,
                         cudaFuncAttributeMaxDynamicSharedMemorySize, SM_TOT);

    // conversions (both weights: single fp16 transpose)
    convert_B1<<<dim3(QKVN / 32, HIDDEN / 32), dim3(32, 8)>>>(w_qkv, Bq, HIDDEN, QKVN);
    convert_B1<<<dim3(HIDDEN / 32, HIDDEN / 32), dim3(32, 8)>>>(w_proj, Bp, HIDDEN, HIDDEN);
    {
        int mk = TOTAL * HIDDEN;
        convert_A<<<(mk / 4 + 255) / 256, 256>>>(x, Aq, mk);
    }

    // 1) QKV projection (fp16, K = 1280)
    gemm_fp16_mma<<<dim3(QKVN / 128, TOTAL / 128), 128, GSMEM>>>(
        Aq, Bq, b_qkv, qkv, QKVN, HIDDEN);

    // 2) RoPE + splits
    {
        int total = TOTAL * HEADS * (HEAD_DIM / 2);
        rope_split<<<(total + 255) / 256, 256>>>(cosp, sinp);
    }
    vtrans<<<dim3(TOTAL / 64, HEADS), 256>>>();

    // 3) flash attention (writes fp16 attn into g_Ap)
    flash_mma<<<dim3(CHUNK_L / 128, HEADS, NCHUNK), 256, SM_TOT>>>();

    // 4) output projection (fp16, K = 1280)
    gemm_fp16_mma<<<dim3(HIDDEN / 128, TOTAL / 128), 128, GSMEM>>>(
        Ap, Bp, b_proj, out, HIDDEN, HIDDEN);
}

// round 10
// speedup vs baseline: 5.5367x; 1.0983x over previous
#include <cuda_runtime.h>
#include <cuda_fp16.h>
#include <cstdint>

#define TOTAL    8192
#define HIDDEN   1280
#define HEADS    16
#define HEAD_DIM 80
#define NCHUNK   8
#define CHUNK_L  1024
#define QKVN     3840
#define SCALE    0.11180339887498949f  /* 80^-0.5 */

// ---------------- device scratch (no allocs allowed) ----------------
__device__ float  g_qkv [(size_t)TOTAL * QKVN];
__device__ __half g_Aq  [(size_t)TOTAL * HIDDEN];  // fp16(x)
__device__ __half g_Ap  [(size_t)TOTAL * HIDDEN];  // fp16(attn) (flash writes)
__device__ __half g_Bq  [(size_t)QKVN  * HIDDEN];  // fp16(w_qkv)^T
__device__ __half g_Bp  [(size_t)HIDDEN* HIDDEN];  // fp16(w_proj)^T
__device__ __half g_Q1 [(size_t)TOTAL * HEADS * HEAD_DIM];  // fp16 roped q
__device__ __half g_K1 [(size_t)TOTAL * HEADS * HEAD_DIM];  // fp16 roped k
__device__ __half g_Vt [(size_t)NCHUNK * HEADS * HEAD_DIM * CHUNK_L];

// ---------------- PTX helpers ----------------
__device__ __forceinline__ uint32_t smem_u32(const void* p) {
    uint32_t a;
    asm("{ .reg .u64 t; cvta.to.shared.u64 t, %1; cvt.u32.u64 %0, t; }"
        : "=r"(a) : "l"(p));
    return a;
}
__device__ __forceinline__ void ldsm_x4(uint32_t* r, uint32_t addr) {
    asm volatile("ldmatrix.sync.aligned.m8n8.x4.shared.b16 {%0,%1,%2,%3}, [%4];"
                 : "=r"(r[0]), "=r"(r[1]), "=r"(r[2]), "=r"(r[3]) : "r"(addr));
}
__device__ __forceinline__ void mma_16816(float* c, const uint32_t* a,
                                          const uint32_t* b) {
    asm volatile(
        "mma.sync.aligned.m16n8k16.row.col.f32.f16.f16.f32 "
        "{%0,%1,%2,%3}, {%4,%5,%6,%7}, {%8,%9}, {%0,%1,%2,%3};"
        : "+f"(c[0]), "+f"(c[1]), "+f"(c[2]), "+f"(c[3])
        : "r"(a[0]), "r"(a[1]), "r"(a[2]), "r"(a[3]), "r"(b[0]), "r"(b[1]));
}
__device__ __forceinline__ void cp16(uint32_t dst, const void* src) {
    asm volatile("cp.async.cg.shared.global [%0], [%1], 16;"
                 :: "r"(dst), "l"(src));
}
__device__ __forceinline__ void cp_commit() {
    asm volatile("cp.async.commit_group;" ::: "memory");
}
template <int W>
__device__ __forceinline__ void cp_wait() {
    asm volatile("cp.async.wait_group %0;" :: "n"(W) : "memory");
}
__device__ __forceinline__ uint32_t pack2h(__half lo, __half hi) {
    return (uint32_t)__half_as_ushort(lo) |
           ((uint32_t)__half_as_ushort(hi) << 16);
}

// ---------------------------------------------------------------------------
// Tensor-core GEMM (unchanged, verified): C[8192, N] = A * B^T + bias
// ---------------------------------------------------------------------------
#define BK     32
#define NST    3
#define LDAE   40
#define ROWB   (LDAE * 2)
#define STAGEB (128 * ROWB)
#define BOFF   (NST * STAGEB)
#define GSMEM  (2 * NST * STAGEB)

__global__ __launch_bounds__(128, 2) void gemm_fp16_mma(
    const __half* __restrict__ A, const __half* __restrict__ B,
    const float* __restrict__ bias, float* __restrict__ C, int N, int K)
{
    extern __shared__ char sm[];
    const int tid  = threadIdx.x;
    const int wid  = tid >> 5;
    const int lane = tid & 31;
    const int m0   = blockIdx.y * 128;
    const int n0   = blockIdx.x * 128;
    const int wm   = wid & 1;
    const int wn   = wid >> 1;

    uint32_t aDst[4], bDst[4];
    const __half *aS[4], *bS[4];
#pragma unroll
    for (int p = 0; p < 4; p++) {
        int u  = tid + p * 128;
        int r  = u >> 2;
        int ch = (u & 3) * 8;
        aDst[p] = smem_u32(sm + r * ROWB + ch * 2);
        bDst[p] = aDst[p] + BOFF;
        aS[p]   = A + (size_t)(m0 + r) * K + ch;
        bS[p]   = B + (size_t)(n0 + r) * K + ch;
    }

    float acc[4][8][4];
#pragma unroll
    for (int mt = 0; mt < 4; mt++)
#pragma unroll
        for (int nt = 0; nt < 8; nt++)
#pragma unroll
            for (int v = 0; v < 4; v++) acc[mt][nt][v] = 0.0f;

    const int lrow  = lane & 15;
    const int lcolb = ((lane >> 4) << 3) * 2;
    uint32_t aAddr[4], bAddr[4];
#pragma unroll
    for (int mt = 0; mt < 4; mt++)
        aAddr[mt] = smem_u32(sm + (wm * 64 + mt * 16 + lrow) * ROWB + lcolb);
#pragma unroll
    for (int np = 0; np < 4; np++)
        bAddr[np] = smem_u32(sm + BOFF + (wn * 64 + np * 16 + lrow) * ROWB + lcolb);

#pragma unroll
    for (int s = 0; s < 2; s++) {
#pragma unroll
        for (int p = 0; p < 4; p++) {
            cp16(aDst[p] + s * STAGEB, aS[p] + s * BK);
            cp16(bDst[p] + s * STAGEB, bS[p] + s * BK);
        }
        cp_commit();
    }

    const int NKB = K / BK;
    for (int kb = 0; kb < NKB; kb++) {
        cp_wait<1>();
        __syncthreads();

        const int nxt = kb + 2;
        if (nxt < NKB) {
            const uint32_t so = (uint32_t)(nxt % NST) * STAGEB;
#pragma unroll
            for (int p = 0; p < 4; p++) {
                cp16(aDst[p] + so, aS[p] + nxt * BK);
                cp16(bDst[p] + so, bS[p] + nxt * BK);
            }
        }
        cp_commit();

        const uint32_t base = (uint32_t)(kb % NST) * STAGEB;
#pragma unroll
        for (int ks = 0; ks < 2; ks++) {
            const uint32_t ko = base + ks * 32;
            uint32_t af[4][4];
#pragma unroll
            for (int mt = 0; mt < 4; mt++)
                ldsm_x4(af[mt], aAddr[mt] + ko);
            uint32_t bf[8][2];
#pragma unroll
            for (int np = 0; np < 4; np++) {
                uint32_t r[4];
                ldsm_x4(r, bAddr[np] + ko);
                bf[2 * np][0]     = r[0]; bf[2 * np][1]     = r[2];
                bf[2 * np + 1][0] = r[1]; bf[2 * np + 1][1] = r[3];
            }
#pragma unroll
            for (int mt = 0; mt < 4; mt++)
#pragma unroll
                for (int nt = 0; nt < 8; nt++)
                    mma_16816(acc[mt][nt], af[mt], bf[nt]);
        }
    }

    const int cr = lane >> 2;
    const int cc = (lane & 3) * 2;
#pragma unroll
    for (int mt = 0; mt < 4; mt++) {
        const int r0 = m0 + wm * 64 + mt * 16 + cr;
#pragma unroll
        for (int nt = 0; nt < 8; nt++) {
            const int col = n0 + wn * 64 + nt * 8 + cc;
            const float b0 = __ldg(&bias[col]);
            const float b1 = __ldg(&bias[col + 1]);
            float2 v0, v1;
            v0.x = acc[mt][nt][0] + b0; v0.y = acc[mt][nt][1] + b1;
            v1.x = acc[mt][nt][2] + b0; v1.y = acc[mt][nt][3] + b1;
            *(float2*)&C[(size_t)r0 * N + col]       = v0;
            *(float2*)&C[(size_t)(r0 + 8) * N + col] = v1;
        }
    }
}

// ---------------------------------------------------------------------------
// Plain fp16 conversion of activations: X[MK] fp32 -> O[MK] fp16
// ---------------------------------------------------------------------------
__global__ __launch_bounds__(256) void convert_A(
    const float* __restrict__ X, __half* __restrict__ O, int MK)
{
    int idx = (blockIdx.x * 256 + threadIdx.x) * 4;
    if (idx >= MK) return;
    float4 v = *(const float4*)&X[idx];
    uint32_t p0 = pack2h(__float2half_rn(v.x), __float2half_rn(v.y));
    uint32_t p1 = pack2h(__float2half_rn(v.z), __float2half_rn(v.w));
    *(uint2*)&O[idx] = make_uint2(p0, p1);
}

// ---------------------------------------------------------------------------
// fp16 weight transpose: W[K,N] fp32 -> O[N,K]
// ---------------------------------------------------------------------------
__global__ __launch_bounds__(256) void convert_B1(
    const float* __restrict__ W, __half* __restrict__ O, int K, int N)
{
    __shared__ float t[32][33];
    const int k0 = blockIdx.y * 32, n0 = blockIdx.x * 32;
    const int tx = threadIdx.x, ty = threadIdx.y;
#pragma unroll
    for (int i = 0; i < 32; i += 8)
        t[ty + i][tx] = W[(size_t)(k0 + ty + i) * N + n0 + tx];
    __syncthreads();
#pragma unroll
    for (int i = 0; i < 32; i += 8) {
        int n = n0 + ty + i, k = k0 + tx;
        O[(size_t)n * K + k] = __float2half_rn(t[tx][ty + i]);
    }
}

// ---------------------------------------------------------------------------
// RoPE + fp16 conversion of q,k (q pre-scaled by hd^-0.5). Single copies.
// ---------------------------------------------------------------------------
__global__ __launch_bounds__(256) void rope_split(
    const float* __restrict__ cosp, const float* __restrict__ sinp)
{
    int idx = blockIdx.x * blockDim.x + threadIdx.x;
    const int total = TOTAL * HEADS * (HEAD_DIM / 2);
    if (idx >= total) return;
    int d = idx % 40;
    int h = (idx / 40) % HEADS;
    int t = idx / (40 * HEADS);

    float c1 = cosp[t * HEAD_DIM + d];
    float s1 = sinp[t * HEAD_DIM + d];
    float c2 = cosp[t * HEAD_DIM + d + 40];
    float s2 = sinp[t * HEAD_DIM + d + 40];

    const float* row = g_qkv + (size_t)t * QKVN;
    int qi = h * HEAD_DIM + d;

    float q1 = row[qi], q2 = row[qi + 40];
    float rq1 = (q1 * c1 - q2 * s1) * SCALE;
    float rq2 = (q2 * c2 + q1 * s2) * SCALE;

    float k1 = row[HIDDEN + qi], k2 = row[HIDDEN + qi + 40];
    float rk1 = k1 * c1 - k2 * s1;
    float rk2 = k2 * c2 + k1 * s2;

    __half* Q = g_Q1 + ((size_t)t * HEADS + h) * HEAD_DIM;
    __half* K = g_K1 + ((size_t)t * HEADS + h) * HEAD_DIM;
    Q[d]      = __float2half_rn(rq1);
    Q[d + 40] = __float2half_rn(rq2);
    K[d]      = __float2half_rn(rk1);
    K[d + 40] = __float2half_rn(rk2);
}

// ---------------------------------------------------------------------------
// V transpose (single fp16 copy): g_qkv v-part -> g_Vt [c][h][d][t_local]
// ---------------------------------------------------------------------------
__global__ __launch_bounds__(256) void vtrans()
{
    __shared__ float vs[64][81];
    const int tid = threadIdx.x;
    const int t0  = blockIdx.x * 64;
    const int h   = blockIdx.y;
    const int c   = t0 / CHUNK_L;
#pragma unroll
    for (int i = 0; i < 20; i++) {
        int idx = tid + i * 256;
        int r = idx / 80, d = idx % 80;
        vs[r][d] = g_qkv[(size_t)(t0 + r) * QKVN + 2 * HIDDEN + h * HEAD_DIM + d];
    }
    __syncthreads();
#pragma unroll
    for (int i = 0; i < 20; i++) {
        int idx = tid + i * 256;
        int d = idx / 64, tl = idx % 64;
        g_Vt[((size_t)(c * HEADS + h) * HEAD_DIM + d) * CHUNK_L
             + (t0 - c * CHUNK_L) + tl] = __float2half_rn(vs[tl][d]);
    }
}

// ---------------------------------------------------------------------------
// Tensor-core flash attention (single fp16 Q, K, P, V). S k = 80, PV k = 64.
// One CTA = 128 q-rows x (chunk, head). Epilogue writes fp16 attn to g_Ap.
// ---------------------------------------------------------------------------
#define LDQ 88    /* 80 + 8 */
#define LDP 72    /* 64 + 8 */
#define SM_Q 0
#define SM_K (SM_Q + 128 * LDQ * 2)       /* 22528 */
#define SM_V (SM_K + 64 * LDQ * 2)        /* 33792 */
#define SM_P (SM_V + 80 * LDP * 2)        /* 45312 */
#define SM_TOT (SM_P + 128 * LDP * 2)     /* 63744 */

__global__ __launch_bounds__(256) void flash_mma()
{
    extern __shared__ char sm[];
    __half (*Q1s)[LDQ] = (__half(*)[LDQ])(sm + SM_Q);
    __half (*K1s)[LDQ] = (__half(*)[LDQ])(sm + SM_K);
    __half (*Vts)[LDP] = (__half(*)[LDP])(sm + SM_V);
    __half (*P1s)[LDP] = (__half(*)[LDP])(sm + SM_P);

    const int tid  = threadIdx.x;
    const int w    = tid >> 5;
    const int lane = tid & 31;
    const int h    = blockIdx.y;
    const int c    = blockIdx.z;
    const int q0   = c * CHUNK_L + blockIdx.x * 128;

    // load Q tile: 128 x 80 = 1280 uint4
#pragma unroll
    for (int i = 0; i < 5; i++) {
        int idx = tid + i * 256;
        int r = idx / 10, j = idx % 10;
        *(uint4*)&Q1s[r][j * 8] =
            *(const uint4*)&g_Q1[((size_t)(q0 + r) * HEADS + h) * HEAD_DIM + j * 8];
    }

    const int lrow = lane & 15;
    const int lcol = (lane >> 4) << 3;
    const uint32_t qAddr = smem_u32(&Q1s[w * 16 + lrow][lcol]);
    const uint32_t pAddr = smem_u32(&P1s[w * 16 + lrow][lcol]);
    uint32_t kAddr[4], vAddr[5];
#pragma unroll
    for (int np = 0; np < 4; np++)
        kAddr[np] = smem_u32(&K1s[np * 16 + lrow][lcol]);
#pragma unroll
    for (int np = 0; np < 5; np++)
        vAddr[np] = smem_u32(&Vts[np * 16 + lrow][lcol]);

    const int cr = lane >> 2;
    const int cc = (lane & 3) * 2;
    uint32_t* Prow0 = (uint32_t*)&P1s[w * 16 + cr][0];
    uint32_t* Prow1 = (uint32_t*)&P1s[w * 16 + cr + 8][0];

    float O[10][4];
#pragma unroll
    for (int nt = 0; nt < 10; nt++)
#pragma unroll
        for (int v = 0; v < 4; v++) O[nt][v] = 0.0f;
    float m0 = -1e30f, m1 = -1e30f, l0 = 0.0f, l1 = 0.0f;

    const size_t vBase = (size_t)(c * HEADS + h) * HEAD_DIM * CHUNK_L;

    for (int kt = 0; kt < CHUNK_L / 64; kt++) {
        const int kv0 = kt * 64;
        __syncthreads();
        // load K tile (640 uint4) + Vt tile (640 uint4)
#pragma unroll
        for (int i = 0; i < 5; i++) {
            int idx = tid + i * 256;
            if (idx < 640) {
                int r = idx / 10, j = idx % 10;
                *(uint4*)&K1s[r][j * 8] =
                    *(const uint4*)&g_K1[((size_t)(c * CHUNK_L + kv0 + r) * HEADS + h) * HEAD_DIM + j * 8];
            } else {
                int vx = idx - 640;
                int d = vx >> 3, j = vx & 7;
                *(uint4*)&Vts[d][j * 8] =
                    *(const uint4*)&g_Vt[vBase + (size_t)d * CHUNK_L + kv0 + j * 8];
            }
        }
        __syncthreads();

        // ---- S = Q @ K^T (k = 80) ----
        float s[8][4];
#pragma unroll
        for (int nt = 0; nt < 8; nt++)
#pragma unroll
            for (int v = 0; v < 4; v++) s[nt][v] = 0.0f;
#pragma unroll
        for (int ks = 0; ks < 5; ks++) {
            uint32_t af[4];
            ldsm_x4(af, qAddr + ks * 32);
            uint32_t bf[8][2];
#pragma unroll
            for (int np = 0; np < 4; np++) {
                uint32_t r[4];
                ldsm_x4(r, kAddr[np] + ks * 32);
                bf[2 * np][0]     = r[0]; bf[2 * np][1]     = r[2];
                bf[2 * np + 1][0] = r[1]; bf[2 * np + 1][1] = r[3];
            }
#pragma unroll
            for (int nt = 0; nt < 8; nt++)
                mma_16816(s[nt], af, bf[nt]);
        }

        // ---- online softmax ----
        float tm0 = -1e30f, tm1 = -1e30f;
#pragma unroll
        for (int nt = 0; nt < 8; nt++) {
            tm0 = fmaxf(tm0, fmaxf(s[nt][0], s[nt][1]));
            tm1 = fmaxf(tm1, fmaxf(s[nt][2], s[nt][3]));
        }
        tm0 = fmaxf(tm0, __shfl_xor_sync(0xffffffffu, tm0, 1));
        tm0 = fmaxf(tm0, __shfl_xor_sync(0xffffffffu, tm0, 2));
        tm1 = fmaxf(tm1, __shfl_xor_sync(0xffffffffu, tm1, 1));
        tm1 = fmaxf(tm1, __shfl_xor_sync(0xffffffffu, tm1, 2));
        const float nm0 = fmaxf(m0, tm0);
        const float nm1 = fmaxf(m1, tm1);
        const float a0 = __expf(m0 - nm0);
        const float a1 = __expf(m1 - nm1);
        m0 = nm0; m1 = nm1;

        float sum0 = 0.0f, sum1 = 0.0f;
#pragma unroll
        for (int nt = 0; nt < 8; nt++) {
            float p00 = __expf(s[nt][0] - nm0);
            float p01 = __expf(s[nt][1] - nm0);
            float p10 = __expf(s[nt][2] - nm1);
            float p11 = __expf(s[nt][3] - nm1);
            sum0 += p00 + p01;
            sum1 += p10 + p11;
            const int cw = (nt * 8 + cc) >> 1;
            Prow0[cw] = pack2h(__float2half_rn(p00), __float2half_rn(p01));
            Prow1[cw] = pack2h(__float2half_rn(p10), __float2half_rn(p11));
        }
        sum0 += __shfl_xor_sync(0xffffffffu, sum0, 1);
        sum0 += __shfl_xor_sync(0xffffffffu, sum0, 2);
        sum1 += __shfl_xor_sync(0xffffffffu, sum1, 1);
        sum1 += __shfl_xor_sync(0xffffffffu, sum1, 2);
        l0 = l0 * a0 + sum0;
        l1 = l1 * a1 + sum1;

#pragma unroll
        for (int nt = 0; nt < 10; nt++) {
            O[nt][0] *= a0; O[nt][1] *= a0;
            O[nt][2] *= a1; O[nt][3] *= a1;
        }
        __syncthreads();

        // ---- O += P @ Vt^T (k = 64, n = 80) ----
#pragma unroll
        for (int ks = 0; ks < 4; ks++) {
            uint32_t af[4];
            ldsm_x4(af, pAddr + ks * 32);
            uint32_t bf[10][2];
#pragma unroll
            for (int np = 0; np < 5; np++) {
                uint32_t r[4];
                ldsm_x4(r, vAddr[np] + ks * 32);
                bf[2 * np][0]     = r[0]; bf[2 * np][1]     = r[2];
                bf[2 * np + 1][0] = r[1]; bf[2 * np + 1][1] = r[3];
            }
#pragma unroll
            for (int nt = 0; nt < 10; nt++)
                mma_16816(O[nt], af, bf[nt]);
        }
    }

    // ---- normalize + single-fp16 output into g_Ap ----
    const float inv0 = 1.0f / l0;
    const float inv1 = 1.0f / l1;
    const int r0 = q0 + w * 16 + cr;
#pragma unroll
    for (int nt = 0; nt < 10; nt++) {
        const int col = h * HEAD_DIM + nt * 8 + cc;
        *(uint32_t*)&g_Ap[(size_t)r0 * HIDDEN + col] =
            pack2h(__float2half_rn(O[nt][0] * inv0),
                   __float2half_rn(O[nt][1] * inv0));
        *(uint32_t*)&g_Ap[(size_t)(r0 + 8) * HIDDEN + col] =
            pack2h(__float2half_rn(O[nt][2] * inv1),
                   __float2half_rn(O[nt][3] * inv1));
    }
}

// ---------------------------------------------------------------------------
extern "C" void kernel_launch(void* const* d_in, const int* in_sizes, int n_in,
                              void* d_out, int out_size)
{
    (void)in_sizes; (void)n_in; (void)out_size;
    const float* x      = (const float*)d_in[0];
    const float* cosp   = (const float*)d_in[1];
    const float* sinp   = (const float*)d_in[2];
    const float* w_qkv  = (const float*)d_in[3];
    const float* b_qkv  = (const float*)d_in[4];
    const float* w_proj = (const float*)d_in[5];
    const float* b_proj = (const float*)d_in[6];
    float* out = (float*)d_out;

    float* qkv = nullptr;
    __half *Aq = nullptr, *Ap = nullptr, *Bq = nullptr, *Bp = nullptr;
    cudaGetSymbolAddress((void**)&qkv,  g_qkv);
    cudaGetSymbolAddress((void**)&Aq,   g_Aq);
    cudaGetSymbolAddress((void**)&Ap,   g_Ap);
    cudaGetSymbolAddress((void**)&Bq,   g_Bq);
    cudaGetSymbolAddress((void**)&Bp,   g_Bp);

    cudaFuncSetAttribute(gemm_fp16_mma,
                         cudaFuncAttributeMaxDynamicSharedMemorySize, GSMEM);
    cudaFuncSetAttribute(flash_mma,
                         cudaFuncAttributeMaxDynamicSharedMemorySize, SM_TOT);

    // conversions
    convert_B1<<<dim3(QKVN / 32, HIDDEN / 32), dim3(32, 8)>>>(w_qkv, Bq, HIDDEN, QKVN);
    convert_B1<<<dim3(HIDDEN / 32, HIDDEN / 32), dim3(32, 8)>>>(w_proj, Bp, HIDDEN, HIDDEN);
    {
        int mk = TOTAL * HIDDEN;
        convert_A<<<(mk / 4 + 255) / 256, 256>>>(x, Aq, mk);
    }

    // 1) QKV projection (fp16, K = 1280)
    gemm_fp16_mma<<<dim3(QKVN / 128, TOTAL / 128), 128, GSMEM>>>(
        Aq, Bq, b_qkv, qkv, QKVN, HIDDEN);

    // 2) RoPE + conversions
    {
        int total = TOTAL * HEADS * (HEAD_DIM / 2);
        rope_split<<<(total + 255) / 256, 256>>>(cosp, sinp);
    }
    vtrans<<<dim3(TOTAL / 64, HEADS), 256>>>();

    // 3) flash attention (writes fp16 attn into g_Ap)
    flash_mma<<<dim3(CHUNK_L / 128, HEADS, NCHUNK), 256, SM_TOT>>>();

    // 4) output projection (fp16, K = 1280)
    gemm_fp16_mma<<<dim3(HIDDEN / 128, TOTAL / 128), 128, GSMEM>>>(
        Ap, Bp, b_proj, out, HIDDEN, HIDDEN);
}